// round 1
// baseline (speedup 1.0000x reference)
#include <cuda_runtime.h>
#include <math.h>

#define BATCH 4
#define SEQL 2048
#define HID 1024
#define NH 4
#define DK 1024
#define DV 2048
#define HDK 256
#define HDV 512
#define CHUNK 64
#define NCHUNK (SEQL / CHUNK)
#define BL (BATCH * SEQL) /* 8192 */

// ---------------- scratch (static device allocations; no runtime alloc) ----
__device__ float g_q[BL * DK];
__device__ float g_k[BL * DK];
__device__ float g_v[BL * DV];
__device__ float g_gt[BL * DV];
__device__ float g_gk[BL * DK];
__device__ float g_t16[BL * 16];
__device__ float g_o[BL * DV];
__device__ float g_og[BL * DV];

// ---------------- generic FP32 SGEMM: C[M,N] = A[M,K] @ B[K,N] -------------
// BM=BN=128, BK=8, TM=TN=8, 256 threads. Requires M%128==0, N%128==0, K%8==0.
__global__ __launch_bounds__(256) void sgemm128(
    const float* __restrict__ A, const float* __restrict__ Bm,
    float* __restrict__ C, int M, int N, int K)
{
    __shared__ float As[8][128];
    __shared__ float Bs[8][128];
    const int tid = threadIdx.x;
    const long brow = blockIdx.y, bcol = blockIdx.x;
    const float* Ab = A + brow * 128 * (long)K;
    const float* Bb = Bm + bcol * 128;
    float* Cb = C + brow * 128 * (long)N + bcol * 128;

    const int trow = (tid / 16) * 8;
    const int tcol = (tid % 16) * 8;
    const int arow = tid / 2, acol = (tid % 2) * 4;
    const int browi = tid / 32, bcoli = (tid % 32) * 4;

    float acc[8][8];
#pragma unroll
    for (int i = 0; i < 8; i++)
#pragma unroll
        for (int j = 0; j < 8; j++) acc[i][j] = 0.f;

    for (int k0 = 0; k0 < K; k0 += 8) {
        float4 a4 = *(const float4*)(Ab + (long)arow * K + k0 + acol);
        As[acol + 0][arow] = a4.x;
        As[acol + 1][arow] = a4.y;
        As[acol + 2][arow] = a4.z;
        As[acol + 3][arow] = a4.w;
        float4 b4 = *(const float4*)(Bb + (long)(k0 + browi) * N + bcoli);
        *(float4*)(&Bs[browi][bcoli]) = b4;
        __syncthreads();
#pragma unroll
        for (int kk = 0; kk < 8; kk++) {
            float ra[8], rb[8];
#pragma unroll
            for (int i = 0; i < 8; i++) ra[i] = As[kk][trow + i];
#pragma unroll
            for (int j = 0; j < 8; j++) rb[j] = Bs[kk][tcol + j];
#pragma unroll
            for (int i = 0; i < 8; i++)
#pragma unroll
                for (int j = 0; j < 8; j++) acc[i][j] += ra[i] * rb[j];
        }
        __syncthreads();
    }
#pragma unroll
    for (int i = 0; i < 8; i++)
#pragma unroll
        for (int j = 0; j < 8; j += 4)
            *(float4*)(Cb + (long)(trow + i) * N + tcol + j) =
                make_float4(acc[i][j], acc[i][j + 1], acc[i][j + 2], acc[i][j + 3]);
}

// ---------------- low-rank gate: tmp = h @ Wgk1  (K=1024, N=16) ------------
__global__ __launch_bounds__(256) void gemm16_kernel(
    const float* __restrict__ A, const float* __restrict__ W)
{
    int idx = blockIdx.x * 256 + threadIdx.x; // BL*16 threads
    int row = idx >> 4, col = idx & 15;
    const float* a = A + (long)row * HID;
    float acc = 0.f;
#pragma unroll 8
    for (int k = 0; k < HID; k++) acc += a[k] * W[k * 16 + col];
    g_t16[idx] = acc;
}

// ---------------- gk = log_sigmoid(tmp @ Wgk2 + b) / 16 --------------------
__global__ __launch_bounds__(256) void gk_kernel(
    const float* __restrict__ W2, const float* __restrict__ bias)
{
    int idx = blockIdx.x * 256 + threadIdx.x; // BL*DK threads
    int row = idx >> 10, c = idx & 1023;
    const float* t = g_t16 + row * 16;
    float acc = bias[c];
#pragma unroll
    for (int l = 0; l < 16; l++) acc += t[l] * W2[l * DK + c];
    float ls = (acc >= 0.f) ? -log1pf(expf(-acc)) : (acc - log1pf(expf(acc)));
    g_gk[idx] = ls * 0.0625f;
}

// ---------------- chunked GLA recurrence ----------------------------------
// grid: (8 value-slices of 64, 16 bh). 256 threads. S[256 x 64] in SMEM.
#define QS 257   /* padded row stride for qg/ki tiles */
#define VS 65    /* padded row stride for v/scores tiles */
#define SSD 64   /* S row stride */
#define GLA_SMEM_FLOATS (64 * QS * 2 + 256 * SSD + 64 * VS * 2 + 256)

__global__ __launch_bounds__(256) void gla_kernel()
{
    extern __shared__ float sm[];
    float* qg = sm;                    // [64][QS]
    float* ki = qg + 64 * QS;          // [64][QS]
    float* S  = ki + 64 * QS;          // [256][SSD]
    float* vt = S + 256 * SSD;         // [64][VS]
    float* sc = vt + 64 * VS;          // [64][VS]
    float* eb = sc + 64 * VS;          // [256]

    const int tid = threadIdx.x;
    const int vs = blockIdx.x;         // value slice 0..7
    const int bh = blockIdx.y;         // 0..15
    const int b = bh >> 2, hh = bh & 3;
    const float scale = 0.0625f;       // HDK^-0.5

    for (int i = tid; i < 256 * SSD; i += 256) S[i] = 0.f;
    __syncthreads();

    for (int n = 0; n < NCHUNK; n++) {
        // ---- phase A: cumsum gates, build gated q/k tiles; load v tile ----
        {
            const int d = tid;
            const long base = ((long)(b * SEQL + n * CHUNK)) * DK + hh * HDK + d;
            const float* gkp = g_gk + base;
            const float* qp = g_q + base;
            const float* kp = g_k + base;
            float bsum = 0.f;
            for (int t = 0; t < CHUNK; t++) {
                bsum += gkp[(long)t * DK];
                float ep = __expf(bsum);
                float en = __expf(-bsum);
                qg[t * QS + d] = qp[(long)t * DK] * ep * scale;
                ki[t * QS + d] = kp[(long)t * DK] * en;
            }
            eb[d] = __expf(bsum);

            const long vbase = ((long)(b * SEQL + n * CHUNK)) * DV + hh * HDV + vs * 64;
            for (int i = tid; i < CHUNK * 64; i += 256) {
                int t = i >> 6, vo = i & 63;
                vt[t * VS + vo] = g_v[vbase + (long)t * DV + vo];
            }
        }
        __syncthreads();

        // ---- phase B: scores[i][j] = sum_d qg[i][d]*ki[j][d], j<=i --------
        {
            const int i = tid >> 2;
            const int jg = (tid & 3) * 16;
#pragma unroll
            for (int u = 0; u < 16; u++) {
                int j = jg + u;
                float a = 0.f;
                if (j <= i) {
#pragma unroll 4
                    for (int d = 0; d < HDK; d++) a += qg[i * QS + d] * ki[j * QS + d];
                }
                sc[i * VS + j] = a;
            }
        }
        __syncthreads();

        // ---- phase C: o = scores@v + qg@S ---------------------------------
        {
            const int i = tid >> 2;
            const int v0 = tid & 3;
            float acc[16];
#pragma unroll
            for (int u = 0; u < 16; u++) acc[u] = 0.f;
            for (int j = 0; j <= i; j++) {
                float s = sc[i * VS + j];
#pragma unroll
                for (int u = 0; u < 16; u++) acc[u] += s * vt[j * VS + v0 + 4 * u];
            }
#pragma unroll 2
            for (int d = 0; d < HDK; d++) {
                float qv = qg[i * QS + d];
#pragma unroll
                for (int u = 0; u < 16; u++) acc[u] += qv * S[d * SSD + v0 + 4 * u];
            }
            float* op = g_o + ((long)(b * SEQL + n * CHUNK + i)) * DV + hh * HDV + vs * 64 + v0;
#pragma unroll
            for (int u = 0; u < 16; u++) op[4 * u] = acc[u];
        }
        __syncthreads();

        // ---- phase D: S = eb[d]*(S + ki^T @ v) ----------------------------
        {
            const int vo = tid & 63;
            const int d0 = (tid >> 6) * 64;
            for (int dd = 0; dd < 64; dd++) {
                int d = d0 + dd;
                float s = 0.f;
#pragma unroll 4
                for (int t = 0; t < CHUNK; t++) s += ki[t * QS + d] * vt[t * VS + vo];
                S[d * SSD + vo] = eb[d] * (S[d * SSD + vo] + s);
            }
        }
        __syncthreads();
    }
}

// ---------------- RMS norm (per head) + swish gate -------------------------
__global__ __launch_bounds__(256) void normgate_kernel(const float* __restrict__ gnw)
{
    const int row = blockIdx.x;  // (b*L+l)*NH + h
    const int tid = threadIdx.x;
    const long base = (long)(row >> 2) * DV + (row & 3) * HDV;
    const float* op = g_o + base;
    const float* gp = g_gt + base;
    float* ogp = g_og + base;

    float vals[2];
    float ss = 0.f;
#pragma unroll
    for (int u = 0; u < 2; u++) {
        vals[u] = op[tid + 256 * u];
        ss += vals[u] * vals[u];
    }
    __shared__ float red[8];
#pragma unroll
    for (int o = 16; o > 0; o >>= 1) ss += __shfl_xor_sync(0xffffffffu, ss, o);
    if ((tid & 31) == 0) red[tid >> 5] = ss;
    __syncthreads();
    if (tid < 8) {
        float r = red[tid];
#pragma unroll
        for (int o = 4; o > 0; o >>= 1) r += __shfl_xor_sync(0xffu, r, o);
        if (tid == 0) red[0] = r;
    }
    __syncthreads();
    const float rinv = rsqrtf(red[0] * (1.f / 512.f) + 1e-5f);
#pragma unroll
    for (int u = 0; u < 2; u++) {
        int c = tid + 256 * u;
        float g = gp[c];
        float sig = 1.f / (1.f + __expf(-g));
        ogp[c] = vals[u] * rinv * gnw[c] * (g * sig);
    }
}

// ---------------- launch ----------------------------------------------------
extern "C" void kernel_launch(void* const* d_in, const int* in_sizes, int n_in,
                              void* d_out, int out_size)
{
    (void)in_sizes; (void)n_in; (void)out_size;
    const float* h    = (const float*)d_in[0];
    const float* Wq   = (const float*)d_in[1];
    const float* Wk   = (const float*)d_in[2];
    const float* Wv   = (const float*)d_in[3];
    const float* Wg   = (const float*)d_in[4];
    const float* Wgk1 = (const float*)d_in[5];
    const float* Wgk2 = (const float*)d_in[6];
    const float* bgk2 = (const float*)d_in[7];
    const float* gnw  = (const float*)d_in[8];
    const float* Wo   = (const float*)d_in[9];
    float* out = (float*)d_out;

    void *pq, *pk, *pv, *pg, *pog;
    cudaGetSymbolAddress(&pq, g_q);
    cudaGetSymbolAddress(&pk, g_k);
    cudaGetSymbolAddress(&pv, g_v);
    cudaGetSymbolAddress(&pg, g_gt);
    cudaGetSymbolAddress(&pog, g_og);

    static_assert(GLA_SMEM_FLOATS * 4 <= 232448, "gla smem too big");
    cudaFuncSetAttribute(gla_kernel, cudaFuncAttributeMaxDynamicSharedMemorySize,
                         GLA_SMEM_FLOATS * 4);

    dim3 t256(256);
    // projections
    sgemm128<<<dim3(DK / 128, BL / 128), t256>>>(h, Wq, (float*)pq, BL, DK, HID);
    sgemm128<<<dim3(DK / 128, BL / 128), t256>>>(h, Wk, (float*)pk, BL, DK, HID);
    sgemm128<<<dim3(DV / 128, BL / 128), t256>>>(h, Wv, (float*)pv, BL, DV, HID);
    sgemm128<<<dim3(DV / 128, BL / 128), t256>>>(h, Wg, (float*)pg, BL, DV, HID);
    // low-rank gate path
    gemm16_kernel<<<(BL * 16) / 256, t256>>>(h, Wgk1);
    gk_kernel<<<(BL * DK) / 256, t256>>>(Wgk2, bgk2);
    // chunked GLA
    gla_kernel<<<dim3(HDV / 64, BATCH * NH), t256, GLA_SMEM_FLOATS * 4>>>();
    // rms norm + swish gate
    normgate_kernel<<<BL * NH, t256>>>(gnw);
    // output projection
    sgemm128<<<dim3(HID / 128, BL / 128), t256>>>((const float*)pog, Wo, out, BL, HID, DV);
}

// round 2
// speedup vs baseline: 1.3660x; 1.3660x over previous
#include <cuda_runtime.h>
#include <math.h>

#define BATCH 4
#define SEQL 2048
#define HID 1024
#define NH 4
#define DK 1024
#define DV 2048
#define HDK 256
#define HDV 512
#define CHUNK 64
#define NCHUNK (SEQL / CHUNK)
#define BL (BATCH * SEQL) /* 8192 */

// ---------------- scratch (static device allocations; no runtime alloc) ----
__device__ float g_q[BL * DK];
__device__ float g_k[BL * DK];
__device__ float g_v[BL * DV];
__device__ float g_gt[BL * DV];
__device__ float g_gk[BL * DK];
__device__ float g_t16[BL * 16];
__device__ float g_o[BL * DV];
__device__ float g_og[BL * DV];

// ================= TF32 tensor-core GEMM ===================================
// C[M,N] = A[M,K] @ B[K,N], fp32 in/out, tf32 mma.m16n8k8, fp32 accum.
// Block 128x128x32, 256 threads (8 warps: 2 along M x 4 along N),
// warp tile 64x32, double-buffered cp.async.
#define ASTR 36    /* A smem row stride (floats), 16B aligned, conflict-free */
#define BSTR 132   /* B smem row stride */
#define ATILE (128 * ASTR)
#define BTILE (32 * BSTR)
#define STAGEF (ATILE + BTILE)
#define GEMM_SMEM_BYTES (2 * STAGEF * 4)

__device__ __forceinline__ unsigned f2tf(float f) {
    unsigned r;
    asm("cvt.rna.tf32.f32 %0, %1;" : "=r"(r) : "f"(f));
    return r;
}

__device__ __forceinline__ void mma_tf32(float* c, const unsigned* a, const unsigned* b) {
    asm volatile(
        "mma.sync.aligned.m16n8k8.row.col.f32.tf32.tf32.f32 "
        "{%0,%1,%2,%3}, {%4,%5,%6,%7}, {%8,%9}, {%0,%1,%2,%3};"
        : "+f"(c[0]), "+f"(c[1]), "+f"(c[2]), "+f"(c[3])
        : "r"(a[0]), "r"(a[1]), "r"(a[2]), "r"(a[3]), "r"(b[0]), "r"(b[1]));
}

__global__ __launch_bounds__(256, 2) void gemm_tf32(
    const float* __restrict__ A, const float* __restrict__ B,
    float* __restrict__ C, int M, int N, int K)
{
    extern __shared__ float sm[];
    const int tid = threadIdx.x;
    const int warp = tid >> 5, lane = tid & 31;
    const long bm = (long)blockIdx.y * 128, bn = (long)blockIdx.x * 128;
    const int wm = (warp & 1) * 64, wn = (warp >> 1) * 32;

    float acc[4][4][4];
#pragma unroll
    for (int mt = 0; mt < 4; mt++)
#pragma unroll
        for (int nt = 0; nt < 4; nt++)
#pragma unroll
            for (int u = 0; u < 4; u++) acc[mt][nt][u] = 0.f;

    const int arow = tid >> 1;           // A loader: row 0..127
    const int aq = tid & 1;              // float4 col parity
    const int bk = tid >> 5;             // B loader: k row 0..7
    const int bn4 = (lane) * 4;          // B cols (float4)

    auto load_tile = [&](int s, int k0) {
        const float* gA = A + (bm + arow) * (long)K + k0;
        float* sA = sm + s * STAGEF + arow * ASTR;
#pragma unroll
        for (int p = 0; p < 4; p++) {
            int q = aq + p * 2;
            unsigned sa = (unsigned)__cvta_generic_to_shared(sA + q * 4);
            asm volatile("cp.async.cg.shared.global [%0], [%1], 16;\n"
                         :: "r"(sa), "l"(gA + q * 4));
        }
        float* sB = sm + s * STAGEF + ATILE;
#pragma unroll
        for (int p = 0; p < 4; p++) {
            int kr = bk + p * 8;
            const float* gB = B + (long)(k0 + kr) * N + bn + bn4;
            unsigned sb = (unsigned)__cvta_generic_to_shared(sB + kr * BSTR + bn4);
            asm volatile("cp.async.cg.shared.global [%0], [%1], 16;\n"
                         :: "r"(sb), "l"(gB));
        }
    };

    load_tile(0, 0);
    asm volatile("cp.async.commit_group;\n");

    const int nk = K >> 5;
    for (int it = 0; it < nk; it++) {
        const int s = it & 1;
        if (it + 1 < nk) {
            load_tile(s ^ 1, (it + 1) * 32);
            asm volatile("cp.async.commit_group;\n");
            asm volatile("cp.async.wait_group 1;\n");
        } else {
            asm volatile("cp.async.wait_group 0;\n");
        }
        __syncthreads();

        const float* sA = sm + s * STAGEF;
        const float* sB = sm + s * STAGEF + ATILE;
#pragma unroll
        for (int kk = 0; kk < 4; kk++) {
            const int k0 = kk * 8;
            unsigned a[4][4], b[4][2];
#pragma unroll
            for (int mt = 0; mt < 4; mt++) {
                const float* ap = sA + (wm + mt * 16 + (lane >> 2)) * ASTR + k0 + (lane & 3);
                a[mt][0] = f2tf(ap[0]);
                a[mt][1] = f2tf(ap[8 * ASTR]);
                a[mt][2] = f2tf(ap[4]);
                a[mt][3] = f2tf(ap[8 * ASTR + 4]);
            }
#pragma unroll
            for (int nt = 0; nt < 4; nt++) {
                const float* bp = sB + (k0 + (lane & 3)) * BSTR + wn + nt * 8 + (lane >> 2);
                b[nt][0] = f2tf(bp[0]);
                b[nt][1] = f2tf(bp[4 * BSTR]);
            }
#pragma unroll
            for (int mt = 0; mt < 4; mt++)
#pragma unroll
                for (int nt = 0; nt < 4; nt++) mma_tf32(acc[mt][nt], a[mt], b[nt]);
        }
        __syncthreads();
    }

    float* Cb = C + (bm + wm) * (long)N + bn + wn;
#pragma unroll
    for (int mt = 0; mt < 4; mt++) {
        const int row0 = mt * 16 + (lane >> 2);
#pragma unroll
        for (int nt = 0; nt < 4; nt++) {
            const int col = nt * 8 + 2 * (lane & 3);
            *(float2*)(Cb + (long)row0 * N + col) =
                make_float2(acc[mt][nt][0], acc[mt][nt][1]);
            *(float2*)(Cb + (long)(row0 + 8) * N + col) =
                make_float2(acc[mt][nt][2], acc[mt][nt][3]);
        }
    }
}

// ---------------- low-rank gate: tmp = h @ Wgk1  (K=1024, N=16) ------------
__global__ __launch_bounds__(256) void gemm16_kernel(
    const float* __restrict__ A, const float* __restrict__ W)
{
    int idx = blockIdx.x * 256 + threadIdx.x; // BL*16 threads
    int row = idx >> 4, col = idx & 15;
    const float* a = A + (long)row * HID;
    float acc = 0.f;
#pragma unroll 8
    for (int k = 0; k < HID; k++) acc += a[k] * W[k * 16 + col];
    g_t16[idx] = acc;
}

// ---------------- gk = log_sigmoid(tmp @ Wgk2 + b) / 16 --------------------
__global__ __launch_bounds__(256) void gk_kernel(
    const float* __restrict__ W2, const float* __restrict__ bias)
{
    int idx = blockIdx.x * 256 + threadIdx.x; // BL*DK threads
    int row = idx >> 10, c = idx & 1023;
    const float* t = g_t16 + row * 16;
    float acc = bias[c];
#pragma unroll
    for (int l = 0; l < 16; l++) acc += t[l] * W2[l * DK + c];
    float ls = (acc >= 0.f) ? -log1pf(expf(-acc)) : (acc - log1pf(expf(acc)));
    g_gk[idx] = ls * 0.0625f;
}

// ---------------- chunked GLA recurrence ----------------------------------
// grid: (8 value-slices of 64, 16 bh). 256 threads. S[256 x 64] in SMEM.
#define QS 257   /* padded row stride for qg/ki tiles */
#define VS 65    /* padded row stride for v/scores tiles */
#define SSD 64   /* S row stride */
#define GLA_SMEM_FLOATS (64 * QS * 2 + 256 * SSD + 64 * VS * 2 + 256)

__global__ __launch_bounds__(256) void gla_kernel()
{
    extern __shared__ float sm[];
    float* qg = sm;                    // [64][QS]
    float* ki = qg + 64 * QS;          // [64][QS]
    float* S  = ki + 64 * QS;          // [256][SSD]
    float* vt = S + 256 * SSD;         // [64][VS]
    float* sc = vt + 64 * VS;          // [64][VS]
    float* eb = sc + 64 * VS;          // [256]

    const int tid = threadIdx.x;
    const int vs = blockIdx.x;         // value slice 0..7
    const int bh = blockIdx.y;         // 0..15
    const int b = bh >> 2, hh = bh & 3;
    const float scale = 0.0625f;       // HDK^-0.5

    for (int i = tid; i < 256 * SSD; i += 256) S[i] = 0.f;
    __syncthreads();

    for (int n = 0; n < NCHUNK; n++) {
        // ---- phase A: cumsum gates, build gated q/k tiles; load v tile ----
        {
            const int d = tid;
            const long base = ((long)(b * SEQL + n * CHUNK)) * DK + hh * HDK + d;
            const float* gkp = g_gk + base;
            const float* qp = g_q + base;
            const float* kp = g_k + base;
            float bsum = 0.f;
            for (int t = 0; t < CHUNK; t++) {
                bsum += gkp[(long)t * DK];
                float ep = __expf(bsum);
                float en = __expf(-bsum);
                qg[t * QS + d] = qp[(long)t * DK] * ep * scale;
                ki[t * QS + d] = kp[(long)t * DK] * en;
            }
            eb[d] = __expf(bsum);

            const long vbase = ((long)(b * SEQL + n * CHUNK)) * DV + hh * HDV + vs * 64;
            for (int i = tid; i < CHUNK * 64; i += 256) {
                int t = i >> 6, vo = i & 63;
                vt[t * VS + vo] = g_v[vbase + (long)t * DV + vo];
            }
        }
        __syncthreads();

        // ---- phase B: scores[i][j] = sum_d qg[i][d]*ki[j][d], j<=i --------
        {
            const int i = tid >> 2;
            const int jg = (tid & 3) * 16;
#pragma unroll
            for (int u = 0; u < 16; u++) {
                int j = jg + u;
                float a = 0.f;
                if (j <= i) {
#pragma unroll 4
                    for (int d = 0; d < HDK; d++) a += qg[i * QS + d] * ki[j * QS + d];
                }
                sc[i * VS + j] = a;
            }
        }
        __syncthreads();

        // ---- phase C: o = scores@v + qg@S ---------------------------------
        {
            const int i = tid >> 2;
            const int v0 = tid & 3;
            float acc[16];
#pragma unroll
            for (int u = 0; u < 16; u++) acc[u] = 0.f;
            for (int j = 0; j <= i; j++) {
                float s = sc[i * VS + j];
#pragma unroll
                for (int u = 0; u < 16; u++) acc[u] += s * vt[j * VS + v0 + 4 * u];
            }
#pragma unroll 2
            for (int d = 0; d < HDK; d++) {
                float qv = qg[i * QS + d];
#pragma unroll
                for (int u = 0; u < 16; u++) acc[u] += qv * S[d * SSD + v0 + 4 * u];
            }
            float* op = g_o + ((long)(b * SEQL + n * CHUNK + i)) * DV + hh * HDV + vs * 64 + v0;
#pragma unroll
            for (int u = 0; u < 16; u++) op[4 * u] = acc[u];
        }
        __syncthreads();

        // ---- phase D: S = eb[d]*(S + ki^T @ v) ----------------------------
        {
            const int vo = tid & 63;
            const int d0 = (tid >> 6) * 64;
            for (int dd = 0; dd < 64; dd++) {
                int d = d0 + dd;
                float s = 0.f;
#pragma unroll 4
                for (int t = 0; t < CHUNK; t++) s += ki[t * QS + d] * vt[t * VS + vo];
                S[d * SSD + vo] = eb[d] * (S[d * SSD + vo] + s);
            }
        }
        __syncthreads();
    }
}

// ---------------- RMS norm (per head) + swish gate -------------------------
__global__ __launch_bounds__(256) void normgate_kernel(const float* __restrict__ gnw)
{
    const int row = blockIdx.x;  // (b*L+l)*NH + h
    const int tid = threadIdx.x;
    const long base = (long)(row >> 2) * DV + (row & 3) * HDV;
    const float* op = g_o + base;
    const float* gp = g_gt + base;
    float* ogp = g_og + base;

    float vals[2];
    float ss = 0.f;
#pragma unroll
    for (int u = 0; u < 2; u++) {
        vals[u] = op[tid + 256 * u];
        ss += vals[u] * vals[u];
    }
    __shared__ float red[8];
#pragma unroll
    for (int o = 16; o > 0; o >>= 1) ss += __shfl_xor_sync(0xffffffffu, ss, o);
    if ((tid & 31) == 0) red[tid >> 5] = ss;
    __syncthreads();
    if (tid < 8) {
        float r = red[tid];
#pragma unroll
        for (int o = 4; o > 0; o >>= 1) r += __shfl_xor_sync(0xffu, r, o);
        if (tid == 0) red[0] = r;
    }
    __syncthreads();
    const float rinv = rsqrtf(red[0] * (1.f / 512.f) + 1e-5f);
#pragma unroll
    for (int u = 0; u < 2; u++) {
        int c = tid + 256 * u;
        float g = gp[c];
        float sig = 1.f / (1.f + __expf(-g));
        ogp[c] = vals[u] * rinv * gnw[c] * (g * sig);
    }
}

// ---------------- launch ----------------------------------------------------
extern "C" void kernel_launch(void* const* d_in, const int* in_sizes, int n_in,
                              void* d_out, int out_size)
{
    (void)in_sizes; (void)n_in; (void)out_size;
    const float* h    = (const float*)d_in[0];
    const float* Wq   = (const float*)d_in[1];
    const float* Wk   = (const float*)d_in[2];
    const float* Wv   = (const float*)d_in[3];
    const float* Wg   = (const float*)d_in[4];
    const float* Wgk1 = (const float*)d_in[5];
    const float* Wgk2 = (const float*)d_in[6];
    const float* bgk2 = (const float*)d_in[7];
    const float* gnw  = (const float*)d_in[8];
    const float* Wo   = (const float*)d_in[9];
    float* out = (float*)d_out;

    void *pq, *pk, *pv, *pg, *pog;
    cudaGetSymbolAddress(&pq, g_q);
    cudaGetSymbolAddress(&pk, g_k);
    cudaGetSymbolAddress(&pv, g_v);
    cudaGetSymbolAddress(&pg, g_gt);
    cudaGetSymbolAddress(&pog, g_og);

    static_assert(GLA_SMEM_FLOATS * 4 <= 232448, "gla smem too big");
    cudaFuncSetAttribute(gla_kernel, cudaFuncAttributeMaxDynamicSharedMemorySize,
                         GLA_SMEM_FLOATS * 4);
    cudaFuncSetAttribute(gemm_tf32, cudaFuncAttributeMaxDynamicSharedMemorySize,
                         GEMM_SMEM_BYTES);

    dim3 t256(256);
    // projections (tf32 tensor cores)
    gemm_tf32<<<dim3(DK / 128, BL / 128), t256, GEMM_SMEM_BYTES>>>(h, Wq, (float*)pq, BL, DK, HID);
    gemm_tf32<<<dim3(DK / 128, BL / 128), t256, GEMM_SMEM_BYTES>>>(h, Wk, (float*)pk, BL, DK, HID);
    gemm_tf32<<<dim3(DV / 128, BL / 128), t256, GEMM_SMEM_BYTES>>>(h, Wv, (float*)pv, BL, DV, HID);
    gemm_tf32<<<dim3(DV / 128, BL / 128), t256, GEMM_SMEM_BYTES>>>(h, Wg, (float*)pg, BL, DV, HID);
    // low-rank gate path
    gemm16_kernel<<<(BL * 16) / 256, t256>>>(h, Wgk1);
    gk_kernel<<<(BL * DK) / 256, t256>>>(Wgk2, bgk2);
    // chunked GLA
    gla_kernel<<<dim3(HDV / 64, BATCH * NH), t256, GLA_SMEM_FLOATS * 4>>>();
    // rms norm + swish gate
    normgate_kernel<<<BL * NH, t256>>>(gnw);
    // output projection
    gemm_tf32<<<dim3(HID / 128, BL / 128), t256, GEMM_SMEM_BYTES>>>((const float*)pog, Wo, out, BL, HID, DV);
}

// round 3
// speedup vs baseline: 3.4906x; 2.5554x over previous
#include <cuda_runtime.h>
#include <math.h>

#define BATCH 4
#define SEQL 2048
#define HID 1024
#define NH 4
#define DK 1024
#define DV 2048
#define HDK 256
#define HDV 512
#define CHUNK 64
#define NCHUNK (SEQL / CHUNK)
#define BL (BATCH * SEQL) /* 8192 */

// ---------------- scratch (static device allocations; no runtime alloc) ----
__device__ float g_q[BL * DK];
__device__ float g_k[BL * DK];
__device__ float g_v[BL * DV];
__device__ float g_gt[BL * DV];
__device__ float g_gk[BL * DK];
__device__ float g_t16[BL * 16];
__device__ float g_o[BL * DV];
__device__ float g_og[BL * DV];

// ================= common tf32 mma helpers =================================
__device__ __forceinline__ unsigned f2tf(float f) {
    unsigned r;
    asm("cvt.rna.tf32.f32 %0, %1;" : "=r"(r) : "f"(f));
    return r;
}

__device__ __forceinline__ void mma_tf32(float* c, const unsigned* a, const unsigned* b) {
    asm volatile(
        "mma.sync.aligned.m16n8k8.row.col.f32.tf32.tf32.f32 "
        "{%0,%1,%2,%3}, {%4,%5,%6,%7}, {%8,%9}, {%0,%1,%2,%3};"
        : "+f"(c[0]), "+f"(c[1]), "+f"(c[2]), "+f"(c[3])
        : "r"(a[0]), "r"(a[1]), "r"(a[2]), "r"(a[3]), "r"(b[0]), "r"(b[1]));
}

// ================= TF32 tensor-core GEMM ===================================
// C[M,N] = A[M,K] @ B[K,N], fp32 in/out, tf32 mma.m16n8k8, fp32 accum.
#define ASTR 36
#define BSTR 132
#define ATILE (128 * ASTR)
#define BTILE (32 * BSTR)
#define STAGEF (ATILE + BTILE)
#define GEMM_SMEM_BYTES (2 * STAGEF * 4)

__global__ __launch_bounds__(256, 2) void gemm_tf32(
    const float* __restrict__ A, const float* __restrict__ B,
    float* __restrict__ C, int M, int N, int K)
{
    extern __shared__ float sm[];
    const int tid = threadIdx.x;
    const int warp = tid >> 5, lane = tid & 31;
    const long bm = (long)blockIdx.y * 128, bn = (long)blockIdx.x * 128;
    const int wm = (warp & 1) * 64, wn = (warp >> 1) * 32;

    float acc[4][4][4];
#pragma unroll
    for (int mt = 0; mt < 4; mt++)
#pragma unroll
        for (int nt = 0; nt < 4; nt++)
#pragma unroll
            for (int u = 0; u < 4; u++) acc[mt][nt][u] = 0.f;

    const int arow = tid >> 1;
    const int aq = tid & 1;
    const int bk = tid >> 5;
    const int bn4 = lane * 4;

    auto load_tile = [&](int s, int k0) {
        const float* gA = A + (bm + arow) * (long)K + k0;
        float* sA = sm + s * STAGEF + arow * ASTR;
#pragma unroll
        for (int p = 0; p < 4; p++) {
            int q = aq + p * 2;
            unsigned sa = (unsigned)__cvta_generic_to_shared(sA + q * 4);
            asm volatile("cp.async.cg.shared.global [%0], [%1], 16;\n"
                         :: "r"(sa), "l"(gA + q * 4));
        }
        float* sB = sm + s * STAGEF + ATILE;
#pragma unroll
        for (int p = 0; p < 4; p++) {
            int kr = bk + p * 8;
            const float* gB = B + (long)(k0 + kr) * N + bn + bn4;
            unsigned sb = (unsigned)__cvta_generic_to_shared(sB + kr * BSTR + bn4);
            asm volatile("cp.async.cg.shared.global [%0], [%1], 16;\n"
                         :: "r"(sb), "l"(gB));
        }
    };

    load_tile(0, 0);
    asm volatile("cp.async.commit_group;\n");

    const int nk = K >> 5;
    for (int it = 0; it < nk; it++) {
        const int s = it & 1;
        if (it + 1 < nk) {
            load_tile(s ^ 1, (it + 1) * 32);
            asm volatile("cp.async.commit_group;\n");
            asm volatile("cp.async.wait_group 1;\n");
        } else {
            asm volatile("cp.async.wait_group 0;\n");
        }
        __syncthreads();

        const float* sA = sm + s * STAGEF;
        const float* sB = sm + s * STAGEF + ATILE;
#pragma unroll
        for (int kk = 0; kk < 4; kk++) {
            const int k0 = kk * 8;
            unsigned a[4][4], b[4][2];
#pragma unroll
            for (int mt = 0; mt < 4; mt++) {
                const float* ap = sA + (wm + mt * 16 + (lane >> 2)) * ASTR + k0 + (lane & 3);
                a[mt][0] = f2tf(ap[0]);
                a[mt][1] = f2tf(ap[8 * ASTR]);
                a[mt][2] = f2tf(ap[4]);
                a[mt][3] = f2tf(ap[8 * ASTR + 4]);
            }
#pragma unroll
            for (int nt = 0; nt < 4; nt++) {
                const float* bp = sB + (k0 + (lane & 3)) * BSTR + wn + nt * 8 + (lane >> 2);
                b[nt][0] = f2tf(bp[0]);
                b[nt][1] = f2tf(bp[4 * BSTR]);
            }
#pragma unroll
            for (int mt = 0; mt < 4; mt++)
#pragma unroll
                for (int nt = 0; nt < 4; nt++) mma_tf32(acc[mt][nt], a[mt], b[nt]);
        }
        __syncthreads();
    }

    float* Cb = C + (bm + wm) * (long)N + bn + wn;
#pragma unroll
    for (int mt = 0; mt < 4; mt++) {
        const int row0 = mt * 16 + (lane >> 2);
#pragma unroll
        for (int nt = 0; nt < 4; nt++) {
            const int col = nt * 8 + 2 * (lane & 3);
            *(float2*)(Cb + (long)row0 * N + col) =
                make_float2(acc[mt][nt][0], acc[mt][nt][1]);
            *(float2*)(Cb + (long)(row0 + 8) * N + col) =
                make_float2(acc[mt][nt][2], acc[mt][nt][3]);
        }
    }
}

// ---------------- low-rank gate: tmp = h @ Wgk1  (K=1024, N=16) ------------
__global__ __launch_bounds__(256) void gemm16_kernel(
    const float* __restrict__ A, const float* __restrict__ W)
{
    int idx = blockIdx.x * 256 + threadIdx.x;
    int row = idx >> 4, col = idx & 15;
    const float* a = A + (long)row * HID;
    float acc = 0.f;
#pragma unroll 8
    for (int k = 0; k < HID; k++) acc += a[k] * W[k * 16 + col];
    g_t16[idx] = acc;
}

// ---------------- gk = log_sigmoid(tmp @ Wgk2 + b) / 16 --------------------
__global__ __launch_bounds__(256) void gk_kernel(
    const float* __restrict__ W2, const float* __restrict__ bias)
{
    int idx = blockIdx.x * 256 + threadIdx.x;
    int row = idx >> 10, c = idx & 1023;
    const float* t = g_t16 + row * 16;
    float acc = bias[c];
#pragma unroll
    for (int l = 0; l < 16; l++) acc += t[l] * W2[l * DK + c];
    float ls = (acc >= 0.f) ? -log1pf(expf(-acc)) : (acc - log1pf(expf(acc)));
    g_gk[idx] = ls * 0.0625f;
}

// ================= chunked GLA recurrence (tensor-core) =====================
// grid (8 v-slices of 64, 16 bh), 256 threads (8 warps).
// smem: qg[64][QSTR] (i x d), ki[64][QSTR] (t x d), ST[64][QSTR] (v x d),
//       vtT[64][VSTR] (v x t), sc[64][VSTR] (i x j), eb[256].
#define QSTR 257
#define VSTR 65
#define GLA_SMEM_FLOATS (3 * 64 * QSTR + 2 * 64 * VSTR + 256)

__global__ __launch_bounds__(256) void gla_kernel()
{
    extern __shared__ float sm[];
    float* qg  = sm;                       // [64][QSTR]
    float* ki  = qg + 64 * QSTR;           // [64][QSTR]
    float* ST  = ki + 64 * QSTR;           // [64 v][QSTR] : S^T (v rows, d cols)
    float* vtT = ST + 64 * QSTR;           // [64 v][VSTR] : v^T (v rows, t cols)
    float* sc  = vtT + 64 * VSTR;          // [64 i][VSTR]
    float* eb  = sc + 64 * VSTR;           // [256]

    const int tid = threadIdx.x;
    const int warp = tid >> 5, lane = tid & 31;
    const int r = lane >> 2, cl = lane & 3, cl2 = 2 * (lane & 3);
    const int vs = blockIdx.x;
    const int bh = blockIdx.y;
    const int b = bh >> 2, hh = bh & 3;
    const float scale = 0.0625f;

    // phase B/C warp tiling: 4 (M) x 2 (N)
    const int wm = (warp & 3) * 16;
    const int wn = (warp >> 2) * 32;

    for (int i = tid; i < 64 * QSTR; i += 256) ST[i] = 0.f;
    __syncthreads();

    for (int n = 0; n < NCHUNK; n++) {
        // ---- phase A: gate cumsum -> gated q/k tiles; v transpose ---------
        {
            const int d = tid;
            const long base = ((long)(b * SEQL + n * CHUNK)) * DK + hh * HDK + d;
            const float* gkp = g_gk + base;
            const float* qp = g_q + base;
            const float* kp = g_k + base;
            float bsum = 0.f;
            float ep = 1.f;
#pragma unroll 4
            for (int t = 0; t < CHUNK; t++) {
                bsum += gkp[(long)t * DK];
                ep = __expf(bsum);
                float en = __expf(-bsum);
                qg[t * QSTR + d] = qp[(long)t * DK] * ep * scale;
                ki[t * QSTR + d] = kp[(long)t * DK] * en;
            }
            eb[d] = ep;

            const long vbase = ((long)(b * SEQL + n * CHUNK)) * DV + hh * HDV + vs * 64;
#pragma unroll
            for (int i = tid; i < CHUNK * 64; i += 256) {
                int t = i >> 6, vo = i & 63;
                vtT[vo * VSTR + t] = g_v[vbase + (long)t * DV + vo];
            }
        }
        __syncthreads();

        // ---- phase B: scores = qg @ ki^T (M=64,N=64,K=256), causal mask ---
        {
            float c[4][4];
#pragma unroll
            for (int ns = 0; ns < 4; ns++)
#pragma unroll
                for (int u = 0; u < 4; u++) c[ns][u] = 0.f;
#pragma unroll 4
            for (int k0 = 0; k0 < HDK; k0 += 8) {
                unsigned a[4];
                const float* ap = qg + (wm + r) * QSTR + k0 + cl;
                a[0] = f2tf(ap[0]);
                a[1] = f2tf(ap[8 * QSTR]);
                a[2] = f2tf(ap[4]);
                a[3] = f2tf(ap[8 * QSTR + 4]);
#pragma unroll
                for (int ns = 0; ns < 4; ns++) {
                    unsigned bb[2];
                    const float* bp = ki + (wn + ns * 8 + r) * QSTR + k0 + cl;
                    bb[0] = f2tf(bp[0]);
                    bb[1] = f2tf(bp[4]);
                    mma_tf32(c[ns], a, bb);
                }
            }
            const int row0 = wm + r, row1 = wm + r + 8;
#pragma unroll
            for (int ns = 0; ns < 4; ns++) {
                const int col = wn + ns * 8 + cl2;
                sc[row0 * VSTR + col]     = (col     <= row0) ? c[ns][0] : 0.f;
                sc[row0 * VSTR + col + 1] = (col + 1 <= row0) ? c[ns][1] : 0.f;
                sc[row1 * VSTR + col]     = (col     <= row1) ? c[ns][2] : 0.f;
                sc[row1 * VSTR + col + 1] = (col + 1 <= row1) ? c[ns][3] : 0.f;
            }
        }
        __syncthreads();

        // ---- phase C: o = sc @ v + qg @ S (uses OLD S) ---------------------
        {
            float o[4][4];
#pragma unroll
            for (int ns = 0; ns < 4; ns++)
#pragma unroll
                for (int u = 0; u < 4; u++) o[ns][u] = 0.f;
            // sc @ v : A=sc[i][j], B[k=j][n=v]=vtT[v][j]
#pragma unroll
            for (int k0 = 0; k0 < CHUNK; k0 += 8) {
                unsigned a[4];
                const float* ap = sc + (wm + r) * VSTR + k0 + cl;
                a[0] = f2tf(ap[0]);
                a[1] = f2tf(ap[8 * VSTR]);
                a[2] = f2tf(ap[4]);
                a[3] = f2tf(ap[8 * VSTR + 4]);
#pragma unroll
                for (int ns = 0; ns < 4; ns++) {
                    unsigned bb[2];
                    const float* bp = vtT + (wn + ns * 8 + r) * VSTR + k0 + cl;
                    bb[0] = f2tf(bp[0]);
                    bb[1] = f2tf(bp[4]);
                    mma_tf32(o[ns], a, bb);
                }
            }
            // qg @ S : A=qg[i][d], B[k=d][n=v]=ST[v][d]
#pragma unroll 4
            for (int k0 = 0; k0 < HDK; k0 += 8) {
                unsigned a[4];
                const float* ap = qg + (wm + r) * QSTR + k0 + cl;
                a[0] = f2tf(ap[0]);
                a[1] = f2tf(ap[8 * QSTR]);
                a[2] = f2tf(ap[4]);
                a[3] = f2tf(ap[8 * QSTR + 4]);
#pragma unroll
                for (int ns = 0; ns < 4; ns++) {
                    unsigned bb[2];
                    const float* bp = ST + (wn + ns * 8 + r) * QSTR + k0 + cl;
                    bb[0] = f2tf(bp[0]);
                    bb[1] = f2tf(bp[4]);
                    mma_tf32(o[ns], a, bb);
                }
            }
            // write o tile to global
            const long orow = (long)(b * SEQL + n * CHUNK);
            const long ocol = hh * HDV + vs * 64;
            float* op = g_o + (orow + wm + r) * (long)DV + ocol + wn;
            float* op8 = op + 8 * DV;
#pragma unroll
            for (int ns = 0; ns < 4; ns++) {
                const int col = ns * 8 + cl2;
                *(float2*)(op + col)  = make_float2(o[ns][0], o[ns][1]);
                *(float2*)(op8 + col) = make_float2(o[ns][2], o[ns][3]);
            }
        }
        __syncthreads();

        // ---- phase D: S = eb[d] * (S + ki^T @ v)  (M=256,N=64,K=64) -------
        {
#pragma unroll
            for (int mt = 0; mt < 2; mt++) {
                const int m0 = warp * 32 + mt * 16;
                float cD[8][4];
#pragma unroll
                for (int ns = 0; ns < 8; ns++)
#pragma unroll
                    for (int u = 0; u < 4; u++) cD[ns][u] = 0.f;
#pragma unroll
                for (int k0 = 0; k0 < CHUNK; k0 += 8) {
                    unsigned a[4];
                    // A[m=d][k=t] = ki[t][d]
                    const float* ap = ki + (k0 + cl) * QSTR + m0 + r;
                    a[0] = f2tf(ap[0]);
                    a[1] = f2tf(ap[8]);
                    a[2] = f2tf(ap[4 * QSTR]);
                    a[3] = f2tf(ap[4 * QSTR + 8]);
#pragma unroll
                    for (int ns = 0; ns < 8; ns++) {
                        unsigned bb[2];
                        const float* bp = vtT + (ns * 8 + r) * VSTR + k0 + cl;
                        bb[0] = f2tf(bp[0]);
                        bb[1] = f2tf(bp[4]);
                        mma_tf32(cD[ns], a, bb);
                    }
                }
                const float e0 = eb[m0 + r];
                const float e1 = eb[m0 + r + 8];
#pragma unroll
                for (int ns = 0; ns < 8; ns++) {
                    const int col = ns * 8 + cl2;
                    float* s00 = ST + col * QSTR + m0 + r;
                    float* s01 = ST + (col + 1) * QSTR + m0 + r;
                    s00[0] = e0 * (s00[0] + cD[ns][0]);
                    s01[0] = e0 * (s01[0] + cD[ns][1]);
                    s00[8] = e1 * (s00[8] + cD[ns][2]);
                    s01[8] = e1 * (s01[8] + cD[ns][3]);
                }
            }
        }
        __syncthreads();
    }
}

// ---------------- RMS norm (per head) + swish gate -------------------------
__global__ __launch_bounds__(256) void normgate_kernel(const float* __restrict__ gnw)
{
    const int row = blockIdx.x;
    const int tid = threadIdx.x;
    const long base = (long)(row >> 2) * DV + (row & 3) * HDV;
    const float* op = g_o + base;
    const float* gp = g_gt + base;
    float* ogp = g_og + base;

    float vals[2];
    float ss = 0.f;
#pragma unroll
    for (int u = 0; u < 2; u++) {
        vals[u] = op[tid + 256 * u];
        ss += vals[u] * vals[u];
    }
    __shared__ float red[8];
#pragma unroll
    for (int o = 16; o > 0; o >>= 1) ss += __shfl_xor_sync(0xffffffffu, ss, o);
    if ((tid & 31) == 0) red[tid >> 5] = ss;
    __syncthreads();
    if (tid < 8) {
        float rr = red[tid];
#pragma unroll
        for (int o = 4; o > 0; o >>= 1) rr += __shfl_xor_sync(0xffu, rr, o);
        if (tid == 0) red[0] = rr;
    }
    __syncthreads();
    const float rinv = rsqrtf(red[0] * (1.f / 512.f) + 1e-5f);
#pragma unroll
    for (int u = 0; u < 2; u++) {
        int c = tid + 256 * u;
        float g = gp[c];
        float sig = 1.f / (1.f + __expf(-g));
        ogp[c] = vals[u] * rinv * gnw[c] * (g * sig);
    }
}

// ---------------- launch ----------------------------------------------------
extern "C" void kernel_launch(void* const* d_in, const int* in_sizes, int n_in,
                              void* d_out, int out_size)
{
    (void)in_sizes; (void)n_in; (void)out_size;
    const float* h    = (const float*)d_in[0];
    const float* Wq   = (const float*)d_in[1];
    const float* Wk   = (const float*)d_in[2];
    const float* Wv   = (const float*)d_in[3];
    const float* Wg   = (const float*)d_in[4];
    const float* Wgk1 = (const float*)d_in[5];
    const float* Wgk2 = (const float*)d_in[6];
    const float* bgk2 = (const float*)d_in[7];
    const float* gnw  = (const float*)d_in[8];
    const float* Wo   = (const float*)d_in[9];
    float* out = (float*)d_out;

    void *pq, *pk, *pv, *pg, *pog;
    cudaGetSymbolAddress(&pq, g_q);
    cudaGetSymbolAddress(&pk, g_k);
    cudaGetSymbolAddress(&pv, g_v);
    cudaGetSymbolAddress(&pg, g_gt);
    cudaGetSymbolAddress(&pog, g_og);

    static_assert(GLA_SMEM_FLOATS * 4 <= 232448, "gla smem too big");
    cudaFuncSetAttribute(gla_kernel, cudaFuncAttributeMaxDynamicSharedMemorySize,
                         GLA_SMEM_FLOATS * 4);
    cudaFuncSetAttribute(gemm_tf32, cudaFuncAttributeMaxDynamicSharedMemorySize,
                         GEMM_SMEM_BYTES);

    dim3 t256(256);
    gemm_tf32<<<dim3(DK / 128, BL / 128), t256, GEMM_SMEM_BYTES>>>(h, Wq, (float*)pq, BL, DK, HID);
    gemm_tf32<<<dim3(DK / 128, BL / 128), t256, GEMM_SMEM_BYTES>>>(h, Wk, (float*)pk, BL, DK, HID);
    gemm_tf32<<<dim3(DV / 128, BL / 128), t256, GEMM_SMEM_BYTES>>>(h, Wv, (float*)pv, BL, DV, HID);
    gemm_tf32<<<dim3(DV / 128, BL / 128), t256, GEMM_SMEM_BYTES>>>(h, Wg, (float*)pg, BL, DV, HID);
    gemm16_kernel<<<(BL * 16) / 256, t256>>>(h, Wgk1);
    gk_kernel<<<(BL * DK) / 256, t256>>>(Wgk2, bgk2);
    gla_kernel<<<dim3(HDV / 64, BATCH * NH), t256, GLA_SMEM_FLOATS * 4>>>();
    normgate_kernel<<<BL * NH, t256>>>(gnw);
    gemm_tf32<<<dim3(HID / 128, BL / 128), t256, GEMM_SMEM_BYTES>>>((const float*)pog, Wo, out, BL, HID, DV);
}

// round 5
// speedup vs baseline: 3.7274x; 1.0678x over previous
#include <cuda_runtime.h>
#include <math.h>

#define BATCH 4
#define SEQL 2048
#define HID 1024
#define NH 4
#define DK 1024
#define DV 2048
#define HDK 256
#define HDV 512
#define CHUNK 64
#define NCHUNK (SEQL / CHUNK)
#define BL (BATCH * SEQL) /* 8192 */

// ---------------- scratch (static device allocations; no runtime alloc) ----
__device__ float g_q[BL * DK];
__device__ float g_k[BL * DK];
__device__ float g_v[BL * DV];
__device__ float g_gt[BL * DV];
__device__ float g_gk[BL * DK];
__device__ float g_t16[BL * 16];
__device__ float g_o[BL * DV];
__device__ float g_og[BL * DV];
// tf32-prerounded copies / gate-prep outputs
__device__ float g_ht[BL * HID];
__device__ float g_wqt[HID * DK];
__device__ float g_wkt[HID * DK];
__device__ float g_wvt[HID * DV];
__device__ float g_wgt[HID * DV];
__device__ float g_wot[DV * HID];
__device__ float g_qg[BL * DK];
__device__ float g_ki[BL * DK];
__device__ float g_eb[BATCH * NCHUNK * DK];

// ================= common tf32 mma helpers =================================
__device__ __forceinline__ unsigned f2tf(float f) {
    unsigned r;
    asm("cvt.rna.tf32.f32 %0, %1;" : "=r"(r) : "f"(f));
    return r;
}
__device__ __forceinline__ float f2tff(float f) { return __uint_as_float(f2tf(f)); }

__device__ __forceinline__ void mma_tf32(float* c, const unsigned* a, const unsigned* b) {
    asm volatile(
        "mma.sync.aligned.m16n8k8.row.col.f32.tf32.tf32.f32 "
        "{%0,%1,%2,%3}, {%4,%5,%6,%7}, {%8,%9}, {%0,%1,%2,%3};"
        : "+f"(c[0]), "+f"(c[1]), "+f"(c[2]), "+f"(c[3])
        : "r"(a[0]), "r"(a[1]), "r"(a[2]), "r"(a[3]), "r"(b[0]), "r"(b[1]));
}

// ---------------- tf32 truncation pass (rna) --------------------------------
__global__ __launch_bounds__(256) void trunc_kernel(
    const float* __restrict__ src, float* __restrict__ dst, int n4)
{
    int i = blockIdx.x * 256 + threadIdx.x;
    if (i < n4) {
        float4 v = ((const float4*)src)[i];
        v.x = f2tff(v.x); v.y = f2tff(v.y); v.z = f2tff(v.z); v.w = f2tff(v.w);
        ((float4*)dst)[i] = v;
    }
}

// ================= TF32 tensor-core GEMM (inputs pre-rounded) ==============
#define ASTR 36
#define BSTR 132
#define ATILE (128 * ASTR)
#define BTILE (32 * BSTR)
#define STAGEF (ATILE + BTILE)
#define GEMM_SMEM_BYTES (3 * STAGEF * 4)

__global__ __launch_bounds__(256, 2) void gemm_tf32(
    const float* __restrict__ A, const float* __restrict__ B,
    float* __restrict__ C, int M, int N, int K)
{
    extern __shared__ float sm[];
    const int tid = threadIdx.x;
    const int warp = tid >> 5, lane = tid & 31;
    const long bm = (long)blockIdx.y * 128, bn = (long)blockIdx.x * 128;
    const int wm = (warp & 1) * 64, wn = (warp >> 1) * 32;

    float acc[4][4][4];
#pragma unroll
    for (int mt = 0; mt < 4; mt++)
#pragma unroll
        for (int nt = 0; nt < 4; nt++)
#pragma unroll
            for (int u = 0; u < 4; u++) acc[mt][nt][u] = 0.f;

    const int arow = tid >> 1;
    const int aq = tid & 1;
    const int bk = tid >> 5;
    const int bn4 = lane * 4;

    auto load_tile = [&](int s, int k0) {
        const float* gA = A + (bm + arow) * (long)K + k0;
        float* sA = sm + s * STAGEF + arow * ASTR;
#pragma unroll
        for (int p = 0; p < 4; p++) {
            int q = aq + p * 2;
            unsigned sa = (unsigned)__cvta_generic_to_shared(sA + q * 4);
            asm volatile("cp.async.cg.shared.global [%0], [%1], 16;\n"
                         :: "r"(sa), "l"(gA + q * 4));
        }
        float* sB = sm + s * STAGEF + ATILE;
#pragma unroll
        for (int p = 0; p < 4; p++) {
            int kr = bk + p * 8;
            const float* gB = B + (long)(k0 + kr) * N + bn + bn4;
            unsigned sb = (unsigned)__cvta_generic_to_shared(sB + kr * BSTR + bn4);
            asm volatile("cp.async.cg.shared.global [%0], [%1], 16;\n"
                         :: "r"(sb), "l"(gB));
        }
    };

    const int nk = K >> 5;
    load_tile(0, 0);
    asm volatile("cp.async.commit_group;\n");
    load_tile(1, 32);
    asm volatile("cp.async.commit_group;\n");

    for (int it = 0; it < nk; it++) {
        const int s = it % 3;
        if (it + 2 < nk) {
            load_tile((it + 2) % 3, (it + 2) * 32);
            asm volatile("cp.async.commit_group;\n");
            asm volatile("cp.async.wait_group 2;\n");
        } else if (it + 1 < nk) {
            asm volatile("cp.async.wait_group 1;\n");
        } else {
            asm volatile("cp.async.wait_group 0;\n");
        }
        __syncthreads();

        const float* sA = sm + s * STAGEF;
        const float* sB = sm + s * STAGEF + ATILE;
#pragma unroll
        for (int kk = 0; kk < 4; kk++) {
            const int k0 = kk * 8;
            unsigned a[4][4], b[4][2];
#pragma unroll
            for (int mt = 0; mt < 4; mt++) {
                const float* ap = sA + (wm + mt * 16 + (lane >> 2)) * ASTR + k0 + (lane & 3);
                a[mt][0] = __float_as_uint(ap[0]);
                a[mt][1] = __float_as_uint(ap[8 * ASTR]);
                a[mt][2] = __float_as_uint(ap[4]);
                a[mt][3] = __float_as_uint(ap[8 * ASTR + 4]);
            }
#pragma unroll
            for (int nt = 0; nt < 4; nt++) {
                const float* bp = sB + (k0 + (lane & 3)) * BSTR + wn + nt * 8 + (lane >> 2);
                b[nt][0] = __float_as_uint(bp[0]);
                b[nt][1] = __float_as_uint(bp[4 * BSTR]);
            }
#pragma unroll
            for (int mt = 0; mt < 4; mt++)
#pragma unroll
                for (int nt = 0; nt < 4; nt++) mma_tf32(acc[mt][nt], a[mt], b[nt]);
        }
        __syncthreads();
    }

    float* Cb = C + (bm + wm) * (long)N + bn + wn;
#pragma unroll
    for (int mt = 0; mt < 4; mt++) {
        const int row0 = mt * 16 + (lane >> 2);
#pragma unroll
        for (int nt = 0; nt < 4; nt++) {
            const int col = nt * 8 + 2 * (lane & 3);
            *(float2*)(Cb + (long)row0 * N + col) =
                make_float2(acc[mt][nt][0], acc[mt][nt][1]);
            *(float2*)(Cb + (long)(row0 + 8) * N + col) =
                make_float2(acc[mt][nt][2], acc[mt][nt][3]);
        }
    }
}

// ---------------- low-rank gate: tmp = h @ Wgk1  (K=1024, N=16) ------------
__global__ __launch_bounds__(256) void gemm16_kernel(
    const float* __restrict__ A, const float* __restrict__ W)
{
    int idx = blockIdx.x * 256 + threadIdx.x;
    int row = idx >> 4, col = idx & 15;
    const float* a = A + (long)row * HID;
    float acc = 0.f;
#pragma unroll 8
    for (int k = 0; k < HID; k++) acc += a[k] * W[k * 16 + col];
    g_t16[idx] = acc;
}

// ---------------- gk = log_sigmoid(tmp @ Wgk2 + b) / 16 --------------------
__global__ __launch_bounds__(256) void gk_kernel(
    const float* __restrict__ W2, const float* __restrict__ bias)
{
    int idx = blockIdx.x * 256 + threadIdx.x;
    int row = idx >> 10, c = idx & 1023;
    const float* t = g_t16 + row * 16;
    float acc = bias[c];
#pragma unroll
    for (int l = 0; l < 16; l++) acc += t[l] * W2[l * DK + c];
    float ls = (acc >= 0.f) ? -log1pf(expf(-acc)) : (acc - log1pf(expf(acc)));
    g_gk[idx] = ls * 0.0625f;
}

// ---------------- gate prep: qg/ki (tf32-rounded) + eb per (b,chunk,col) ---
__global__ __launch_bounds__(256) void gateprep_kernel()
{
    const int col = blockIdx.x * 256 + threadIdx.x;    // 0..DK-1
    const int bn = blockIdx.y;                          // b*NCHUNK + n
    const int b = bn / NCHUNK, n = bn % NCHUNK;
    const long base = ((long)(b * SEQL + n * CHUNK)) * DK + col;
    const float* gkp = g_gk + base;
    const float* qp = g_q + base;
    const float* kp = g_k + base;
    float* qgp = g_qg + base;
    float* kip = g_ki + base;
    const float scale = 0.0625f;

    float bsum = 0.f, ep = 1.f;
#pragma unroll 4
    for (int t = 0; t < CHUNK; t++) {
        bsum += gkp[(long)t * DK];
        ep = __expf(bsum);
        float en = __expf(-bsum);
        qgp[(long)t * DK] = f2tff(qp[(long)t * DK] * ep * scale);
        kip[(long)t * DK] = f2tff(kp[(long)t * DK] * en);
    }
    g_eb[(long)bn * DK + col] = ep;
}

// ================= chunked GLA recurrence (tensor-core) =====================
// grid (8 v-slices of 64, 16 bh), 256 threads (8 warps).
#define QSTR 257
#define VSTR 65
#define STSTR 257
#define GLA_SMEM_FLOATS (2 * 64 * QSTR + 64 * STSTR + 2 * 64 * VSTR + 256)

__global__ __launch_bounds__(256) void gla_kernel()
{
    extern __shared__ float sm[];
    float* qg  = sm;                        // [64][QSTR]  (i x d)  tf32 bits
    float* ki  = qg + 64 * QSTR;            // [64][QSTR]  (t x d)  tf32 bits
    float* ST  = ki + 64 * QSTR;            // [64 v][STSTR] S^T fp32
    float* vtT = ST + 64 * STSTR;           // [64 v][VSTR] v^T tf32 bits
    float* sc  = vtT + 64 * VSTR;           // [64 i][VSTR] tf32 bits
    float* eb  = sc + 64 * VSTR;            // [256]

    const int tid = threadIdx.x;
    const int warp = tid >> 5, lane = tid & 31;
    const int r = lane >> 2, cl = lane & 3, cl2 = 2 * (lane & 3);
    const int vs = blockIdx.x;
    const int bh = blockIdx.y;
    const int b = bh >> 2, hh = bh & 3;

    const int wm = (warp & 3) * 16;
    const int wn = (warp >> 2) * 32;

    for (int i = tid; i < 64 * STSTR; i += 256) ST[i] = 0.f;
    __syncthreads();

    for (int n = 0; n < NCHUNK; n++) {
        // ---- phase A: tile loads (qg/ki pre-gated + pre-rounded) ----------
        {
            eb[tid] = g_eb[((long)(b * NCHUNK + n)) * DK + hh * HDK + tid];
            const long rowbase = (long)(b * SEQL + n * CHUNK);
            const float4* qsrc = (const float4*)(g_qg + rowbase * DK + hh * HDK);
            const float4* ksrc = (const float4*)(g_ki + rowbase * DK + hh * HDK);
#pragma unroll
            for (int idx = tid; idx < 64 * 64; idx += 256) {
                int t = idx >> 6, c4 = idx & 63;
                float4 vq = qsrc[t * (DK / 4) + c4];
                float* qd = qg + t * QSTR + c4 * 4;
                qd[0] = vq.x; qd[1] = vq.y; qd[2] = vq.z; qd[3] = vq.w;
                float4 vk = ksrc[t * (DK / 4) + c4];
                float* kd = ki + t * QSTR + c4 * 4;
                kd[0] = vk.x; kd[1] = vk.y; kd[2] = vk.z; kd[3] = vk.w;
            }
            const long vbase = rowbase * DV + hh * HDV + vs * 64;
#pragma unroll
            for (int i = tid; i < 64 * 64; i += 256) {
                int t = i >> 6, vo = i & 63;
                vtT[vo * VSTR + t] = f2tff(g_v[vbase + (long)t * DV + vo]);
            }
        }
        __syncthreads();

        // ---- phase B: scores = qg @ ki^T, causal mask, tf32-rounded store -
        {
            float c[4][4];
#pragma unroll
            for (int ns = 0; ns < 4; ns++)
#pragma unroll
                for (int u = 0; u < 4; u++) c[ns][u] = 0.f;
#pragma unroll 4
            for (int k0 = 0; k0 < HDK; k0 += 8) {
                unsigned a[4];
                const float* ap = qg + (wm + r) * QSTR + k0 + cl;
                a[0] = __float_as_uint(ap[0]);
                a[1] = __float_as_uint(ap[8 * QSTR]);
                a[2] = __float_as_uint(ap[4]);
                a[3] = __float_as_uint(ap[8 * QSTR + 4]);
#pragma unroll
                for (int ns = 0; ns < 4; ns++) {
                    unsigned bb[2];
                    const float* bp = ki + (wn + ns * 8 + r) * QSTR + k0 + cl;
                    bb[0] = __float_as_uint(bp[0]);
                    bb[1] = __float_as_uint(bp[4]);
                    mma_tf32(c[ns], a, bb);
                }
            }
            const int row0 = wm + r, row1 = wm + r + 8;
#pragma unroll
            for (int ns = 0; ns < 4; ns++) {
                const int col = wn + ns * 8 + cl2;
                sc[row0 * VSTR + col]     = (col     <= row0) ? f2tff(c[ns][0]) : 0.f;
                sc[row0 * VSTR + col + 1] = (col + 1 <= row0) ? f2tff(c[ns][1]) : 0.f;
                sc[row1 * VSTR + col]     = (col     <= row1) ? f2tff(c[ns][2]) : 0.f;
                sc[row1 * VSTR + col + 1] = (col + 1 <= row1) ? f2tff(c[ns][3]) : 0.f;
            }
        }
        __syncthreads();

        // ---- phase C: o = sc @ v + qg @ S (OLD S) --------------------------
        {
            float o[4][4];
#pragma unroll
            for (int ns = 0; ns < 4; ns++)
#pragma unroll
                for (int u = 0; u < 4; u++) o[ns][u] = 0.f;
#pragma unroll
            for (int k0 = 0; k0 < CHUNK; k0 += 8) {
                unsigned a[4];
                const float* ap = sc + (wm + r) * VSTR + k0 + cl;
                a[0] = __float_as_uint(ap[0]);
                a[1] = __float_as_uint(ap[8 * VSTR]);
                a[2] = __float_as_uint(ap[4]);
                a[3] = __float_as_uint(ap[8 * VSTR + 4]);
#pragma unroll
                for (int ns = 0; ns < 4; ns++) {
                    unsigned bb[2];
                    const float* bp = vtT + (wn + ns * 8 + r) * VSTR + k0 + cl;
                    bb[0] = __float_as_uint(bp[0]);
                    bb[1] = __float_as_uint(bp[4]);
                    mma_tf32(o[ns], a, bb);
                }
            }
#pragma unroll 4
            for (int k0 = 0; k0 < HDK; k0 += 8) {
                unsigned a[4];
                const float* ap = qg + (wm + r) * QSTR + k0 + cl;
                a[0] = __float_as_uint(ap[0]);
                a[1] = __float_as_uint(ap[8 * QSTR]);
                a[2] = __float_as_uint(ap[4]);
                a[3] = __float_as_uint(ap[8 * QSTR + 4]);
#pragma unroll
                for (int ns = 0; ns < 4; ns++) {
                    unsigned bb[2];
                    const float* bp = ST + (wn + ns * 8 + r) * STSTR + k0 + cl;
                    bb[0] = f2tf(bp[0]);
                    bb[1] = f2tf(bp[4]);
                    mma_tf32(o[ns], a, bb);
                }
            }
            const long orow = (long)(b * SEQL + n * CHUNK);
            const long ocol = hh * HDV + vs * 64;
            float* op = g_o + (orow + wm + r) * (long)DV + ocol + wn;
            float* op8 = op + 8 * DV;
#pragma unroll
            for (int ns = 0; ns < 4; ns++) {
                const int col = ns * 8 + cl2;
                *(float2*)(op + col)  = make_float2(o[ns][0], o[ns][1]);
                *(float2*)(op8 + col) = make_float2(o[ns][2], o[ns][3]);
            }
        }
        __syncthreads();

        // ---- phase D: S = eb[d] * (S + ki^T @ v) ---------------------------
        {
#pragma unroll
            for (int mt = 0; mt < 2; mt++) {
                const int m0 = warp * 32 + mt * 16;
                float cD[8][4];
#pragma unroll
                for (int ns = 0; ns < 8; ns++)
#pragma unroll
                    for (int u = 0; u < 4; u++) cD[ns][u] = 0.f;
#pragma unroll
                for (int k0 = 0; k0 < CHUNK; k0 += 8) {
                    unsigned a[4];
                    const float* ap = ki + (k0 + cl) * QSTR + m0 + r;
                    a[0] = __float_as_uint(ap[0]);
                    a[1] = __float_as_uint(ap[8]);
                    a[2] = __float_as_uint(ap[4 * QSTR]);
                    a[3] = __float_as_uint(ap[4 * QSTR + 8]);
#pragma unroll
                    for (int ns = 0; ns < 8; ns++) {
                        unsigned bb[2];
                        const float* bp = vtT + (ns * 8 + r) * VSTR + k0 + cl;
                        bb[0] = __float_as_uint(bp[0]);
                        bb[1] = __float_as_uint(bp[4]);
                        mma_tf32(cD[ns], a, bb);
                    }
                }
                const float e0 = eb[m0 + r];
                const float e1 = eb[m0 + r + 8];
#pragma unroll
                for (int ns = 0; ns < 8; ns++) {
                    const int col = ns * 8 + cl2;
                    float* s00 = ST + col * STSTR + m0 + r;
                    float* s01 = ST + (col + 1) * STSTR + m0 + r;
                    s00[0] = e0 * (s00[0] + cD[ns][0]);
                    s01[0] = e0 * (s01[0] + cD[ns][1]);
                    s00[8] = e1 * (s00[8] + cD[ns][2]);
                    s01[8] = e1 * (s01[8] + cD[ns][3]);
                }
            }
        }
        __syncthreads();
    }
}

// ---------------- RMS norm + swish gate (tf32-rounded output) --------------
__global__ __launch_bounds__(256) void normgate_kernel(const float* __restrict__ gnw)
{
    const int row = blockIdx.x;
    const int tid = threadIdx.x;
    const long base = (long)(row >> 2) * DV + (row & 3) * HDV;
    const float* op = g_o + base;
    const float* gp = g_gt + base;
    float* ogp = g_og + base;

    float vals[2];
    float ss = 0.f;
#pragma unroll
    for (int u = 0; u < 2; u++) {
        vals[u] = op[tid + 256 * u];
        ss += vals[u] * vals[u];
    }
    __shared__ float red[8];
#pragma unroll
    for (int o = 16; o > 0; o >>= 1) ss += __shfl_xor_sync(0xffffffffu, ss, o);
    if ((tid & 31) == 0) red[tid >> 5] = ss;
    __syncthreads();
    if (tid < 8) {
        float rr = red[tid];
#pragma unroll
        for (int o = 4; o > 0; o >>= 1) rr += __shfl_xor_sync(0xffu, rr, o);
        if (tid == 0) red[0] = rr;
    }
    __syncthreads();
    const float rinv = rsqrtf(red[0] * (1.f / 512.f) + 1e-5f);
#pragma unroll
    for (int u = 0; u < 2; u++) {
        int c = tid + 256 * u;
        float g = gp[c];
        float sig = 1.f / (1.f + __expf(-g));
        ogp[c] = f2tff(vals[u] * rinv * gnw[c] * (g * sig));
    }
}

// ---------------- launch ----------------------------------------------------
extern "C" void kernel_launch(void* const* d_in, const int* in_sizes, int n_in,
                              void* d_out, int out_size)
{
    (void)in_sizes; (void)n_in; (void)out_size;
    const float* h    = (const float*)d_in[0];
    const float* Wq   = (const float*)d_in[1];
    const float* Wk   = (const float*)d_in[2];
    const float* Wv   = (const float*)d_in[3];
    const float* Wg   = (const float*)d_in[4];
    const float* Wgk1 = (const float*)d_in[5];
    const float* Wgk2 = (const float*)d_in[6];
    const float* bgk2 = (const float*)d_in[7];
    const float* gnw  = (const float*)d_in[8];
    const float* Wo   = (const float*)d_in[9];
    float* out = (float*)d_out;

    void *pq, *pk, *pv, *pg, *pog, *pht, *pwq, *pwk, *pwv, *pwg, *pwo;
    cudaGetSymbolAddress(&pq, g_q);
    cudaGetSymbolAddress(&pk, g_k);
    cudaGetSymbolAddress(&pv, g_v);
    cudaGetSymbolAddress(&pg, g_gt);
    cudaGetSymbolAddress(&pog, g_og);
    cudaGetSymbolAddress(&pht, g_ht);
    cudaGetSymbolAddress(&pwq, g_wqt);
    cudaGetSymbolAddress(&pwk, g_wkt);
    cudaGetSymbolAddress(&pwv, g_wvt);
    cudaGetSymbolAddress(&pwg, g_wgt);
    cudaGetSymbolAddress(&pwo, g_wot);

    static_assert(GLA_SMEM_FLOATS * 4 <= 232448, "gla smem too big");
    cudaFuncSetAttribute(gla_kernel, cudaFuncAttributeMaxDynamicSharedMemorySize,
                         GLA_SMEM_FLOATS * 4);
    cudaFuncSetAttribute(gemm_tf32, cudaFuncAttributeMaxDynamicSharedMemorySize,
                         GEMM_SMEM_BYTES);

    dim3 t256(256);
    // tf32 pre-rounding passes
    trunc_kernel<<<(BL * HID / 4 + 255) / 256, t256>>>(h, (float*)pht, BL * HID / 4);
    trunc_kernel<<<(HID * DK / 4 + 255) / 256, t256>>>(Wq, (float*)pwq, HID * DK / 4);
    trunc_kernel<<<(HID * DK / 4 + 255) / 256, t256>>>(Wk, (float*)pwk, HID * DK / 4);
    trunc_kernel<<<(HID * DV / 4 + 255) / 256, t256>>>(Wv, (float*)pwv, HID * DV / 4);
    trunc_kernel<<<(HID * DV / 4 + 255) / 256, t256>>>(Wg, (float*)pwg, HID * DV / 4);
    trunc_kernel<<<(DV * HID / 4 + 255) / 256, t256>>>(Wo, (float*)pwo, DV * HID / 4);

    // projections (tf32 tensor cores)
    gemm_tf32<<<dim3(DK / 128, BL / 128), t256, GEMM_SMEM_BYTES>>>((const float*)pht, (const float*)pwq, (float*)pq, BL, DK, HID);
    gemm_tf32<<<dim3(DK / 128, BL / 128), t256, GEMM_SMEM_BYTES>>>((const float*)pht, (const float*)pwk, (float*)pk, BL, DK, HID);
    gemm_tf32<<<dim3(DV / 128, BL / 128), t256, GEMM_SMEM_BYTES>>>((const float*)pht, (const float*)pwv, (float*)pv, BL, DV, HID);
    gemm_tf32<<<dim3(DV / 128, BL / 128), t256, GEMM_SMEM_BYTES>>>((const float*)pht, (const float*)pwg, (float*)pg, BL, DV, HID);
    // low-rank gate path (fp32, uses original h)
    gemm16_kernel<<<(BL * 16) / 256, t256>>>(h, Wgk1);
    gk_kernel<<<(BL * DK) / 256, t256>>>(Wgk2, bgk2);
    // gate prep (qg/ki/eb)
    gateprep_kernel<<<dim3(DK / 256, BATCH * NCHUNK), t256>>>();
    // chunked GLA
    gla_kernel<<<dim3(HDV / 64, BATCH * NH), t256, GLA_SMEM_FLOATS * 4>>>();
    // rms norm + swish gate
    normgate_kernel<<<BL * NH, t256>>>(gnw);
    // output projection
    gemm_tf32<<<dim3(HID / 128, BL / 128), t256, GEMM_SMEM_BYTES>>>((const float*)pog, (const float*)pwo, out, BL, HID, DV);
}

// round 6
// speedup vs baseline: 4.0383x; 1.0834x over previous
#include <cuda_runtime.h>
#include <math.h>

#define BATCH 4
#define SEQL 2048
#define HID 1024
#define NH 4
#define DK 1024
#define DV 2048
#define HDK 256
#define HDV 512
#define CHUNK 64
#define NCHUNK (SEQL / CHUNK)
#define BL (BATCH * SEQL) /* 8192 */
#define BH (BATCH * NH)   /* 16 */

// ---------------- scratch (static device allocations; no runtime alloc) ----
__device__ float g_q[BL * DK];
__device__ float g_k[BL * DK];
__device__ float g_v[BL * DV];
__device__ float g_gt[BL * DV];
__device__ float g_gk[BL * DK];
__device__ float g_t16[BL * 16];
__device__ float g_o[BL * DV];
__device__ float g_og[BL * DV];
// tf32-prerounded copies / gate-prep outputs
__device__ float g_ht[BL * HID];
__device__ float g_wqt[HID * DK];
__device__ float g_wkt[HID * DK];
__device__ float g_wvt[HID * DV];
__device__ float g_wgt[HID * DV];
__device__ float g_wot[DV * HID];
__device__ float g_qg[BL * DK];
__device__ float g_ki[BL * DK];
__device__ float g_eb[BATCH * NCHUNK * DK];
// materialized chunk-start states: [bh][n][v(512)][d(256)]
__device__ float g_S[(long)BH * NCHUNK * HDV * HDK];

// ================= common tf32 mma helpers =================================
__device__ __forceinline__ unsigned f2tf(float f) {
    unsigned r;
    asm("cvt.rna.tf32.f32 %0, %1;" : "=r"(r) : "f"(f));
    return r;
}
__device__ __forceinline__ float f2tff(float f) { return __uint_as_float(f2tf(f)); }

__device__ __forceinline__ void mma_tf32(float* c, const unsigned* a, const unsigned* b) {
    asm volatile(
        "mma.sync.aligned.m16n8k8.row.col.f32.tf32.tf32.f32 "
        "{%0,%1,%2,%3}, {%4,%5,%6,%7}, {%8,%9}, {%0,%1,%2,%3};"
        : "+f"(c[0]), "+f"(c[1]), "+f"(c[2]), "+f"(c[3])
        : "r"(a[0]), "r"(a[1]), "r"(a[2]), "r"(a[3]), "r"(b[0]), "r"(b[1]));
}

// ---------------- tf32 truncation pass (rna) --------------------------------
__global__ __launch_bounds__(256) void trunc_kernel(
    const float* __restrict__ src, float* __restrict__ dst, int n4)
{
    int i = blockIdx.x * 256 + threadIdx.x;
    if (i < n4) {
        float4 v = ((const float4*)src)[i];
        v.x = f2tff(v.x); v.y = f2tff(v.y); v.z = f2tff(v.z); v.w = f2tff(v.w);
        ((float4*)dst)[i] = v;
    }
}

// ================= TF32 tensor-core GEMM (inputs pre-rounded) ==============
#define ASTR 36
#define BSTR 132
#define ATILE (128 * ASTR)
#define BTILE (32 * BSTR)
#define STAGEF (ATILE + BTILE)
#define GEMM_SMEM_BYTES (3 * STAGEF * 4)

__global__ __launch_bounds__(256, 2) void gemm_tf32(
    const float* __restrict__ A, const float* __restrict__ B,
    float* __restrict__ C, int M, int N, int K)
{
    extern __shared__ float sm[];
    const int tid = threadIdx.x;
    const int warp = tid >> 5, lane = tid & 31;
    const long bm = (long)blockIdx.y * 128, bn = (long)blockIdx.x * 128;
    const int wm = (warp & 1) * 64, wn = (warp >> 1) * 32;

    float acc[4][4][4];
#pragma unroll
    for (int mt = 0; mt < 4; mt++)
#pragma unroll
        for (int nt = 0; nt < 4; nt++)
#pragma unroll
            for (int u = 0; u < 4; u++) acc[mt][nt][u] = 0.f;

    const int arow = tid >> 1;
    const int aq = tid & 1;
    const int bk = tid >> 5;
    const int bn4 = lane * 4;

    auto load_tile = [&](int s, int k0) {
        const float* gA = A + (bm + arow) * (long)K + k0;
        float* sA = sm + s * STAGEF + arow * ASTR;
#pragma unroll
        for (int p = 0; p < 4; p++) {
            int q = aq + p * 2;
            unsigned sa = (unsigned)__cvta_generic_to_shared(sA + q * 4);
            asm volatile("cp.async.cg.shared.global [%0], [%1], 16;\n"
                         :: "r"(sa), "l"(gA + q * 4));
        }
        float* sB = sm + s * STAGEF + ATILE;
#pragma unroll
        for (int p = 0; p < 4; p++) {
            int kr = bk + p * 8;
            const float* gB = B + (long)(k0 + kr) * N + bn + bn4;
            unsigned sb = (unsigned)__cvta_generic_to_shared(sB + kr * BSTR + bn4);
            asm volatile("cp.async.cg.shared.global [%0], [%1], 16;\n"
                         :: "r"(sb), "l"(gB));
        }
    };

    const int nk = K >> 5;
    load_tile(0, 0);
    asm volatile("cp.async.commit_group;\n");
    load_tile(1, 32);
    asm volatile("cp.async.commit_group;\n");

    for (int it = 0; it < nk; it++) {
        const int s = it % 3;
        if (it + 2 < nk) {
            load_tile((it + 2) % 3, (it + 2) * 32);
            asm volatile("cp.async.commit_group;\n");
            asm volatile("cp.async.wait_group 2;\n");
        } else if (it + 1 < nk) {
            asm volatile("cp.async.wait_group 1;\n");
        } else {
            asm volatile("cp.async.wait_group 0;\n");
        }
        __syncthreads();

        const float* sA = sm + s * STAGEF;
        const float* sB = sm + s * STAGEF + ATILE;
#pragma unroll
        for (int kk = 0; kk < 4; kk++) {
            const int k0 = kk * 8;
            unsigned a[4][4], b[4][2];
#pragma unroll
            for (int mt = 0; mt < 4; mt++) {
                const float* ap = sA + (wm + mt * 16 + (lane >> 2)) * ASTR + k0 + (lane & 3);
                a[mt][0] = __float_as_uint(ap[0]);
                a[mt][1] = __float_as_uint(ap[8 * ASTR]);
                a[mt][2] = __float_as_uint(ap[4]);
                a[mt][3] = __float_as_uint(ap[8 * ASTR + 4]);
            }
#pragma unroll
            for (int nt = 0; nt < 4; nt++) {
                const float* bp = sB + (k0 + (lane & 3)) * BSTR + wn + nt * 8 + (lane >> 2);
                b[nt][0] = __float_as_uint(bp[0]);
                b[nt][1] = __float_as_uint(bp[4 * BSTR]);
            }
#pragma unroll
            for (int mt = 0; mt < 4; mt++)
#pragma unroll
                for (int nt = 0; nt < 4; nt++) mma_tf32(acc[mt][nt], a[mt], b[nt]);
        }
        __syncthreads();
    }

    float* Cb = C + (bm + wm) * (long)N + bn + wn;
#pragma unroll
    for (int mt = 0; mt < 4; mt++) {
        const int row0 = mt * 16 + (lane >> 2);
#pragma unroll
        for (int nt = 0; nt < 4; nt++) {
            const int col = nt * 8 + 2 * (lane & 3);
            *(float2*)(Cb + (long)row0 * N + col) =
                make_float2(acc[mt][nt][0], acc[mt][nt][1]);
            *(float2*)(Cb + (long)(row0 + 8) * N + col) =
                make_float2(acc[mt][nt][2], acc[mt][nt][3]);
        }
    }
}

// ---------------- low-rank gate: tmp = h @ Wgk1  (K=1024, N=16) ------------
__global__ __launch_bounds__(256) void gemm16_kernel(
    const float* __restrict__ A, const float* __restrict__ W)
{
    int idx = blockIdx.x * 256 + threadIdx.x;
    int row = idx >> 4, col = idx & 15;
    const float* a = A + (long)row * HID;
    float acc = 0.f;
#pragma unroll 8
    for (int k = 0; k < HID; k++) acc += a[k] * W[k * 16 + col];
    g_t16[idx] = acc;
}

// ---------------- gk = log_sigmoid(tmp @ Wgk2 + b) / 16 --------------------
__global__ __launch_bounds__(256) void gk_kernel(
    const float* __restrict__ W2, const float* __restrict__ bias)
{
    int idx = blockIdx.x * 256 + threadIdx.x;
    int row = idx >> 10, c = idx & 1023;
    const float* t = g_t16 + row * 16;
    float acc = bias[c];
#pragma unroll
    for (int l = 0; l < 16; l++) acc += t[l] * W2[l * DK + c];
    float ls = (acc >= 0.f) ? -log1pf(expf(-acc)) : (acc - log1pf(expf(acc)));
    g_gk[idx] = ls * 0.0625f;
}

// ---------------- gate prep: qg/ki (tf32-rounded) + eb per (b,chunk,col) ---
__global__ __launch_bounds__(256) void gateprep_kernel()
{
    const int col = blockIdx.x * 256 + threadIdx.x;    // 0..DK-1
    const int bn = blockIdx.y;                          // b*NCHUNK + n
    const int b = bn / NCHUNK, n = bn % NCHUNK;
    const long base = ((long)(b * SEQL + n * CHUNK)) * DK + col;
    const float* gkp = g_gk + base;
    const float* qp = g_q + base;
    const float* kp = g_k + base;
    float* qgp = g_qg + base;
    float* kip = g_ki + base;
    const float scale = 0.0625f;

    float bsum = 0.f, ep = 1.f;
#pragma unroll 4
    for (int t = 0; t < CHUNK; t++) {
        bsum += gkp[(long)t * DK];
        ep = __expf(bsum);
        float en = __expf(-bsum);
        qgp[(long)t * DK] = f2tff(qp[(long)t * DK] * ep * scale);
        kip[(long)t * DK] = f2tff(kp[(long)t * DK] * en);
    }
    g_eb[(long)bn * DK + col] = ep;
}

// ================= GLA split: sequential state kernel ======================
// grid (8 vslices, 16 bh), 256 threads. Per chunk: store S_n, update S.
#define QSTR 257
#define VSTR 65
#define STSTR 260  /* 16B-aligned rows, conflict-free col writes */
#define STATE_SMEM_FLOATS (64 * QSTR + 64 * STSTR + 64 * VSTR + 256)

__global__ __launch_bounds__(256) void gla_state_kernel()
{
    extern __shared__ float sm[];
    float* ki  = sm;                        // [64 t][QSTR] (t x d)
    float* ST  = ki + 64 * QSTR;            // [64 v][STSTR] S^T fp32
    float* vtT = ST + 64 * STSTR;           // [64 v][VSTR]
    float* eb  = vtT + 64 * VSTR;           // [256]

    const int tid = threadIdx.x;
    const int warp = tid >> 5, lane = tid & 31;
    const int r = lane >> 2, cl = lane & 3, cl2 = 2 * (lane & 3);
    const int vs = blockIdx.x;
    const int bh = blockIdx.y;
    const int b = bh >> 2, hh = bh & 3;

    for (int i = tid; i < 64 * STSTR; i += 256) ST[i] = 0.f;
    __syncthreads();

    for (int n = 0; n < NCHUNK; n++) {
        // ---- store S_n (chunk-start state) to global, [v][d] coalesced ----
        {
            const long sbase = ((long)(bh * NCHUNK + n) * HDV + vs * 64) * HDK;
#pragma unroll
            for (int idx = tid; idx < 64 * 64; idx += 256) {
                int row = idx >> 6, c4 = idx & 63;
                const float* srow = ST + row * STSTR + c4 * 4;
                ((float4*)(g_S + sbase + (long)row * HDK))[c4] =
                    make_float4(srow[0], srow[1], srow[2], srow[3]);
            }
        }
        // ---- load eb, ki tile, v tile --------------------------------------
        {
            eb[tid] = g_eb[((long)(b * NCHUNK + n)) * DK + hh * HDK + tid];
            const long rowbase = (long)(b * SEQL + n * CHUNK);
            const float4* ksrc = (const float4*)(g_ki + rowbase * DK + hh * HDK);
#pragma unroll
            for (int idx = tid; idx < 64 * 64; idx += 256) {
                int t = idx >> 6, c4 = idx & 63;
                float4 vk = ksrc[t * (DK / 4) + c4];
                float* kd = ki + t * QSTR + c4 * 4;
                kd[0] = vk.x; kd[1] = vk.y; kd[2] = vk.z; kd[3] = vk.w;
            }
            const long vbase = rowbase * DV + hh * HDV + vs * 64;
#pragma unroll
            for (int i = tid; i < 64 * 64; i += 256) {
                int t = i >> 6, vo = i & 63;
                vtT[vo * VSTR + t] = f2tff(g_v[vbase + (long)t * DV + vo]);
            }
        }
        __syncthreads();

        // ---- S = eb[d] * (S + ki^T @ v) ------------------------------------
        {
#pragma unroll
            for (int mt = 0; mt < 2; mt++) {
                const int m0 = warp * 32 + mt * 16;
                float cD[8][4];
#pragma unroll
                for (int ns = 0; ns < 8; ns++)
#pragma unroll
                    for (int u = 0; u < 4; u++) cD[ns][u] = 0.f;
#pragma unroll
                for (int k0 = 0; k0 < CHUNK; k0 += 8) {
                    unsigned a[4];
                    const float* ap = ki + (k0 + cl) * QSTR + m0 + r;
                    a[0] = __float_as_uint(ap[0]);
                    a[1] = __float_as_uint(ap[8]);
                    a[2] = __float_as_uint(ap[4 * QSTR]);
                    a[3] = __float_as_uint(ap[4 * QSTR + 8]);
#pragma unroll
                    for (int ns = 0; ns < 8; ns++) {
                        unsigned bb[2];
                        const float* bp = vtT + (ns * 8 + r) * VSTR + k0 + cl;
                        bb[0] = __float_as_uint(bp[0]);
                        bb[1] = __float_as_uint(bp[4]);
                        mma_tf32(cD[ns], a, bb);
                    }
                }
                const float e0 = eb[m0 + r];
                const float e1 = eb[m0 + r + 8];
#pragma unroll
                for (int ns = 0; ns < 8; ns++) {
                    const int col = ns * 8 + cl2;
                    float* s00 = ST + col * STSTR + m0 + r;
                    float* s01 = ST + (col + 1) * STSTR + m0 + r;
                    s00[0] = e0 * (s00[0] + cD[ns][0]);
                    s01[0] = e0 * (s01[0] + cD[ns][1]);
                    s00[8] = e1 * (s00[8] + cD[ns][2]);
                    s01[8] = e1 * (s01[8] + cD[ns][3]);
                }
            }
        }
        __syncthreads();
    }
}

// ================= GLA split: parallel output kernel ========================
// grid (32 chunks, 16 bh), 256 threads. scores once, then 8 v-slices.
#define OUT_SMEM_FLOATS (2 * 64 * QSTR + 64 * VSTR + 64 * STSTR + 64 * VSTR)

__global__ __launch_bounds__(256) void gla_out_kernel()
{
    extern __shared__ float sm[];
    float* qg  = sm;                        // [64 i][QSTR]
    float* ki  = qg + 64 * QSTR;            // [64 t][QSTR]
    float* sc  = ki + 64 * QSTR;            // [64 i][VSTR]
    float* ST  = sc + 64 * VSTR;            // [64 v][STSTR] S_n slice
    float* vtT = ST + 64 * STSTR;           // [64 v][VSTR]

    const int tid = threadIdx.x;
    const int warp = tid >> 5, lane = tid & 31;
    const int r = lane >> 2, cl = lane & 3, cl2 = 2 * (lane & 3);
    const int n = blockIdx.x;
    const int bh = blockIdx.y;
    const int b = bh >> 2, hh = bh & 3;

    const int wm = (warp & 3) * 16;
    const int wn = (warp >> 2) * 32;

    const long rowbase = (long)(b * SEQL + n * CHUNK);

    // ---- load qg/ki tiles ---------------------------------------------------
    {
        const float4* qsrc = (const float4*)(g_qg + rowbase * DK + hh * HDK);
        const float4* ksrc = (const float4*)(g_ki + rowbase * DK + hh * HDK);
#pragma unroll
        for (int idx = tid; idx < 64 * 64; idx += 256) {
            int t = idx >> 6, c4 = idx & 63;
            float4 vq = qsrc[t * (DK / 4) + c4];
            float* qd = qg + t * QSTR + c4 * 4;
            qd[0] = vq.x; qd[1] = vq.y; qd[2] = vq.z; qd[3] = vq.w;
            float4 vk = ksrc[t * (DK / 4) + c4];
            float* kd = ki + t * QSTR + c4 * 4;
            kd[0] = vk.x; kd[1] = vk.y; kd[2] = vk.z; kd[3] = vk.w;
        }
    }
    __syncthreads();

    // ---- scores = mask(qg @ ki^T), tf32-rounded -----------------------------
    {
        float c[4][4];
#pragma unroll
        for (int ns = 0; ns < 4; ns++)
#pragma unroll
            for (int u = 0; u < 4; u++) c[ns][u] = 0.f;
#pragma unroll 4
        for (int k0 = 0; k0 < HDK; k0 += 8) {
            unsigned a[4];
            const float* ap = qg + (wm + r) * QSTR + k0 + cl;
            a[0] = __float_as_uint(ap[0]);
            a[1] = __float_as_uint(ap[8 * QSTR]);
            a[2] = __float_as_uint(ap[4]);
            a[3] = __float_as_uint(ap[8 * QSTR + 4]);
#pragma unroll
            for (int ns = 0; ns < 4; ns++) {
                unsigned bb[2];
                const float* bp = ki + (wn + ns * 8 + r) * QSTR + k0 + cl;
                bb[0] = __float_as_uint(bp[0]);
                bb[1] = __float_as_uint(bp[4]);
                mma_tf32(c[ns], a, bb);
            }
        }
        const int row0 = wm + r, row1 = wm + r + 8;
#pragma unroll
        for (int ns = 0; ns < 4; ns++) {
            const int col = wn + ns * 8 + cl2;
            sc[row0 * VSTR + col]     = (col     <= row0) ? f2tff(c[ns][0]) : 0.f;
            sc[row0 * VSTR + col + 1] = (col + 1 <= row0) ? f2tff(c[ns][1]) : 0.f;
            sc[row1 * VSTR + col]     = (col     <= row1) ? f2tff(c[ns][2]) : 0.f;
            sc[row1 * VSTR + col + 1] = (col + 1 <= row1) ? f2tff(c[ns][3]) : 0.f;
        }
    }
    __syncthreads();

    // ---- per v-slice: o = sc @ v + qg @ S_n ---------------------------------
    for (int vs = 0; vs < HDV / 64; vs++) {
        // load S_n slice ([v][d] rows, coalesced) and v tile
        {
            const long sbase = ((long)(bh * NCHUNK + n) * HDV + vs * 64) * HDK;
#pragma unroll
            for (int idx = tid; idx < 64 * 64; idx += 256) {
                int row = idx >> 6, c4 = idx & 63;
                float4 v4 = ((const float4*)(g_S + sbase + (long)row * HDK))[c4];
                float* sd = ST + row * STSTR + c4 * 4;
                sd[0] = v4.x; sd[1] = v4.y; sd[2] = v4.z; sd[3] = v4.w;
            }
            const long vbase = rowbase * DV + hh * HDV + vs * 64;
#pragma unroll
            for (int i = tid; i < 64 * 64; i += 256) {
                int t = i >> 6, vo = i & 63;
                vtT[vo * VSTR + t] = f2tff(g_v[vbase + (long)t * DV + vo]);
            }
        }
        __syncthreads();

        {
            float o[4][4];
#pragma unroll
            for (int ns = 0; ns < 4; ns++)
#pragma unroll
                for (int u = 0; u < 4; u++) o[ns][u] = 0.f;
            // sc @ v
#pragma unroll
            for (int k0 = 0; k0 < CHUNK; k0 += 8) {
                unsigned a[4];
                const float* ap = sc + (wm + r) * VSTR + k0 + cl;
                a[0] = __float_as_uint(ap[0]);
                a[1] = __float_as_uint(ap[8 * VSTR]);
                a[2] = __float_as_uint(ap[4]);
                a[3] = __float_as_uint(ap[8 * VSTR + 4]);
#pragma unroll
                for (int ns = 0; ns < 4; ns++) {
                    unsigned bb[2];
                    const float* bp = vtT + (wn + ns * 8 + r) * VSTR + k0 + cl;
                    bb[0] = __float_as_uint(bp[0]);
                    bb[1] = __float_as_uint(bp[4]);
                    mma_tf32(o[ns], a, bb);
                }
            }
            // qg @ S_n
#pragma unroll 4
            for (int k0 = 0; k0 < HDK; k0 += 8) {
                unsigned a[4];
                const float* ap = qg + (wm + r) * QSTR + k0 + cl;
                a[0] = __float_as_uint(ap[0]);
                a[1] = __float_as_uint(ap[8 * QSTR]);
                a[2] = __float_as_uint(ap[4]);
                a[3] = __float_as_uint(ap[8 * QSTR + 4]);
#pragma unroll
                for (int ns = 0; ns < 4; ns++) {
                    unsigned bb[2];
                    const float* bp = ST + (wn + ns * 8 + r) * STSTR + k0 + cl;
                    bb[0] = f2tf(bp[0]);
                    bb[1] = f2tf(bp[4]);
                    mma_tf32(o[ns], a, bb);
                }
            }
            const long ocol = hh * HDV + vs * 64;
            float* op = g_o + (rowbase + wm + r) * (long)DV + ocol + wn;
            float* op8 = op + 8 * DV;
#pragma unroll
            for (int ns = 0; ns < 4; ns++) {
                const int col = ns * 8 + cl2;
                *(float2*)(op + col)  = make_float2(o[ns][0], o[ns][1]);
                *(float2*)(op8 + col) = make_float2(o[ns][2], o[ns][3]);
            }
        }
        __syncthreads();
    }
}

// ---------------- RMS norm + swish gate (tf32-rounded output) --------------
__global__ __launch_bounds__(256) void normgate_kernel(const float* __restrict__ gnw)
{
    const int row = blockIdx.x;
    const int tid = threadIdx.x;
    const long base = (long)(row >> 2) * DV + (row & 3) * HDV;
    const float* op = g_o + base;
    const float* gp = g_gt + base;
    float* ogp = g_og + base;

    float vals[2];
    float ss = 0.f;
#pragma unroll
    for (int u = 0; u < 2; u++) {
        vals[u] = op[tid + 256 * u];
        ss += vals[u] * vals[u];
    }
    __shared__ float red[8];
#pragma unroll
    for (int o = 16; o > 0; o >>= 1) ss += __shfl_xor_sync(0xffffffffu, ss, o);
    if ((tid & 31) == 0) red[tid >> 5] = ss;
    __syncthreads();
    if (tid < 8) {
        float rr = red[tid];
#pragma unroll
        for (int o = 4; o > 0; o >>= 1) rr += __shfl_xor_sync(0xffu, rr, o);
        if (tid == 0) red[0] = rr;
    }
    __syncthreads();
    const float rinv = rsqrtf(red[0] * (1.f / 512.f) + 1e-5f);
#pragma unroll
    for (int u = 0; u < 2; u++) {
        int c = tid + 256 * u;
        float g = gp[c];
        float sig = 1.f / (1.f + __expf(-g));
        ogp[c] = f2tff(vals[u] * rinv * gnw[c] * (g * sig));
    }
}

// ---------------- launch ----------------------------------------------------
extern "C" void kernel_launch(void* const* d_in, const int* in_sizes, int n_in,
                              void* d_out, int out_size)
{
    (void)in_sizes; (void)n_in; (void)out_size;
    const float* h    = (const float*)d_in[0];
    const float* Wq   = (const float*)d_in[1];
    const float* Wk   = (const float*)d_in[2];
    const float* Wv   = (const float*)d_in[3];
    const float* Wg   = (const float*)d_in[4];
    const float* Wgk1 = (const float*)d_in[5];
    const float* Wgk2 = (const float*)d_in[6];
    const float* bgk2 = (const float*)d_in[7];
    const float* gnw  = (const float*)d_in[8];
    const float* Wo   = (const float*)d_in[9];
    float* out = (float*)d_out;

    void *pq, *pk, *pv, *pg, *pog, *pht, *pwq, *pwk, *pwv, *pwg, *pwo;
    cudaGetSymbolAddress(&pq, g_q);
    cudaGetSymbolAddress(&pk, g_k);
    cudaGetSymbolAddress(&pv, g_v);
    cudaGetSymbolAddress(&pg, g_gt);
    cudaGetSymbolAddress(&pog, g_og);
    cudaGetSymbolAddress(&pht, g_ht);
    cudaGetSymbolAddress(&pwq, g_wqt);
    cudaGetSymbolAddress(&pwk, g_wkt);
    cudaGetSymbolAddress(&pwv, g_wvt);
    cudaGetSymbolAddress(&pwg, g_wgt);
    cudaGetSymbolAddress(&pwo, g_wot);

    static_assert(STATE_SMEM_FLOATS * 4 <= 232448, "state smem too big");
    static_assert(OUT_SMEM_FLOATS * 4 <= 232448, "out smem too big");
    cudaFuncSetAttribute(gla_state_kernel, cudaFuncAttributeMaxDynamicSharedMemorySize,
                         STATE_SMEM_FLOATS * 4);
    cudaFuncSetAttribute(gla_out_kernel, cudaFuncAttributeMaxDynamicSharedMemorySize,
                         OUT_SMEM_FLOATS * 4);
    cudaFuncSetAttribute(gemm_tf32, cudaFuncAttributeMaxDynamicSharedMemorySize,
                         GEMM_SMEM_BYTES);

    dim3 t256(256);
    // tf32 pre-rounding passes
    trunc_kernel<<<(BL * HID / 4 + 255) / 256, t256>>>(h, (float*)pht, BL * HID / 4);
    trunc_kernel<<<(HID * DK / 4 + 255) / 256, t256>>>(Wq, (float*)pwq, HID * DK / 4);
    trunc_kernel<<<(HID * DK / 4 + 255) / 256, t256>>>(Wk, (float*)pwk, HID * DK / 4);
    trunc_kernel<<<(HID * DV / 4 + 255) / 256, t256>>>(Wv, (float*)pwv, HID * DV / 4);
    trunc_kernel<<<(HID * DV / 4 + 255) / 256, t256>>>(Wg, (float*)pwg, HID * DV / 4);
    trunc_kernel<<<(DV * HID / 4 + 255) / 256, t256>>>(Wo, (float*)pwo, DV * HID / 4);

    // projections (tf32 tensor cores)
    gemm_tf32<<<dim3(DK / 128, BL / 128), t256, GEMM_SMEM_BYTES>>>((const float*)pht, (const float*)pwq, (float*)pq, BL, DK, HID);
    gemm_tf32<<<dim3(DK / 128, BL / 128), t256, GEMM_SMEM_BYTES>>>((const float*)pht, (const float*)pwk, (float*)pk, BL, DK, HID);
    gemm_tf32<<<dim3(DV / 128, BL / 128), t256, GEMM_SMEM_BYTES>>>((const float*)pht, (const float*)pwv, (float*)pv, BL, DV, HID);
    gemm_tf32<<<dim3(DV / 128, BL / 128), t256, GEMM_SMEM_BYTES>>>((const float*)pht, (const float*)pwg, (float*)pg, BL, DV, HID);
    // low-rank gate path (fp32, uses original h)
    gemm16_kernel<<<(BL * 16) / 256, t256>>>(h, Wgk1);
    gk_kernel<<<(BL * DK) / 256, t256>>>(Wgk2, bgk2);
    // gate prep (qg/ki/eb)
    gateprep_kernel<<<dim3(DK / 256, BATCH * NCHUNK), t256>>>();
    // GLA: sequential state materialization, then parallel output
    gla_state_kernel<<<dim3(HDV / 64, BH), t256, STATE_SMEM_FLOATS * 4>>>();
    gla_out_kernel<<<dim3(NCHUNK, BH), t256, OUT_SMEM_FLOATS * 4>>>();
    // rms norm + swish gate
    normgate_kernel<<<BL * NH, t256>>>(gnw);
    // output projection
    gemm_tf32<<<dim3(HID / 128, BL / 128), t256, GEMM_SMEM_BYTES>>>((const float*)pog, (const float*)pwo, out, BL, HID, DV);
}

// round 7
// speedup vs baseline: 4.3476x; 1.0766x over previous
#include <cuda_runtime.h>
#include <math.h>

#define BATCH 4
#define SEQL 2048
#define HID 1024
#define NH 4
#define DK 1024
#define DV 2048
#define HDK 256
#define HDV 512
#define CHUNK 64
#define NCHUNK (SEQL / CHUNK)
#define BL (BATCH * SEQL) /* 8192 */
#define BH (BATCH * NH)   /* 16 */

// ---------------- scratch (static device allocations; no runtime alloc) ----
__device__ float g_q[BL * DK];
__device__ float g_k[BL * DK];
__device__ float g_v[BL * DV];
__device__ float g_gt[BL * DV];
__device__ float g_gk[BL * DK];
__device__ float g_t16[BL * 16];
__device__ float g_o[BL * DV];
__device__ float g_og[BL * DV];
// tf32-prerounded copies / gate-prep outputs
__device__ float g_ht[BL * HID];
__device__ float g_wqt[HID * DK];
__device__ float g_wkt[HID * DK];
__device__ float g_wvt[HID * DV];
__device__ float g_wgt[HID * DV];
__device__ float g_wot[DV * HID];
__device__ float g_qg[BL * DK];
__device__ float g_ki[BL * DK];
__device__ float g_eb[BATCH * NCHUNK * DK];
// materialized chunk-start states: [bh][n][v(512)][d(256)]
__device__ float g_S[(long)BH * NCHUNK * HDV * HDK];

// ================= common tf32 mma helpers =================================
__device__ __forceinline__ unsigned f2tf(float f) {
    unsigned r;
    asm("cvt.rna.tf32.f32 %0, %1;" : "=r"(r) : "f"(f));
    return r;
}
__device__ __forceinline__ float f2tff(float f) { return __uint_as_float(f2tf(f)); }

__device__ __forceinline__ void mma_tf32(float* c, const unsigned* a, const unsigned* b) {
    asm volatile(
        "mma.sync.aligned.m16n8k8.row.col.f32.tf32.tf32.f32 "
        "{%0,%1,%2,%3}, {%4,%5,%6,%7}, {%8,%9}, {%0,%1,%2,%3};"
        : "+f"(c[0]), "+f"(c[1]), "+f"(c[2]), "+f"(c[3])
        : "r"(a[0]), "r"(a[1]), "r"(a[2]), "r"(a[3]), "r"(b[0]), "r"(b[1]));
}

__device__ __forceinline__ void ldsm_x4(unsigned* r, unsigned addr) {
    asm volatile("ldmatrix.sync.aligned.m8n8.x4.shared.b16 {%0,%1,%2,%3}, [%4];"
                 : "=r"(r[0]), "=r"(r[1]), "=r"(r[2]), "=r"(r[3]) : "r"(addr));
}

// ---------------- tf32 truncation pass (rna) --------------------------------
__global__ __launch_bounds__(256) void trunc_kernel(
    const float* __restrict__ src, float* __restrict__ dst, int n4)
{
    int i = blockIdx.x * 256 + threadIdx.x;
    if (i < n4) {
        float4 v = ((const float4*)src)[i];
        v.x = f2tff(v.x); v.y = f2tff(v.y); v.z = f2tff(v.z); v.w = f2tff(v.w);
        ((float4*)dst)[i] = v;
    }
}

// ================= TF32 tensor-core GEMM (inputs pre-rounded) ==============
// A-frags via ldmatrix.x4 (ASTR=36 conflict-free); B swizzled stride-128.
#define ASTR 36
#define ATILE (128 * ASTR)
#define BTILE (32 * 128)
#define STAGEF (ATILE + BTILE)
#define GEMM_SMEM_BYTES (3 * STAGEF * 4)

__global__ __launch_bounds__(256, 2) void gemm_tf32(
    const float* __restrict__ A, const float* __restrict__ B,
    float* __restrict__ C, int M, int N, int K)
{
    extern __shared__ float sm[];
    const int tid = threadIdx.x;
    const int warp = tid >> 5, lane = tid & 31;
    const long bm = (long)blockIdx.y * 128, bn = (long)blockIdx.x * 128;
    const int wm = (warp & 1) * 64, wn = (warp >> 1) * 32;
    const int r = lane >> 2, cl = lane & 3;

    float acc[4][4][4];
#pragma unroll
    for (int mt = 0; mt < 4; mt++)
#pragma unroll
        for (int nt = 0; nt < 4; nt++)
#pragma unroll
            for (int u = 0; u < 4; u++) acc[mt][nt][u] = 0.f;

    const int arow = tid >> 1;
    const int aq = tid & 1;
    const int bk = tid >> 5;
    const int bn4 = lane * 4;

    auto load_tile = [&](int s, int k0) {
        const float* gA = A + (bm + arow) * (long)K + k0;
        float* sA = sm + s * STAGEF + arow * ASTR;
#pragma unroll
        for (int p = 0; p < 4; p++) {
            int q = aq + p * 2;
            unsigned sa = (unsigned)__cvta_generic_to_shared(sA + q * 4);
            asm volatile("cp.async.cg.shared.global [%0], [%1], 16;\n"
                         :: "r"(sa), "l"(gA + q * 4));
        }
        float* sB = sm + s * STAGEF + ATILE;
#pragma unroll
        for (int p = 0; p < 4; p++) {
            int kr = bk + p * 8;
            const float* gB = B + (long)(k0 + kr) * N + bn + bn4;
            int nphys = bn4 ^ ((kr & 3) << 3);
            unsigned sb = (unsigned)__cvta_generic_to_shared(sB + kr * 128 + nphys);
            asm volatile("cp.async.cg.shared.global [%0], [%1], 16;\n"
                         :: "r"(sb), "l"(gB));
        }
    };

    // ldmatrix lane mapping for A fragment
    const int lrow = lane & 15;             // row within 16-row tile
    const int lkoff = (lane >> 4) << 2;     // 0 or 4 (k offset)

    const int nk = K >> 5;
    load_tile(0, 0);
    asm volatile("cp.async.commit_group;\n");
    load_tile(1, 32);
    asm volatile("cp.async.commit_group;\n");

    for (int it = 0; it < nk; it++) {
        const int s = it % 3;
        if (it + 2 < nk) {
            load_tile((it + 2) % 3, (it + 2) * 32);
            asm volatile("cp.async.commit_group;\n");
            asm volatile("cp.async.wait_group 2;\n");
        } else if (it + 1 < nk) {
            asm volatile("cp.async.wait_group 1;\n");
        } else {
            asm volatile("cp.async.wait_group 0;\n");
        }
        __syncthreads();

        const float* sA = sm + s * STAGEF;
        const float* sB = sm + s * STAGEF + ATILE;
        const unsigned abase = (unsigned)__cvta_generic_to_shared(
            sA + (wm + lrow) * ASTR + lkoff);
        // B frag base: addr = (k0+cl)*128 + wn + ((nt^cl)<<3) + r
        const float* bbase = sB + cl * 128 + wn + r;
#pragma unroll
        for (int kk = 0; kk < 4; kk++) {
            const int k0 = kk * 8;
            unsigned a[4][4], b[4][2];
#pragma unroll
            for (int mt = 0; mt < 4; mt++)
                ldsm_x4(a[mt], abase + (unsigned)((mt * 16 * ASTR + k0) * 4));
            const float* bk0 = bbase + k0 * 128;
#pragma unroll
            for (int nt = 0; nt < 4; nt++) {
                const float* bp = bk0 + ((nt ^ cl) << 3);
                b[nt][0] = __float_as_uint(bp[0]);
                b[nt][1] = __float_as_uint(bp[4 * 128]);
            }
#pragma unroll
            for (int mt = 0; mt < 4; mt++)
#pragma unroll
                for (int nt = 0; nt < 4; nt++) mma_tf32(acc[mt][nt], a[mt], b[nt]);
        }
        __syncthreads();
    }

    float* Cb = C + (bm + wm) * (long)N + bn + wn;
#pragma unroll
    for (int mt = 0; mt < 4; mt++) {
        const int row0 = mt * 16 + r;
#pragma unroll
        for (int nt = 0; nt < 4; nt++) {
            const int col = nt * 8 + 2 * cl;
            *(float2*)(Cb + (long)row0 * N + col) =
                make_float2(acc[mt][nt][0], acc[mt][nt][1]);
            *(float2*)(Cb + (long)(row0 + 8) * N + col) =
                make_float2(acc[mt][nt][2], acc[mt][nt][3]);
        }
    }
}

// ---------------- low-rank gate: tmp = h @ Wgk1  (K=1024, N=16) ------------
__global__ __launch_bounds__(256) void gemm16_kernel(
    const float* __restrict__ A, const float* __restrict__ W)
{
    int idx = blockIdx.x * 256 + threadIdx.x;
    int row = idx >> 4, col = idx & 15;
    const float* a = A + (long)row * HID;
    float acc = 0.f;
#pragma unroll 8
    for (int k = 0; k < HID; k++) acc += a[k] * W[k * 16 + col];
    g_t16[idx] = acc;
}

// ---------------- gk = log_sigmoid(tmp @ Wgk2 + b) / 16 --------------------
__global__ __launch_bounds__(256) void gk_kernel(
    const float* __restrict__ W2, const float* __restrict__ bias)
{
    int idx = blockIdx.x * 256 + threadIdx.x;
    int row = idx >> 10, c = idx & 1023;
    const float* t = g_t16 + row * 16;
    float acc = bias[c];
#pragma unroll
    for (int l = 0; l < 16; l++) acc += t[l] * W2[l * DK + c];
    float ax = fabsf(acc);
    float ls = fminf(acc, 0.f) - __logf(1.f + __expf(-ax));
    g_gk[idx] = ls * 0.0625f;
}

// ---------------- gate prep: qg/ki (tf32-rounded) + eb per (b,chunk,col) ---
__global__ __launch_bounds__(256) void gateprep_kernel()
{
    const int col = blockIdx.x * 256 + threadIdx.x;    // 0..DK-1
    const int bn = blockIdx.y;                          // b*NCHUNK + n
    const int b = bn / NCHUNK, n = bn % NCHUNK;
    const long base = ((long)(b * SEQL + n * CHUNK)) * DK + col;
    const float* gkp = g_gk + base;
    const float* qp = g_q + base;
    const float* kp = g_k + base;
    float* qgp = g_qg + base;
    float* kip = g_ki + base;
    const float scale = 0.0625f;

    float bsum = 0.f, ep = 1.f;
#pragma unroll 4
    for (int t = 0; t < CHUNK; t++) {
        bsum += gkp[(long)t * DK];
        ep = __expf(bsum);
        float en = __expf(-bsum);
        qgp[(long)t * DK] = f2tff(qp[(long)t * DK] * ep * scale);
        kip[(long)t * DK] = f2tff(kp[(long)t * DK] * en);
    }
    g_eb[(long)bn * DK + col] = ep;
}

// ================= GLA split: sequential state kernel ======================
#define QSTR 257
#define VSTR 65
#define STSTR 260
#define STATE_SMEM_FLOATS (64 * QSTR + 64 * STSTR + 64 * VSTR + 256)

__global__ __launch_bounds__(256) void gla_state_kernel()
{
    extern __shared__ float sm[];
    float* ki  = sm;                        // [64 t][QSTR]
    float* ST  = ki + 64 * QSTR;            // [64 v][STSTR]
    float* vtT = ST + 64 * STSTR;           // [64 v][VSTR]
    float* eb  = vtT + 64 * VSTR;           // [256]

    const int tid = threadIdx.x;
    const int warp = tid >> 5, lane = tid & 31;
    const int r = lane >> 2, cl = lane & 3, cl2 = 2 * (lane & 3);
    const int vs = blockIdx.x;
    const int bh = blockIdx.y;
    const int b = bh >> 2, hh = bh & 3;

    for (int i = tid; i < 64 * STSTR; i += 256) ST[i] = 0.f;
    __syncthreads();

    for (int n = 0; n < NCHUNK; n++) {
        {
            const long sbase = ((long)(bh * NCHUNK + n) * HDV + vs * 64) * HDK;
#pragma unroll
            for (int idx = tid; idx < 64 * 64; idx += 256) {
                int row = idx >> 6, c4 = idx & 63;
                const float* srow = ST + row * STSTR + c4 * 4;
                ((float4*)(g_S + sbase + (long)row * HDK))[c4] =
                    make_float4(srow[0], srow[1], srow[2], srow[3]);
            }
        }
        {
            eb[tid] = g_eb[((long)(b * NCHUNK + n)) * DK + hh * HDK + tid];
            const long rowbase = (long)(b * SEQL + n * CHUNK);
            const float4* ksrc = (const float4*)(g_ki + rowbase * DK + hh * HDK);
#pragma unroll
            for (int idx = tid; idx < 64 * 64; idx += 256) {
                int t = idx >> 6, c4 = idx & 63;
                float4 vk = ksrc[t * (DK / 4) + c4];
                float* kd = ki + t * QSTR + c4 * 4;
                kd[0] = vk.x; kd[1] = vk.y; kd[2] = vk.z; kd[3] = vk.w;
            }
            const long vbase = rowbase * DV + hh * HDV + vs * 64;
#pragma unroll
            for (int i = tid; i < 64 * 64; i += 256) {
                int t = i >> 6, vo = i & 63;
                vtT[vo * VSTR + t] = f2tff(g_v[vbase + (long)t * DV + vo]);
            }
        }
        __syncthreads();

        {
#pragma unroll
            for (int mt = 0; mt < 2; mt++) {
                const int m0 = warp * 32 + mt * 16;
                float cD[8][4];
#pragma unroll
                for (int ns = 0; ns < 8; ns++)
#pragma unroll
                    for (int u = 0; u < 4; u++) cD[ns][u] = 0.f;
#pragma unroll
                for (int k0 = 0; k0 < CHUNK; k0 += 8) {
                    unsigned a[4];
                    const float* ap = ki + (k0 + cl) * QSTR + m0 + r;
                    a[0] = __float_as_uint(ap[0]);
                    a[1] = __float_as_uint(ap[8]);
                    a[2] = __float_as_uint(ap[4 * QSTR]);
                    a[3] = __float_as_uint(ap[4 * QSTR + 8]);
#pragma unroll
                    for (int ns = 0; ns < 8; ns++) {
                        unsigned bb[2];
                        const float* bp = vtT + (ns * 8 + r) * VSTR + k0 + cl;
                        bb[0] = __float_as_uint(bp[0]);
                        bb[1] = __float_as_uint(bp[4]);
                        mma_tf32(cD[ns], a, bb);
                    }
                }
                const float e0 = eb[m0 + r];
                const float e1 = eb[m0 + r + 8];
#pragma unroll
                for (int ns = 0; ns < 8; ns++) {
                    const int col = ns * 8 + cl2;
                    float* s00 = ST + col * STSTR + m0 + r;
                    float* s01 = ST + (col + 1) * STSTR + m0 + r;
                    s00[0] = e0 * (s00[0] + cD[ns][0]);
                    s01[0] = e0 * (s01[0] + cD[ns][1]);
                    s00[8] = e1 * (s00[8] + cD[ns][2]);
                    s01[8] = e1 * (s01[8] + cD[ns][3]);
                }
            }
        }
        __syncthreads();
    }
}

// ================= GLA split: parallel output kernel ========================
#define OUT_SMEM_FLOATS (2 * 64 * QSTR + 64 * VSTR + 64 * STSTR + 64 * VSTR)

__global__ __launch_bounds__(256) void gla_out_kernel()
{
    extern __shared__ float sm[];
    float* qg  = sm;                        // [64 i][QSTR]
    float* ki  = qg + 64 * QSTR;            // [64 t][QSTR]
    float* sc  = ki + 64 * QSTR;            // [64 i][VSTR]
    float* ST  = sc + 64 * VSTR;            // [64 v][STSTR]
    float* vtT = ST + 64 * STSTR;           // [64 v][VSTR]

    const int tid = threadIdx.x;
    const int warp = tid >> 5, lane = tid & 31;
    const int r = lane >> 2, cl = lane & 3, cl2 = 2 * (lane & 3);
    const int n = blockIdx.x;
    const int bh = blockIdx.y;
    const int b = bh >> 2, hh = bh & 3;

    const int wm = (warp & 3) * 16;
    const int wn = (warp >> 2) * 32;

    const long rowbase = (long)(b * SEQL + n * CHUNK);

    {
        const float4* qsrc = (const float4*)(g_qg + rowbase * DK + hh * HDK);
        const float4* ksrc = (const float4*)(g_ki + rowbase * DK + hh * HDK);
#pragma unroll
        for (int idx = tid; idx < 64 * 64; idx += 256) {
            int t = idx >> 6, c4 = idx & 63;
            float4 vq = qsrc[t * (DK / 4) + c4];
            float* qd = qg + t * QSTR + c4 * 4;
            qd[0] = vq.x; qd[1] = vq.y; qd[2] = vq.z; qd[3] = vq.w;
            float4 vk = ksrc[t * (DK / 4) + c4];
            float* kd = ki + t * QSTR + c4 * 4;
            kd[0] = vk.x; kd[1] = vk.y; kd[2] = vk.z; kd[3] = vk.w;
        }
    }
    __syncthreads();

    {
        float c[4][4];
#pragma unroll
        for (int ns = 0; ns < 4; ns++)
#pragma unroll
            for (int u = 0; u < 4; u++) c[ns][u] = 0.f;
#pragma unroll 4
        for (int k0 = 0; k0 < HDK; k0 += 8) {
            unsigned a[4];
            const float* ap = qg + (wm + r) * QSTR + k0 + cl;
            a[0] = __float_as_uint(ap[0]);
            a[1] = __float_as_uint(ap[8 * QSTR]);
            a[2] = __float_as_uint(ap[4]);
            a[3] = __float_as_uint(ap[8 * QSTR + 4]);
#pragma unroll
            for (int ns = 0; ns < 4; ns++) {
                unsigned bb[2];
                const float* bp = ki + (wn + ns * 8 + r) * QSTR + k0 + cl;
                bb[0] = __float_as_uint(bp[0]);
                bb[1] = __float_as_uint(bp[4]);
                mma_tf32(c[ns], a, bb);
            }
        }
        const int row0 = wm + r, row1 = wm + r + 8;
#pragma unroll
        for (int ns = 0; ns < 4; ns++) {
            const int col = wn + ns * 8 + cl2;
            sc[row0 * VSTR + col]     = (col     <= row0) ? f2tff(c[ns][0]) : 0.f;
            sc[row0 * VSTR + col + 1] = (col + 1 <= row0) ? f2tff(c[ns][1]) : 0.f;
            sc[row1 * VSTR + col]     = (col     <= row1) ? f2tff(c[ns][2]) : 0.f;
            sc[row1 * VSTR + col + 1] = (col + 1 <= row1) ? f2tff(c[ns][3]) : 0.f;
        }
    }
    __syncthreads();

    for (int vs = 0; vs < HDV / 64; vs++) {
        {
            const long sbase = ((long)(bh * NCHUNK + n) * HDV + vs * 64) * HDK;
#pragma unroll
            for (int idx = tid; idx < 64 * 64; idx += 256) {
                int row = idx >> 6, c4 = idx & 63;
                float4 v4 = ((const float4*)(g_S + sbase + (long)row * HDK))[c4];
                float* sd = ST + row * STSTR + c4 * 4;
                sd[0] = v4.x; sd[1] = v4.y; sd[2] = v4.z; sd[3] = v4.w;
            }
            const long vbase = rowbase * DV + hh * HDV + vs * 64;
#pragma unroll
            for (int i = tid; i < 64 * 64; i += 256) {
                int t = i >> 6, vo = i & 63;
                vtT[vo * VSTR + t] = f2tff(g_v[vbase + (long)t * DV + vo]);
            }
        }
        __syncthreads();

        {
            float o[4][4];
#pragma unroll
            for (int ns = 0; ns < 4; ns++)
#pragma unroll
                for (int u = 0; u < 4; u++) o[ns][u] = 0.f;
#pragma unroll
            for (int k0 = 0; k0 < CHUNK; k0 += 8) {
                unsigned a[4];
                const float* ap = sc + (wm + r) * VSTR + k0 + cl;
                a[0] = __float_as_uint(ap[0]);
                a[1] = __float_as_uint(ap[8 * VSTR]);
                a[2] = __float_as_uint(ap[4]);
                a[3] = __float_as_uint(ap[8 * VSTR + 4]);
#pragma unroll
                for (int ns = 0; ns < 4; ns++) {
                    unsigned bb[2];
                    const float* bp = vtT + (wn + ns * 8 + r) * VSTR + k0 + cl;
                    bb[0] = __float_as_uint(bp[0]);
                    bb[1] = __float_as_uint(bp[4]);
                    mma_tf32(o[ns], a, bb);
                }
            }
#pragma unroll 4
            for (int k0 = 0; k0 < HDK; k0 += 8) {
                unsigned a[4];
                const float* ap = qg + (wm + r) * QSTR + k0 + cl;
                a[0] = __float_as_uint(ap[0]);
                a[1] = __float_as_uint(ap[8 * QSTR]);
                a[2] = __float_as_uint(ap[4]);
                a[3] = __float_as_uint(ap[8 * QSTR + 4]);
#pragma unroll
                for (int ns = 0; ns < 4; ns++) {
                    unsigned bb[2];
                    const float* bp = ST + (wn + ns * 8 + r) * STSTR + k0 + cl;
                    bb[0] = f2tf(bp[0]);
                    bb[1] = f2tf(bp[4]);
                    mma_tf32(o[ns], a, bb);
                }
            }
            const long ocol = hh * HDV + vs * 64;
            float* op = g_o + (rowbase + wm + r) * (long)DV + ocol + wn;
            float* op8 = op + 8 * DV;
#pragma unroll
            for (int ns = 0; ns < 4; ns++) {
                const int col = ns * 8 + cl2;
                *(float2*)(op + col)  = make_float2(o[ns][0], o[ns][1]);
                *(float2*)(op8 + col) = make_float2(o[ns][2], o[ns][3]);
            }
        }
        __syncthreads();
    }
}

// ---------------- RMS norm + swish gate (tf32-rounded output) --------------
__global__ __launch_bounds__(256) void normgate_kernel(const float* __restrict__ gnw)
{
    const int row = blockIdx.x;
    const int tid = threadIdx.x;
    const long base = (long)(row >> 2) * DV + (row & 3) * HDV;
    const float* op = g_o + base;
    const float* gp = g_gt + base;
    float* ogp = g_og + base;

    float vals[2];
    float ss = 0.f;
#pragma unroll
    for (int u = 0; u < 2; u++) {
        vals[u] = op[tid + 256 * u];
        ss += vals[u] * vals[u];
    }
    __shared__ float red[8];
#pragma unroll
    for (int o = 16; o > 0; o >>= 1) ss += __shfl_xor_sync(0xffffffffu, ss, o);
    if ((tid & 31) == 0) red[tid >> 5] = ss;
    __syncthreads();
    if (tid < 8) {
        float rr = red[tid];
#pragma unroll
        for (int o = 4; o > 0; o >>= 1) rr += __shfl_xor_sync(0xffu, rr, o);
        if (tid == 0) red[0] = rr;
    }
    __syncthreads();
    const float rinv = rsqrtf(red[0] * (1.f / 512.f) + 1e-5f);
#pragma unroll
    for (int u = 0; u < 2; u++) {
        int c = tid + 256 * u;
        float g = gp[c];
        float sig = 1.f / (1.f + __expf(-g));
        ogp[c] = f2tff(vals[u] * rinv * gnw[c] * (g * sig));
    }
}

// ---------------- launch ----------------------------------------------------
extern "C" void kernel_launch(void* const* d_in, const int* in_sizes, int n_in,
                              void* d_out, int out_size)
{
    (void)in_sizes; (void)n_in; (void)out_size;
    const float* h    = (const float*)d_in[0];
    const float* Wq   = (const float*)d_in[1];
    const float* Wk   = (const float*)d_in[2];
    const float* Wv   = (const float*)d_in[3];
    const float* Wg   = (const float*)d_in[4];
    const float* Wgk1 = (const float*)d_in[5];
    const float* Wgk2 = (const float*)d_in[6];
    const float* bgk2 = (const float*)d_in[7];
    const float* gnw  = (const float*)d_in[8];
    const float* Wo   = (const float*)d_in[9];
    float* out = (float*)d_out;

    void *pq, *pk, *pv, *pg, *pog, *pht, *pwq, *pwk, *pwv, *pwg, *pwo;
    cudaGetSymbolAddress(&pq, g_q);
    cudaGetSymbolAddress(&pk, g_k);
    cudaGetSymbolAddress(&pv, g_v);
    cudaGetSymbolAddress(&pg, g_gt);
    cudaGetSymbolAddress(&pog, g_og);
    cudaGetSymbolAddress(&pht, g_ht);
    cudaGetSymbolAddress(&pwq, g_wqt);
    cudaGetSymbolAddress(&pwk, g_wkt);
    cudaGetSymbolAddress(&pwv, g_wvt);
    cudaGetSymbolAddress(&pwg, g_wgt);
    cudaGetSymbolAddress(&pwo, g_wot);

    static_assert(STATE_SMEM_FLOATS * 4 <= 232448, "state smem too big");
    static_assert(OUT_SMEM_FLOATS * 4 <= 232448, "out smem too big");
    static_assert(GEMM_SMEM_BYTES * 2 <= 232448, "gemm smem too big");
    cudaFuncSetAttribute(gla_state_kernel, cudaFuncAttributeMaxDynamicSharedMemorySize,
                         STATE_SMEM_FLOATS * 4);
    cudaFuncSetAttribute(gla_out_kernel, cudaFuncAttributeMaxDynamicSharedMemorySize,
                         OUT_SMEM_FLOATS * 4);
    cudaFuncSetAttribute(gemm_tf32, cudaFuncAttributeMaxDynamicSharedMemorySize,
                         GEMM_SMEM_BYTES);

    dim3 t256(256);
    // tf32 pre-rounding passes
    trunc_kernel<<<(BL * HID / 4 + 255) / 256, t256>>>(h, (float*)pht, BL * HID / 4);
    trunc_kernel<<<(HID * DK / 4 + 255) / 256, t256>>>(Wq, (float*)pwq, HID * DK / 4);
    trunc_kernel<<<(HID * DK / 4 + 255) / 256, t256>>>(Wk, (float*)pwk, HID * DK / 4);
    trunc_kernel<<<(HID * DV / 4 + 255) / 256, t256>>>(Wv, (float*)pwv, HID * DV / 4);
    trunc_kernel<<<(HID * DV / 4 + 255) / 256, t256>>>(Wg, (float*)pwg, HID * DV / 4);
    trunc_kernel<<<(DV * HID / 4 + 255) / 256, t256>>>(Wo, (float*)pwo, DV * HID / 4);

    // projections (tf32 tensor cores)
    gemm_tf32<<<dim3(DK / 128, BL / 128), t256, GEMM_SMEM_BYTES>>>((const float*)pht, (const float*)pwq, (float*)pq, BL, DK, HID);
    gemm_tf32<<<dim3(DK / 128, BL / 128), t256, GEMM_SMEM_BYTES>>>((const float*)pht, (const float*)pwk, (float*)pk, BL, DK, HID);
    gemm_tf32<<<dim3(DV / 128, BL / 128), t256, GEMM_SMEM_BYTES>>>((const float*)pht, (const float*)pwv, (float*)pv, BL, DV, HID);
    gemm_tf32<<<dim3(DV / 128, BL / 128), t256, GEMM_SMEM_BYTES>>>((const float*)pht, (const float*)pwg, (float*)pg, BL, DV, HID);
    // low-rank gate path (fp32, uses original h)
    gemm16_kernel<<<(BL * 16) / 256, t256>>>(h, Wgk1);
    gk_kernel<<<(BL * DK) / 256, t256>>>(Wgk2, bgk2);
    // gate prep (qg/ki/eb)
    gateprep_kernel<<<dim3(DK / 256, BATCH * NCHUNK), t256>>>();
    // GLA: sequential state materialization, then parallel output
    gla_state_kernel<<<dim3(HDV / 64, BH), t256, STATE_SMEM_FLOATS * 4>>>();
    gla_out_kernel<<<dim3(NCHUNK, BH), t256, OUT_SMEM_FLOATS * 4>>>();
    // rms norm + swish gate
    normgate_kernel<<<BL * NH, t256>>>(gnw);
    // output projection
    gemm_tf32<<<dim3(HID / 128, BL / 128), t256, GEMM_SMEM_BYTES>>>((const float*)pog, (const float*)pwo, out, BL, HID, DV);
}

// round 10
// speedup vs baseline: 6.0266x; 1.3862x over previous
#include <cuda_runtime.h>
#include <cuda_fp16.h>
#include <math.h>
#include <stdint.h>

#define BATCH 4
#define SEQL 2048
#define HID 1024
#define NH 4
#define DK 1024
#define DV 2048
#define HDK 256
#define HDV 512
#define CHUNK 64
#define NCHUNK (SEQL / CHUNK)
#define BL (BATCH * SEQL) /* 8192 */
#define BH (BATCH * NH)   /* 16 */

// ---------------- scratch (static device allocations; no runtime alloc) ----
__device__ float g_q[BL * DK];
__device__ float g_k[BL * DK];
__device__ float g_v[BL * DV];
__device__ float g_gt[BL * DV];
__device__ float g_gk[BL * DK];
__device__ float g_t16[BL * 16];
__device__ float g_o[BL * DV];
// fp16 operands for tensor-core GEMMs
__device__ __half g_hh[BL * HID];          // h, fp16
__device__ __half g_ogh[BL * DV];          // normgate output, fp16
__device__ __half g_wqh[HID * DK];         // weights transposed [N][K], fp16
__device__ __half g_wkh[HID * DK];
__device__ __half g_wvh[HID * DV];
__device__ __half g_wgh[HID * DV];
__device__ __half g_woh[DV * HID];
// gate-prep outputs (fp32, tf32-rounded; consumed by GLA)
__device__ float g_qg[BL * DK];
__device__ float g_ki[BL * DK];
__device__ float g_eb[BATCH * NCHUNK * DK];
// materialized chunk-start states: [bh][n][v(512)][d(256)]
__device__ float g_S[(long)BH * NCHUNK * HDV * HDK];

// ================= helpers =================================================
__device__ __forceinline__ unsigned f2tf(float f) {
    unsigned r;
    asm("cvt.rna.tf32.f32 %0, %1;" : "=r"(r) : "f"(f));
    return r;
}
__device__ __forceinline__ float f2tff(float f) { return __uint_as_float(f2tf(f)); }

__device__ __forceinline__ void mma_tf32(float* c, const unsigned* a, const unsigned* b) {
    asm volatile(
        "mma.sync.aligned.m16n8k8.row.col.f32.tf32.tf32.f32 "
        "{%0,%1,%2,%3}, {%4,%5,%6,%7}, {%8,%9}, {%0,%1,%2,%3};"
        : "+f"(c[0]), "+f"(c[1]), "+f"(c[2]), "+f"(c[3])
        : "r"(a[0]), "r"(a[1]), "r"(a[2]), "r"(a[3]), "r"(b[0]), "r"(b[1]));
}

__device__ __forceinline__ void mma_f16(float* c, const unsigned* a, const unsigned* b) {
    asm volatile(
        "mma.sync.aligned.m16n8k16.row.col.f32.f16.f16.f32 "
        "{%0,%1,%2,%3}, {%4,%5,%6,%7}, {%8,%9}, {%0,%1,%2,%3};"
        : "+f"(c[0]), "+f"(c[1]), "+f"(c[2]), "+f"(c[3])
        : "r"(a[0]), "r"(a[1]), "r"(a[2]), "r"(a[3]), "r"(b[0]), "r"(b[1]));
}

__device__ __forceinline__ void ldsm_x4(unsigned* r, unsigned addr) {
    asm volatile("ldmatrix.sync.aligned.m8n8.x4.shared.b16 {%0,%1,%2,%3}, [%4];"
                 : "=r"(r[0]), "=r"(r[1]), "=r"(r[2]), "=r"(r[3]) : "r"(addr));
}
__device__ __forceinline__ void ldsm_x2(unsigned* r, unsigned addr) {
    asm volatile("ldmatrix.sync.aligned.m8n8.x2.shared.b16 {%0,%1}, [%2];"
                 : "=r"(r[0]), "=r"(r[1]) : "r"(addr));
}

// ---------------- fp16 conversion pass --------------------------------------
__global__ __launch_bounds__(256) void htrunc_kernel(
    const float* __restrict__ src, __half* __restrict__ dst, int n4)
{
    int i = blockIdx.x * 256 + threadIdx.x;
    if (i < n4) {
        float4 v = ((const float4*)src)[i];
        __half2 lo = __floats2half2_rn(v.x, v.y);
        __half2 hi = __floats2half2_rn(v.z, v.w);
        ((__half2*)dst)[i * 2] = lo;
        ((__half2*)dst)[i * 2 + 1] = hi;
    }
}

// ---------------- weight transpose + fp16: W[K][N] -> WT[N][K] --------------
__global__ __launch_bounds__(256) void ttrans_kernel(
    const float* __restrict__ W, __half* __restrict__ WT, int Kd, int Nd)
{
    __shared__ float t[32][33];
    const int bx = blockIdx.x * 32;   // n
    const int by = blockIdx.y * 32;   // k
    const int x = threadIdx.x & 31, y = threadIdx.x >> 5;  // 32 x 8
#pragma unroll
    for (int j = 0; j < 32; j += 8)
        t[y + j][x] = W[(long)(by + y + j) * Nd + bx + x];
    __syncthreads();
#pragma unroll
    for (int j = 0; j < 32; j += 8)
        WT[(long)(bx + y + j) * Kd + by + x] = __float2half_rn(t[x][y + j]);
}

// ================= FP16 tensor-core GEMM ===================================
// C[M,N] = A[M,K] @ BT[N,K]^T, fp16 in, fp32 accum/out.
// Block 128x128x32, 256 threads (8 warps 2Mx4N), warp 64x32, 3-stage cp.async.
#define KC 32
#define ASTRH 40                         /* halves per smem row (80 B) */
#define TILEH (128 * ASTRH)              /* 5120 halves = 10240 B */
#define STAGEH (2 * TILEH)
#define GEMMF16_SMEM_BYTES (3 * STAGEH * 2)

__global__ __launch_bounds__(256, 2) void gemm_f16(
    const __half* __restrict__ A, const __half* __restrict__ BT,
    float* __restrict__ C, int M, int N, int K)
{
    extern __shared__ __half smh[];
    const int tid = threadIdx.x;
    const int warp = tid >> 5, lane = tid & 31;
    const long bm = (long)blockIdx.y * 128, bn = (long)blockIdx.x * 128;
    const int wm = (warp & 1) * 64, wn = (warp >> 1) * 32;

    float acc[4][4][4];
#pragma unroll
    for (int mt = 0; mt < 4; mt++)
#pragma unroll
        for (int nt = 0; nt < 4; nt++)
#pragma unroll
            for (int u = 0; u < 4; u++) acc[mt][nt][u] = 0.f;

    auto load_tile = [&](int s, int kc) {
        const int k0 = kc * KC;
#pragma unroll
        for (int p = 0; p < 4; p++) {
            const int i = tid + p * 256;
            const int hsel = i >> 9;            // 0 = A, 1 = B
            const int idx = i & 511;
            const int row = idx >> 2, ch = idx & 3;
            const __half* src = hsel ? (BT + (bn + row) * (long)K + k0 + ch * 8)
                                     : (A + (bm + row) * (long)K + k0 + ch * 8);
            unsigned dst = (unsigned)__cvta_generic_to_shared(
                smh + s * STAGEH + hsel * TILEH + row * ASTRH + ch * 8);
            asm volatile("cp.async.cg.shared.global [%0], [%1], 16;\n"
                         :: "r"(dst), "l"(src));
        }
    };

    const int nk = K / KC;
    load_tile(0, 0);
    asm volatile("cp.async.commit_group;\n");
    load_tile(1, 1);
    asm volatile("cp.async.commit_group;\n");

    // ldmatrix lane addressing
    const int arow = (lane & 7) + ((lane >> 3) & 1) * 8;   // A row within 16
    const int akoff = (lane >> 4) * 8;                      // A k offset 0/8
    const int bnrow = lane & 7;                             // B n row within 8
    const int bkoff = ((lane >> 3) & 1) * 8;                // B k offset 0/8

    for (int it = 0; it < nk; it++) {
        const int s = it % 3;
        if (it + 2 < nk) {
            load_tile((it + 2) % 3, it + 2);
            asm volatile("cp.async.commit_group;\n");
            asm volatile("cp.async.wait_group 2;\n");
        } else if (it + 1 < nk) {
            asm volatile("cp.async.wait_group 1;\n");
        } else {
            asm volatile("cp.async.wait_group 0;\n");
        }
        __syncthreads();

        const __half* sA = smh + s * STAGEH;
        const __half* sB = smh + s * STAGEH + TILEH;
#pragma unroll
        for (int kk = 0; kk < 2; kk++) {
            const int k0 = kk * 16;
            unsigned a[4][4], b[4][2];
#pragma unroll
            for (int mt = 0; mt < 4; mt++) {
                unsigned ad = (unsigned)__cvta_generic_to_shared(
                    sA + (wm + mt * 16 + arow) * ASTRH + k0 + akoff);
                ldsm_x4(a[mt], ad);
            }
#pragma unroll
            for (int nt = 0; nt < 4; nt++) {
                unsigned bd = (unsigned)__cvta_generic_to_shared(
                    sB + (wn + nt * 8 + bnrow) * ASTRH + k0 + bkoff);
                ldsm_x2(b[nt], bd);   // NON-trans: BT is [n][k], k contiguous
            }
#pragma unroll
            for (int mt = 0; mt < 4; mt++)
#pragma unroll
                for (int nt = 0; nt < 4; nt++) mma_f16(acc[mt][nt], a[mt], b[nt]);
        }
        __syncthreads();
    }

    const int r = lane >> 2, cl = lane & 3;
    float* Cb = C + (bm + wm) * (long)N + bn + wn;
#pragma unroll
    for (int mt = 0; mt < 4; mt++) {
        const int row0 = mt * 16 + r;
#pragma unroll
        for (int nt = 0; nt < 4; nt++) {
            const int col = nt * 8 + 2 * cl;
            *(float2*)(Cb + (long)row0 * N + col) =
                make_float2(acc[mt][nt][0], acc[mt][nt][1]);
            *(float2*)(Cb + (long)(row0 + 8) * N + col) =
                make_float2(acc[mt][nt][2], acc[mt][nt][3]);
        }
    }
}

// ---------------- low-rank gate: tmp = h @ Wgk1  (K=1024, N=16) ------------
__global__ __launch_bounds__(256) void gemm16_kernel(
    const float* __restrict__ A, const float* __restrict__ W)
{
    int idx = blockIdx.x * 256 + threadIdx.x;
    int row = idx >> 4, col = idx & 15;
    const float* a = A + (long)row * HID;
    float acc = 0.f;
#pragma unroll 8
    for (int k = 0; k < HID; k++) acc += a[k] * W[k * 16 + col];
    g_t16[idx] = acc;
}

// ---------------- gk = log_sigmoid(tmp @ Wgk2 + b) / 16 --------------------
__global__ __launch_bounds__(256) void gk_kernel(
    const float* __restrict__ W2, const float* __restrict__ bias)
{
    int idx = blockIdx.x * 256 + threadIdx.x;
    int row = idx >> 10, c = idx & 1023;
    const float* t = g_t16 + row * 16;
    float acc = bias[c];
#pragma unroll
    for (int l = 0; l < 16; l++) acc += t[l] * W2[l * DK + c];
    float ax = fabsf(acc);
    float ls = fminf(acc, 0.f) - __logf(1.f + __expf(-ax));
    g_gk[idx] = ls * 0.0625f;
}

// ---------------- gate prep: qg/ki (tf32-rounded) + eb per (b,chunk,col) ---
__global__ __launch_bounds__(256) void gateprep_kernel()
{
    const int col = blockIdx.x * 256 + threadIdx.x;
    const int bn = blockIdx.y;
    const int b = bn / NCHUNK, n = bn % NCHUNK;
    const long base = ((long)(b * SEQL + n * CHUNK)) * DK + col;
    const float* gkp = g_gk + base;
    const float* qp = g_q + base;
    const float* kp = g_k + base;
    float* qgp = g_qg + base;
    float* kip = g_ki + base;
    const float scale = 0.0625f;

    float bsum = 0.f, ep = 1.f;
#pragma unroll 4
    for (int t = 0; t < CHUNK; t++) {
        bsum += gkp[(long)t * DK];
        ep = __expf(bsum);
        float en = __expf(-bsum);
        qgp[(long)t * DK] = f2tff(qp[(long)t * DK] * ep * scale);
        kip[(long)t * DK] = f2tff(kp[(long)t * DK] * en);
    }
    g_eb[(long)bn * DK + col] = ep;
}

// ================= GLA split: sequential state kernel ======================
#define QSTR 257
#define VSTR 65
#define STSTR 260
#define STATE_SMEM_FLOATS (64 * QSTR + 64 * STSTR + 64 * VSTR + 256)

__global__ __launch_bounds__(256) void gla_state_kernel()
{
    extern __shared__ float sm[];
    float* ki  = sm;
    float* ST  = ki + 64 * QSTR;
    float* vtT = ST + 64 * STSTR;
    float* eb  = vtT + 64 * VSTR;

    const int tid = threadIdx.x;
    const int warp = tid >> 5, lane = tid & 31;
    const int r = lane >> 2, cl = lane & 3, cl2 = 2 * (lane & 3);
    const int vs = blockIdx.x;
    const int bh = blockIdx.y;
    const int b = bh >> 2, hh = bh & 3;

    for (int i = tid; i < 64 * STSTR; i += 256) ST[i] = 0.f;
    __syncthreads();

    for (int n = 0; n < NCHUNK; n++) {
        {
            const long sbase = ((long)(bh * NCHUNK + n) * HDV + vs * 64) * HDK;
#pragma unroll
            for (int idx = tid; idx < 64 * 64; idx += 256) {
                int row = idx >> 6, c4 = idx & 63;
                const float* srow = ST + row * STSTR + c4 * 4;
                ((float4*)(g_S + sbase + (long)row * HDK))[c4] =
                    make_float4(srow[0], srow[1], srow[2], srow[3]);
            }
        }
        {
            eb[tid] = g_eb[((long)(b * NCHUNK + n)) * DK + hh * HDK + tid];
            const long rowbase = (long)(b * SEQL + n * CHUNK);
            const float4* ksrc = (const float4*)(g_ki + rowbase * DK + hh * HDK);
#pragma unroll
            for (int idx = tid; idx < 64 * 64; idx += 256) {
                int t = idx >> 6, c4 = idx & 63;
                float4 vk = ksrc[t * (DK / 4) + c4];
                float* kd = ki + t * QSTR + c4 * 4;
                kd[0] = vk.x; kd[1] = vk.y; kd[2] = vk.z; kd[3] = vk.w;
            }
            const long vbase = rowbase * DV + hh * HDV + vs * 64;
#pragma unroll
            for (int i = tid; i < 64 * 64; i += 256) {
                int t = i >> 6, vo = i & 63;
                vtT[vo * VSTR + t] = f2tff(g_v[vbase + (long)t * DV + vo]);
            }
        }
        __syncthreads();

        {
#pragma unroll
            for (int mt = 0; mt < 2; mt++) {
                const int m0 = warp * 32 + mt * 16;
                float cD[8][4];
#pragma unroll
                for (int ns = 0; ns < 8; ns++)
#pragma unroll
                    for (int u = 0; u < 4; u++) cD[ns][u] = 0.f;
#pragma unroll
                for (int k0 = 0; k0 < CHUNK; k0 += 8) {
                    unsigned a[4];
                    const float* ap = ki + (k0 + cl) * QSTR + m0 + r;
                    a[0] = __float_as_uint(ap[0]);
                    a[1] = __float_as_uint(ap[8]);
                    a[2] = __float_as_uint(ap[4 * QSTR]);
                    a[3] = __float_as_uint(ap[4 * QSTR + 8]);
#pragma unroll
                    for (int ns = 0; ns < 8; ns++) {
                        unsigned bb[2];
                        const float* bp = vtT + (ns * 8 + r) * VSTR + k0 + cl;
                        bb[0] = __float_as_uint(bp[0]);
                        bb[1] = __float_as_uint(bp[4]);
                        mma_tf32(cD[ns], a, bb);
                    }
                }
                const float e0 = eb[m0 + r];
                const float e1 = eb[m0 + r + 8];
#pragma unroll
                for (int ns = 0; ns < 8; ns++) {
                    const int col = ns * 8 + cl2;
                    float* s00 = ST + col * STSTR + m0 + r;
                    float* s01 = ST + (col + 1) * STSTR + m0 + r;
                    s00[0] = e0 * (s00[0] + cD[ns][0]);
                    s01[0] = e0 * (s01[0] + cD[ns][1]);
                    s00[8] = e1 * (s00[8] + cD[ns][2]);
                    s01[8] = e1 * (s01[8] + cD[ns][3]);
                }
            }
        }
        __syncthreads();
    }
}

// ================= GLA split: parallel output kernel ========================
#define OUT_SMEM_FLOATS (2 * 64 * QSTR + 64 * VSTR + 64 * STSTR + 64 * VSTR)

__global__ __launch_bounds__(256) void gla_out_kernel()
{
    extern __shared__ float sm[];
    float* qg  = sm;
    float* ki  = qg + 64 * QSTR;
    float* sc  = ki + 64 * QSTR;
    float* ST  = sc + 64 * VSTR;
    float* vtT = ST + 64 * STSTR;

    const int tid = threadIdx.x;
    const int warp = tid >> 5, lane = tid & 31;
    const int r = lane >> 2, cl = lane & 3, cl2 = 2 * (lane & 3);
    const int n = blockIdx.x;
    const int bh = blockIdx.y;
    const int b = bh >> 2, hh = bh & 3;

    const int wm = (warp & 3) * 16;
    const int wn = (warp >> 2) * 32;

    const long rowbase = (long)(b * SEQL + n * CHUNK);

    {
        const float4* qsrc = (const float4*)(g_qg + rowbase * DK + hh * HDK);
        const float4* ksrc = (const float4*)(g_ki + rowbase * DK + hh * HDK);
#pragma unroll
        for (int idx = tid; idx < 64 * 64; idx += 256) {
            int t = idx >> 6, c4 = idx & 63;
            float4 vq = qsrc[t * (DK / 4) + c4];
            float* qd = qg + t * QSTR + c4 * 4;
            qd[0] = vq.x; qd[1] = vq.y; qd[2] = vq.z; qd[3] = vq.w;
            float4 vk = ksrc[t * (DK / 4) + c4];
            float* kd = ki + t * QSTR + c4 * 4;
            kd[0] = vk.x; kd[1] = vk.y; kd[2] = vk.z; kd[3] = vk.w;
        }
    }
    __syncthreads();

    {
        float c[4][4];
#pragma unroll
        for (int ns = 0; ns < 4; ns++)
#pragma unroll
            for (int u = 0; u < 4; u++) c[ns][u] = 0.f;
#pragma unroll 4
        for (int k0 = 0; k0 < HDK; k0 += 8) {
            unsigned a[4];
            const float* ap = qg + (wm + r) * QSTR + k0 + cl;
            a[0] = __float_as_uint(ap[0]);
            a[1] = __float_as_uint(ap[8 * QSTR]);
            a[2] = __float_as_uint(ap[4]);
            a[3] = __float_as_uint(ap[8 * QSTR + 4]);
#pragma unroll
            for (int ns = 0; ns < 4; ns++) {
                unsigned bb[2];
                const float* bp = ki + (wn + ns * 8 + r) * QSTR + k0 + cl;
                bb[0] = __float_as_uint(bp[0]);
                bb[1] = __float_as_uint(bp[4]);
                mma_tf32(c[ns], a, bb);
            }
        }
        const int row0 = wm + r, row1 = wm + r + 8;
#pragma unroll
        for (int ns = 0; ns < 4; ns++) {
            const int col = wn + ns * 8 + cl2;
            sc[row0 * VSTR + col]     = (col     <= row0) ? f2tff(c[ns][0]) : 0.f;
            sc[row0 * VSTR + col + 1] = (col + 1 <= row0) ? f2tff(c[ns][1]) : 0.f;
            sc[row1 * VSTR + col]     = (col     <= row1) ? f2tff(c[ns][2]) : 0.f;
            sc[row1 * VSTR + col + 1] = (col + 1 <= row1) ? f2tff(c[ns][3]) : 0.f;
        }
    }
    __syncthreads();

    for (int vs = 0; vs < HDV / 64; vs++) {
        {
            const long sbase = ((long)(bh * NCHUNK + n) * HDV + vs * 64) * HDK;
#pragma unroll
            for (int idx = tid; idx < 64 * 64; idx += 256) {
                int row = idx >> 6, c4 = idx & 63;
                float4 v4 = ((const float4*)(g_S + sbase + (long)row * HDK))[c4];
                float* sd = ST + row * STSTR + c4 * 4;
                sd[0] = v4.x; sd[1] = v4.y; sd[2] = v4.z; sd[3] = v4.w;
            }
            const long vbase = rowbase * DV + hh * HDV + vs * 64;
#pragma unroll
            for (int i = tid; i < 64 * 64; i += 256) {
                int t = i >> 6, vo = i & 63;
                vtT[vo * VSTR + t] = f2tff(g_v[vbase + (long)t * DV + vo]);
            }
        }
        __syncthreads();

        {
            float o[4][4];
#pragma unroll
            for (int ns = 0; ns < 4; ns++)
#pragma unroll
                for (int u = 0; u < 4; u++) o[ns][u] = 0.f;
#pragma unroll
            for (int k0 = 0; k0 < CHUNK; k0 += 8) {
                unsigned a[4];
                const float* ap = sc + (wm + r) * VSTR + k0 + cl;
                a[0] = __float_as_uint(ap[0]);
                a[1] = __float_as_uint(ap[8 * VSTR]);
                a[2] = __float_as_uint(ap[4]);
                a[3] = __float_as_uint(ap[8 * VSTR + 4]);
#pragma unroll
                for (int ns = 0; ns < 4; ns++) {
                    unsigned bb[2];
                    const float* bp = vtT + (wn + ns * 8 + r) * VSTR + k0 + cl;
                    bb[0] = __float_as_uint(bp[0]);
                    bb[1] = __float_as_uint(bp[4]);
                    mma_tf32(o[ns], a, bb);
                }
            }
#pragma unroll 4
            for (int k0 = 0; k0 < HDK; k0 += 8) {
                unsigned a[4];
                const float* ap = qg + (wm + r) * QSTR + k0 + cl;
                a[0] = __float_as_uint(ap[0]);
                a[1] = __float_as_uint(ap[8 * QSTR]);
                a[2] = __float_as_uint(ap[4]);
                a[3] = __float_as_uint(ap[8 * QSTR + 4]);
#pragma unroll
                for (int ns = 0; ns < 4; ns++) {
                    unsigned bb[2];
                    const float* bp = ST + (wn + ns * 8 + r) * STSTR + k0 + cl;
                    bb[0] = f2tf(bp[0]);
                    bb[1] = f2tf(bp[4]);
                    mma_tf32(o[ns], a, bb);
                }
            }
            const long ocol = hh * HDV + vs * 64;
            float* op = g_o + (rowbase + wm + r) * (long)DV + ocol + wn;
            float* op8 = op + 8 * DV;
#pragma unroll
            for (int ns = 0; ns < 4; ns++) {
                const int col = ns * 8 + cl2;
                *(float2*)(op + col)  = make_float2(o[ns][0], o[ns][1]);
                *(float2*)(op8 + col) = make_float2(o[ns][2], o[ns][3]);
            }
        }
        __syncthreads();
    }
}

// ---------------- RMS norm + swish gate (fp16 output) ----------------------
__global__ __launch_bounds__(256) void normgate_kernel(const float* __restrict__ gnw)
{
    const int row = blockIdx.x;
    const int tid = threadIdx.x;
    const long base = (long)(row >> 2) * DV + (row & 3) * HDV;
    const float* op = g_o + base;
    const float* gp = g_gt + base;
    __half* ogp = g_ogh + base;

    float vals[2];
    float ss = 0.f;
#pragma unroll
    for (int u = 0; u < 2; u++) {
        vals[u] = op[tid + 256 * u];
        ss += vals[u] * vals[u];
    }
    __shared__ float red[8];
#pragma unroll
    for (int o = 16; o > 0; o >>= 1) ss += __shfl_xor_sync(0xffffffffu, ss, o);
    if ((tid & 31) == 0) red[tid >> 5] = ss;
    __syncthreads();
    if (tid < 8) {
        float rr = red[tid];
#pragma unroll
        for (int o = 4; o > 0; o >>= 1) rr += __shfl_xor_sync(0xffu, rr, o);
        if (tid == 0) red[0] = rr;
    }
    __syncthreads();
    const float rinv = rsqrtf(red[0] * (1.f / 512.f) + 1e-5f);
#pragma unroll
    for (int u = 0; u < 2; u++) {
        int c = tid + 256 * u;
        float g = gp[c];
        float sig = 1.f / (1.f + __expf(-g));
        ogp[c] = __float2half_rn(vals[u] * rinv * gnw[c] * (g * sig));
    }
}

// ---------------- launch ----------------------------------------------------
extern "C" void kernel_launch(void* const* d_in, const int* in_sizes, int n_in,
                              void* d_out, int out_size)
{
    (void)in_sizes; (void)n_in; (void)out_size;
    const float* h    = (const float*)d_in[0];
    const float* Wq   = (const float*)d_in[1];
    const float* Wk   = (const float*)d_in[2];
    const float* Wv   = (const float*)d_in[3];
    const float* Wg   = (const float*)d_in[4];
    const float* Wgk1 = (const float*)d_in[5];
    const float* Wgk2 = (const float*)d_in[6];
    const float* bgk2 = (const float*)d_in[7];
    const float* gnw  = (const float*)d_in[8];
    const float* Wo   = (const float*)d_in[9];
    float* out = (float*)d_out;

    void *pq, *pk, *pv, *pg, *pogh, *phh, *pwq, *pwk, *pwv, *pwg, *pwo;
    cudaGetSymbolAddress(&pq, g_q);
    cudaGetSymbolAddress(&pk, g_k);
    cudaGetSymbolAddress(&pv, g_v);
    cudaGetSymbolAddress(&pg, g_gt);
    cudaGetSymbolAddress(&pogh, g_ogh);
    cudaGetSymbolAddress(&phh, g_hh);
    cudaGetSymbolAddress(&pwq, g_wqh);
    cudaGetSymbolAddress(&pwk, g_wkh);
    cudaGetSymbolAddress(&pwv, g_wvh);
    cudaGetSymbolAddress(&pwg, g_wgh);
    cudaGetSymbolAddress(&pwo, g_woh);

    static_assert(STATE_SMEM_FLOATS * 4 <= 232448, "state smem too big");
    static_assert(OUT_SMEM_FLOATS * 4 <= 232448, "out smem too big");
    static_assert(GEMMF16_SMEM_BYTES * 2 <= 232448, "gemm smem too big");
    cudaFuncSetAttribute(gla_state_kernel, cudaFuncAttributeMaxDynamicSharedMemorySize,
                         STATE_SMEM_FLOATS * 4);
    cudaFuncSetAttribute(gla_out_kernel, cudaFuncAttributeMaxDynamicSharedMemorySize,
                         OUT_SMEM_FLOATS * 4);
    cudaFuncSetAttribute(gemm_f16, cudaFuncAttributeMaxDynamicSharedMemorySize,
                         GEMMF16_SMEM_BYTES);

    dim3 t256(256);
    // fp16 conversion passes (5 launches; 6th = first fp16 gemm for ncu)
    htrunc_kernel<<<(BL * HID / 4 + 255) / 256, t256>>>(h, (__half*)phh, BL * HID / 4);
    ttrans_kernel<<<dim3(DK / 32, HID / 32), t256>>>(Wq, (__half*)pwq, HID, DK);
    ttrans_kernel<<<dim3(DK / 32, HID / 32), t256>>>(Wk, (__half*)pwk, HID, DK);
    ttrans_kernel<<<dim3(DV / 32, HID / 32), t256>>>(Wv, (__half*)pwv, HID, DV);
    ttrans_kernel<<<dim3(DV / 32, HID / 32), t256>>>(Wg, (__half*)pwg, HID, DV);

    // projections (fp16 tensor cores, fp32 accum)
    gemm_f16<<<dim3(DK / 128, BL / 128), t256, GEMMF16_SMEM_BYTES>>>(
        (const __half*)phh, (const __half*)pwq, (float*)pq, BL, DK, HID);
    gemm_f16<<<dim3(DK / 128, BL / 128), t256, GEMMF16_SMEM_BYTES>>>(
        (const __half*)phh, (const __half*)pwk, (float*)pk, BL, DK, HID);
    gemm_f16<<<dim3(DV / 128, BL / 128), t256, GEMMF16_SMEM_BYTES>>>(
        (const __half*)phh, (const __half*)pwv, (float*)pv, BL, DV, HID);
    gemm_f16<<<dim3(DV / 128, BL / 128), t256, GEMMF16_SMEM_BYTES>>>(
        (const __half*)phh, (const __half*)pwg, (float*)pg, BL, DV, HID);
    // low-rank gate path (fp32, original h)
    gemm16_kernel<<<(BL * 16) / 256, t256>>>(h, Wgk1);
    gk_kernel<<<(BL * DK) / 256, t256>>>(Wgk2, bgk2);
    // gate prep
    gateprep_kernel<<<dim3(DK / 256, BATCH * NCHUNK), t256>>>();
    // GLA
    gla_state_kernel<<<dim3(HDV / 64, BH), t256, STATE_SMEM_FLOATS * 4>>>();
    gla_out_kernel<<<dim3(NCHUNK, BH), t256, OUT_SMEM_FLOATS * 4>>>();
    // rms norm + swish gate (fp16 out)
    normgate_kernel<<<BL * NH, t256>>>(gnw);
    // output projection
    ttrans_kernel<<<dim3(HID / 32, DV / 32), t256>>>(Wo, (__half*)pwo, DV, HID);
    gemm_f16<<<dim3(HID / 128, BL / 128), t256, GEMMF16_SMEM_BYTES>>>(
        (const __half*)pogh, (const __half*)pwo, out, BL, HID, DV);
}

// round 11
// speedup vs baseline: 7.5854x; 1.2586x over previous
#include <cuda_runtime.h>
#include <cuda_fp16.h>
#include <math.h>
#include <stdint.h>

#define BATCH 4
#define SEQL 2048
#define HID 1024
#define NH 4
#define DK 1024
#define DV 2048
#define HDK 256
#define HDV 512
#define CHUNK 64
#define NCHUNK (SEQL / CHUNK)
#define BL (BATCH * SEQL) /* 8192 */
#define BH (BATCH * NH)   /* 16 */

// ---------------- scratch (static device allocations; no runtime alloc) ----
__device__ float g_q[BL * DK];
__device__ float g_k[BL * DK];
__device__ float g_v[BL * DV];
__device__ float g_gt[BL * DV];
__device__ float g_gk[BL * DK];
__device__ float g_t16[BL * 16];
__device__ float g_o[BL * DV];
// fp16 operands
__device__ __half g_hh[BL * HID];
__device__ __half g_ogh[BL * DV];
__device__ __half g_wqh[HID * DK];
__device__ __half g_wkh[HID * DK];
__device__ __half g_wvh[HID * DV];
__device__ __half g_wgh[HID * DV];
__device__ __half g_woh[DV * HID];
// gate-prep outputs (fp16) + eb (fp32)
__device__ __half g_qgh[BL * DK];
__device__ __half g_kih[BL * DK];
__device__ float g_eb[BATCH * NCHUNK * DK];
// materialized chunk-start states: [bh][n][v(512)][d(256)] fp32
__device__ float g_S[(long)BH * NCHUNK * HDV * HDK];

// ================= helpers =================================================
__device__ __forceinline__ unsigned f2tf(float f) {
    unsigned r;
    asm("cvt.rna.tf32.f32 %0, %1;" : "=r"(r) : "f"(f));
    return r;
}
__device__ __forceinline__ float f2tff(float f) { return __uint_as_float(f2tf(f)); }

__device__ __forceinline__ void mma_tf32(float* c, const unsigned* a, const unsigned* b) {
    asm volatile(
        "mma.sync.aligned.m16n8k8.row.col.f32.tf32.tf32.f32 "
        "{%0,%1,%2,%3}, {%4,%5,%6,%7}, {%8,%9}, {%0,%1,%2,%3};"
        : "+f"(c[0]), "+f"(c[1]), "+f"(c[2]), "+f"(c[3])
        : "r"(a[0]), "r"(a[1]), "r"(a[2]), "r"(a[3]), "r"(b[0]), "r"(b[1]));
}

__device__ __forceinline__ void mma_f16(float* c, const unsigned* a, const unsigned* b) {
    asm volatile(
        "mma.sync.aligned.m16n8k16.row.col.f32.f16.f16.f32 "
        "{%0,%1,%2,%3}, {%4,%5,%6,%7}, {%8,%9}, {%0,%1,%2,%3};"
        : "+f"(c[0]), "+f"(c[1]), "+f"(c[2]), "+f"(c[3])
        : "r"(a[0]), "r"(a[1]), "r"(a[2]), "r"(a[3]), "r"(b[0]), "r"(b[1]));
}

__device__ __forceinline__ void ldsm_x4(unsigned* r, unsigned addr) {
    asm volatile("ldmatrix.sync.aligned.m8n8.x4.shared.b16 {%0,%1,%2,%3}, [%4];"
                 : "=r"(r[0]), "=r"(r[1]), "=r"(r[2]), "=r"(r[3]) : "r"(addr));
}
__device__ __forceinline__ void ldsm_x2(unsigned* r, unsigned addr) {
    asm volatile("ldmatrix.sync.aligned.m8n8.x2.shared.b16 {%0,%1}, [%2];"
                 : "=r"(r[0]), "=r"(r[1]) : "r"(addr));
}

// ---------------- fp16 conversion pass --------------------------------------
__global__ __launch_bounds__(256) void htrunc_kernel(
    const float* __restrict__ src, __half* __restrict__ dst, int n4)
{
    int i = blockIdx.x * 256 + threadIdx.x;
    if (i < n4) {
        float4 v = ((const float4*)src)[i];
        ((__half2*)dst)[i * 2] = __floats2half2_rn(v.x, v.y);
        ((__half2*)dst)[i * 2 + 1] = __floats2half2_rn(v.z, v.w);
    }
}

// ---------------- weight transpose + fp16: W[K][N] -> WT[N][K] --------------
__global__ __launch_bounds__(256) void ttrans_kernel(
    const float* __restrict__ W, __half* __restrict__ WT, int Kd, int Nd)
{
    __shared__ float t[32][33];
    const int bx = blockIdx.x * 32;
    const int by = blockIdx.y * 32;
    const int x = threadIdx.x & 31, y = threadIdx.x >> 5;
#pragma unroll
    for (int j = 0; j < 32; j += 8)
        t[y + j][x] = W[(long)(by + y + j) * Nd + bx + x];
    __syncthreads();
#pragma unroll
    for (int j = 0; j < 32; j += 8)
        WT[(long)(bx + y + j) * Kd + by + x] = __float2half_rn(t[x][y + j]);
}

// ================= FP16 tensor-core GEMM ===================================
// C[M,N] = A[M,K] @ BT[N,K]^T, fp16 in, fp32 accum/out.
// Block 128x128x64, 256 threads (8 warps 2Mx4N), warp 64x32, 3-stage cp.async.
#define KC 64
#define ASTRH 72                         /* halves per smem row (144 B) */
#define TILEH (128 * ASTRH)
#define STAGEH (2 * TILEH)
#define GEMMF16_SMEM_BYTES (3 * STAGEH * 2)

__global__ __launch_bounds__(256, 2) void gemm_f16(
    const __half* __restrict__ A, const __half* __restrict__ BT,
    float* __restrict__ C, int M, int N, int K)
{
    extern __shared__ __half smh[];
    const int tid = threadIdx.x;
    const int warp = tid >> 5, lane = tid & 31;
    const long bm = (long)blockIdx.y * 128, bn = (long)blockIdx.x * 128;
    const int wm = (warp & 1) * 64, wn = (warp >> 1) * 32;

    float acc[4][4][4];
#pragma unroll
    for (int mt = 0; mt < 4; mt++)
#pragma unroll
        for (int nt = 0; nt < 4; nt++)
#pragma unroll
            for (int u = 0; u < 4; u++) acc[mt][nt][u] = 0.f;

    auto load_tile = [&](int s, int kc) {
        const int k0 = kc * KC;
#pragma unroll
        for (int p = 0; p < 8; p++) {
            const int i = tid + p * 256;
            const int hsel = i >> 10;           // 0 = A, 1 = B
            const int idx = i & 1023;
            const int row = idx >> 3, ch = idx & 7;
            const __half* src = hsel ? (BT + (bn + row) * (long)K + k0 + ch * 8)
                                     : (A + (bm + row) * (long)K + k0 + ch * 8);
            unsigned dst = (unsigned)__cvta_generic_to_shared(
                smh + s * STAGEH + hsel * TILEH + row * ASTRH + ch * 8);
            asm volatile("cp.async.cg.shared.global [%0], [%1], 16;\n"
                         :: "r"(dst), "l"(src));
        }
    };

    const int nk = K / KC;
    load_tile(0, 0);
    asm volatile("cp.async.commit_group;\n");
    load_tile(1, 1);
    asm volatile("cp.async.commit_group;\n");

    const int arow = (lane & 7) + ((lane >> 3) & 1) * 8;
    const int akoff = (lane >> 4) * 8;
    const int bnrow = lane & 7;
    const int bkoff = ((lane >> 3) & 1) * 8;

    for (int it = 0; it < nk; it++) {
        const int s = it % 3;
        if (it + 2 < nk) {
            load_tile((it + 2) % 3, it + 2);
            asm volatile("cp.async.commit_group;\n");
            asm volatile("cp.async.wait_group 2;\n");
        } else if (it + 1 < nk) {
            asm volatile("cp.async.wait_group 1;\n");
        } else {
            asm volatile("cp.async.wait_group 0;\n");
        }
        __syncthreads();

        const __half* sA = smh + s * STAGEH;
        const __half* sB = smh + s * STAGEH + TILEH;
#pragma unroll
        for (int kk = 0; kk < 4; kk++) {
            const int k0 = kk * 16;
            unsigned a[4][4], b[4][2];
#pragma unroll
            for (int mt = 0; mt < 4; mt++) {
                unsigned ad = (unsigned)__cvta_generic_to_shared(
                    sA + (wm + mt * 16 + arow) * ASTRH + k0 + akoff);
                ldsm_x4(a[mt], ad);
            }
#pragma unroll
            for (int nt = 0; nt < 4; nt++) {
                unsigned bd = (unsigned)__cvta_generic_to_shared(
                    sB + (wn + nt * 8 + bnrow) * ASTRH + k0 + bkoff);
                ldsm_x2(b[nt], bd);
            }
#pragma unroll
            for (int mt = 0; mt < 4; mt++)
#pragma unroll
                for (int nt = 0; nt < 4; nt++) mma_f16(acc[mt][nt], a[mt], b[nt]);
        }
        __syncthreads();
    }

    const int r = lane >> 2, cl = lane & 3;
    float* Cb = C + (bm + wm) * (long)N + bn + wn;
#pragma unroll
    for (int mt = 0; mt < 4; mt++) {
        const int row0 = mt * 16 + r;
#pragma unroll
        for (int nt = 0; nt < 4; nt++) {
            const int col = nt * 8 + 2 * cl;
            *(float2*)(Cb + (long)row0 * N + col) =
                make_float2(acc[mt][nt][0], acc[mt][nt][1]);
            *(float2*)(Cb + (long)(row0 + 8) * N + col) =
                make_float2(acc[mt][nt][2], acc[mt][nt][3]);
        }
    }
}

// ---------------- low-rank gate: tmp = h @ Wgk1 -----------------------------
__global__ __launch_bounds__(256) void gemm16_kernel(
    const float* __restrict__ A, const float* __restrict__ W)
{
    int idx = blockIdx.x * 256 + threadIdx.x;
    int row = idx >> 4, col = idx & 15;
    const float* a = A + (long)row * HID;
    float acc = 0.f;
#pragma unroll 8
    for (int k = 0; k < HID; k++) acc += a[k] * W[k * 16 + col];
    g_t16[idx] = acc;
}

// ---------------- gk = log_sigmoid(tmp @ Wgk2 + b) / 16 --------------------
__global__ __launch_bounds__(256) void gk_kernel(
    const float* __restrict__ W2, const float* __restrict__ bias)
{
    int idx = blockIdx.x * 256 + threadIdx.x;
    int row = idx >> 10, c = idx & 1023;
    const float* t = g_t16 + row * 16;
    float acc = bias[c];
#pragma unroll
    for (int l = 0; l < 16; l++) acc += t[l] * W2[l * DK + c];
    float ax = fabsf(acc);
    float ls = fminf(acc, 0.f) - __logf(1.f + __expf(-ax));
    g_gk[idx] = ls * 0.0625f;
}

// ---------------- gate prep: qg/ki (fp16) + eb per (b,chunk,col) -----------
__global__ __launch_bounds__(256) void gateprep_kernel()
{
    const int col = blockIdx.x * 256 + threadIdx.x;
    const int bn = blockIdx.y;
    const int b = bn / NCHUNK, n = bn % NCHUNK;
    const long base = ((long)(b * SEQL + n * CHUNK)) * DK + col;
    const float* gkp = g_gk + base;
    const float* qp = g_q + base;
    const float* kp = g_k + base;
    __half* qgp = g_qgh + base;
    __half* kip = g_kih + base;
    const float scale = 0.0625f;

    float bsum = 0.f, ep = 1.f;
#pragma unroll 4
    for (int t = 0; t < CHUNK; t++) {
        bsum += gkp[(long)t * DK];
        ep = __expf(bsum);
        float en = __expf(-bsum);
        qgp[(long)t * DK] = __float2half_rn(qp[(long)t * DK] * ep * scale);
        kip[(long)t * DK] = __float2half_rn(kp[(long)t * DK] * en);
    }
    g_eb[(long)bn * DK + col] = ep;
}

// ================= GLA split: sequential state kernel (tf32) ================
#define QSTR 257
#define VSTR 65
#define STSTR 260
#define STATE_SMEM_FLOATS (64 * QSTR + 64 * STSTR + 64 * VSTR + 256)

__global__ __launch_bounds__(256) void gla_state_kernel()
{
    extern __shared__ float sm[];
    float* ki  = sm;
    float* ST  = ki + 64 * QSTR;
    float* vtT = ST + 64 * STSTR;
    float* eb  = vtT + 64 * VSTR;

    const int tid = threadIdx.x;
    const int warp = tid >> 5, lane = tid & 31;
    const int r = lane >> 2, cl = lane & 3, cl2 = 2 * (lane & 3);
    const int vs = blockIdx.x;
    const int bh = blockIdx.y;
    const int b = bh >> 2, hh = bh & 3;

    for (int i = tid; i < 64 * STSTR; i += 256) ST[i] = 0.f;
    __syncthreads();

    for (int n = 0; n < NCHUNK; n++) {
        {
            const long sbase = ((long)(bh * NCHUNK + n) * HDV + vs * 64) * HDK;
#pragma unroll
            for (int idx = tid; idx < 64 * 64; idx += 256) {
                int row = idx >> 6, c4 = idx & 63;
                const float* srow = ST + row * STSTR + c4 * 4;
                ((float4*)(g_S + sbase + (long)row * HDK))[c4] =
                    make_float4(srow[0], srow[1], srow[2], srow[3]);
            }
        }
        {
            eb[tid] = g_eb[((long)(b * NCHUNK + n)) * DK + hh * HDK + tid];
            const long rowbase = (long)(b * SEQL + n * CHUNK);
            // ki: fp16 gmem -> fp32 smem (exact)
#pragma unroll
            for (int idx = tid; idx < 64 * 32; idx += 256) {
                int t = idx >> 5, c8 = idx & 31;
                const __half2* src = (const __half2*)(g_kih + (rowbase + t) * DK + hh * HDK + c8 * 8);
                float* kd = ki + t * QSTR + c8 * 8;
#pragma unroll
                for (int j = 0; j < 4; j++) {
                    float2 f = __half22float2(src[j]);
                    kd[j * 2] = f.x;
                    kd[j * 2 + 1] = f.y;
                }
            }
            const long vbase = rowbase * DV + hh * HDV + vs * 64;
#pragma unroll
            for (int i = tid; i < 64 * 64; i += 256) {
                int t = i >> 6, vo = i & 63;
                vtT[vo * VSTR + t] = f2tff(g_v[vbase + (long)t * DV + vo]);
            }
        }
        __syncthreads();

        {
#pragma unroll
            for (int mt = 0; mt < 2; mt++) {
                const int m0 = warp * 32 + mt * 16;
                float cD[8][4];
#pragma unroll
                for (int ns = 0; ns < 8; ns++)
#pragma unroll
                    for (int u = 0; u < 4; u++) cD[ns][u] = 0.f;
#pragma unroll
                for (int k0 = 0; k0 < CHUNK; k0 += 8) {
                    unsigned a[4];
                    const float* ap = ki + (k0 + cl) * QSTR + m0 + r;
                    a[0] = __float_as_uint(ap[0]);
                    a[1] = __float_as_uint(ap[8]);
                    a[2] = __float_as_uint(ap[4 * QSTR]);
                    a[3] = __float_as_uint(ap[4 * QSTR + 8]);
#pragma unroll
                    for (int ns = 0; ns < 8; ns++) {
                        unsigned bb[2];
                        const float* bp = vtT + (ns * 8 + r) * VSTR + k0 + cl;
                        bb[0] = __float_as_uint(bp[0]);
                        bb[1] = __float_as_uint(bp[4]);
                        mma_tf32(cD[ns], a, bb);
                    }
                }
                const float e0 = eb[m0 + r];
                const float e1 = eb[m0 + r + 8];
#pragma unroll
                for (int ns = 0; ns < 8; ns++) {
                    const int col = ns * 8 + cl2;
                    float* s00 = ST + col * STSTR + m0 + r;
                    float* s01 = ST + (col + 1) * STSTR + m0 + r;
                    s00[0] = e0 * (s00[0] + cD[ns][0]);
                    s01[0] = e0 * (s01[0] + cD[ns][1]);
                    s00[8] = e1 * (s00[8] + cD[ns][2]);
                    s01[8] = e1 * (s01[8] + cD[ns][3]);
                }
            }
        }
        __syncthreads();
    }
}

// ================= GLA split: parallel output kernel (fp16) =================
// smem (halves): qgh[64][OQ], kist[64][OQ] (ki then S), sch[64][OV], vtTh[64][OV]
#define OQ 264
#define OV 72
#define OUT_SMEM_HALVES (2 * 64 * OQ + 2 * 64 * OV)

__global__ __launch_bounds__(256, 2) void gla_out_kernel()
{
    extern __shared__ __half smo[];
    __half* qgh  = smo;
    __half* kist = qgh + 64 * OQ;
    __half* sch  = kist + 64 * OQ;
    __half* vtTh = sch + 64 * OV;

    const int tid = threadIdx.x;
    const int warp = tid >> 5, lane = tid & 31;
    const int r = lane >> 2, cl = lane & 3;
    const int n = blockIdx.x;
    const int bh = blockIdx.y;
    const int b = bh >> 2, hh = bh & 3;

    const int wm = (warp & 3) * 16;
    const int wn = (warp >> 2) * 32;

    const int arow = (lane & 7) + ((lane >> 3) & 1) * 8;
    const int akoff = (lane >> 4) * 8;
    const int bnrow = lane & 7;
    const int bkoff = ((lane >> 3) & 1) * 8;

    const long rowbase = (long)(b * SEQL + n * CHUNK);

    // ---- load qg/ki tiles (fp16, vectorized) --------------------------------
    {
#pragma unroll
        for (int idx = tid; idx < 64 * 32; idx += 256) {
            int t = idx >> 5, c8 = idx & 31;
            *(uint4*)(qgh + t * OQ + c8 * 8) =
                *(const uint4*)(g_qgh + (rowbase + t) * DK + hh * HDK + c8 * 8);
            *(uint4*)(kist + t * OQ + c8 * 8) =
                *(const uint4*)(g_kih + (rowbase + t) * DK + hh * HDK + c8 * 8);
        }
    }
    __syncthreads();

    // ---- scores = mask(qg @ ki^T), fp16 -------------------------------------
    {
        float c[4][4];
#pragma unroll
        for (int nt = 0; nt < 4; nt++)
#pragma unroll
            for (int u = 0; u < 4; u++) c[nt][u] = 0.f;
#pragma unroll
        for (int k0 = 0; k0 < HDK; k0 += 16) {
            unsigned a[4];
            ldsm_x4(a, (unsigned)__cvta_generic_to_shared(
                qgh + (wm + arow) * OQ + k0 + akoff));
#pragma unroll
            for (int nt = 0; nt < 4; nt++) {
                unsigned bb[2];
                ldsm_x2(bb, (unsigned)__cvta_generic_to_shared(
                    kist + (wn + nt * 8 + bnrow) * OQ + k0 + bkoff));
                mma_f16(c[nt], a, bb);
            }
        }
        const int row0 = wm + r, row1 = wm + r + 8;
#pragma unroll
        for (int nt = 0; nt < 4; nt++) {
            const int col = wn + nt * 8 + 2 * cl;
            sch[row0 * OV + col]     = (col     <= row0) ? __float2half_rn(c[nt][0]) : __half(0.f);
            sch[row0 * OV + col + 1] = (col + 1 <= row0) ? __float2half_rn(c[nt][1]) : __half(0.f);
            sch[row1 * OV + col]     = (col     <= row1) ? __float2half_rn(c[nt][2]) : __half(0.f);
            sch[row1 * OV + col + 1] = (col + 1 <= row1) ? __float2half_rn(c[nt][3]) : __half(0.f);
        }
    }
    __syncthreads();

    // ---- per v-slice: o = sc @ v + qg @ S_n ---------------------------------
    for (int vs = 0; vs < HDV / 64; vs++) {
        {
            const long sbase = ((long)(bh * NCHUNK + n) * HDV + vs * 64) * HDK;
#pragma unroll
            for (int idx = tid; idx < 64 * 64; idx += 256) {
                int row = idx >> 6, c4 = idx & 63;
                float4 v4 = ((const float4*)(g_S + sbase + (long)row * HDK))[c4];
                __half* dst = kist + row * OQ + c4 * 4;
                *(__half2*)dst       = __floats2half2_rn(v4.x, v4.y);
                *(__half2*)(dst + 2) = __floats2half2_rn(v4.z, v4.w);
            }
            const long vbase = rowbase * DV + hh * HDV + vs * 64;
#pragma unroll
            for (int i = tid; i < 64 * 64; i += 256) {
                int t = i >> 6, vo = i & 63;
                vtTh[vo * OV + t] = __float2half_rn(g_v[vbase + (long)t * DV + vo]);
            }
        }
        __syncthreads();

        {
            float o[4][4];
#pragma unroll
            for (int nt = 0; nt < 4; nt++)
#pragma unroll
                for (int u = 0; u < 4; u++) o[nt][u] = 0.f;
            // sc @ v (K = 64)
#pragma unroll
            for (int k0 = 0; k0 < CHUNK; k0 += 16) {
                unsigned a[4];
                ldsm_x4(a, (unsigned)__cvta_generic_to_shared(
                    sch + (wm + arow) * OV + k0 + akoff));
#pragma unroll
                for (int nt = 0; nt < 4; nt++) {
                    unsigned bb[2];
                    ldsm_x2(bb, (unsigned)__cvta_generic_to_shared(
                        vtTh + (wn + nt * 8 + bnrow) * OV + k0 + bkoff));
                    mma_f16(o[nt], a, bb);
                }
            }
            // qg @ S (K = 256)
#pragma unroll
            for (int k0 = 0; k0 < HDK; k0 += 16) {
                unsigned a[4];
                ldsm_x4(a, (unsigned)__cvta_generic_to_shared(
                    qgh + (wm + arow) * OQ + k0 + akoff));
#pragma unroll
                for (int nt = 0; nt < 4; nt++) {
                    unsigned bb[2];
                    ldsm_x2(bb, (unsigned)__cvta_generic_to_shared(
                        kist + (wn + nt * 8 + bnrow) * OQ + k0 + bkoff));
                    mma_f16(o[nt], a, bb);
                }
            }
            const long ocol = hh * HDV + vs * 64;
            float* op = g_o + (rowbase + wm + r) * (long)DV + ocol + wn;
            float* op8 = op + 8 * DV;
#pragma unroll
            for (int nt = 0; nt < 4; nt++) {
                const int col = nt * 8 + 2 * cl;
                *(float2*)(op + col)  = make_float2(o[nt][0], o[nt][1]);
                *(float2*)(op8 + col) = make_float2(o[nt][2], o[nt][3]);
            }
        }
        __syncthreads();
    }
}

// ---------------- RMS norm + swish gate (fp16 output) ----------------------
__global__ __launch_bounds__(256) void normgate_kernel(const float* __restrict__ gnw)
{
    const int row = blockIdx.x;
    const int tid = threadIdx.x;
    const long base = (long)(row >> 2) * DV + (row & 3) * HDV;
    const float* op = g_o + base;
    const float* gp = g_gt + base;
    __half* ogp = g_ogh + base;

    float vals[2];
    float ss = 0.f;
#pragma unroll
    for (int u = 0; u < 2; u++) {
        vals[u] = op[tid + 256 * u];
        ss += vals[u] * vals[u];
    }
    __shared__ float red[8];
#pragma unroll
    for (int o = 16; o > 0; o >>= 1) ss += __shfl_xor_sync(0xffffffffu, ss, o);
    if ((tid & 31) == 0) red[tid >> 5] = ss;
    __syncthreads();
    if (tid < 8) {
        float rr = red[tid];
#pragma unroll
        for (int o = 4; o > 0; o >>= 1) rr += __shfl_xor_sync(0xffu, rr, o);
        if (tid == 0) red[0] = rr;
    }
    __syncthreads();
    const float rinv = rsqrtf(red[0] * (1.f / 512.f) + 1e-5f);
#pragma unroll
    for (int u = 0; u < 2; u++) {
        int c = tid + 256 * u;
        float g = gp[c];
        float sig = 1.f / (1.f + __expf(-g));
        ogp[c] = __float2half_rn(vals[u] * rinv * gnw[c] * (g * sig));
    }
}

// ---------------- launch ----------------------------------------------------
extern "C" void kernel_launch(void* const* d_in, const int* in_sizes, int n_in,
                              void* d_out, int out_size)
{
    (void)in_sizes; (void)n_in; (void)out_size;
    const float* h    = (const float*)d_in[0];
    const float* Wq   = (const float*)d_in[1];
    const float* Wk   = (const float*)d_in[2];
    const float* Wv   = (const float*)d_in[3];
    const float* Wg   = (const float*)d_in[4];
    const float* Wgk1 = (const float*)d_in[5];
    const float* Wgk2 = (const float*)d_in[6];
    const float* bgk2 = (const float*)d_in[7];
    const float* gnw  = (const float*)d_in[8];
    const float* Wo   = (const float*)d_in[9];
    float* out = (float*)d_out;

    void *pq, *pk, *pv, *pg, *pogh, *phh, *pwq, *pwk, *pwv, *pwg, *pwo;
    cudaGetSymbolAddress(&pq, g_q);
    cudaGetSymbolAddress(&pk, g_k);
    cudaGetSymbolAddress(&pv, g_v);
    cudaGetSymbolAddress(&pg, g_gt);
    cudaGetSymbolAddress(&pogh, g_ogh);
    cudaGetSymbolAddress(&phh, g_hh);
    cudaGetSymbolAddress(&pwq, g_wqh);
    cudaGetSymbolAddress(&pwk, g_wkh);
    cudaGetSymbolAddress(&pwv, g_wvh);
    cudaGetSymbolAddress(&pwg, g_wgh);
    cudaGetSymbolAddress(&pwo, g_woh);

    static_assert(STATE_SMEM_FLOATS * 4 <= 232448, "state smem too big");
    static_assert(OUT_SMEM_HALVES * 2 * 2 <= 232448, "out smem too big");
    static_assert(GEMMF16_SMEM_BYTES * 2 <= 232448, "gemm smem too big");
    cudaFuncSetAttribute(gla_state_kernel, cudaFuncAttributeMaxDynamicSharedMemorySize,
                         STATE_SMEM_FLOATS * 4);
    cudaFuncSetAttribute(gla_out_kernel, cudaFuncAttributeMaxDynamicSharedMemorySize,
                         OUT_SMEM_HALVES * 2);
    cudaFuncSetAttribute(gemm_f16, cudaFuncAttributeMaxDynamicSharedMemorySize,
                         GEMMF16_SMEM_BYTES);

    dim3 t256(256);
    // conversion passes (5 launches; 6th = first fp16 gemm for ncu)
    htrunc_kernel<<<(BL * HID / 4 + 255) / 256, t256>>>(h, (__half*)phh, BL * HID / 4);
    ttrans_kernel<<<dim3(DK / 32, HID / 32), t256>>>(Wq, (__half*)pwq, HID, DK);
    ttrans_kernel<<<dim3(DK / 32, HID / 32), t256>>>(Wk, (__half*)pwk, HID, DK);
    ttrans_kernel<<<dim3(DV / 32, HID / 32), t256>>>(Wv, (__half*)pwv, HID, DV);
    ttrans_kernel<<<dim3(DV / 32, HID / 32), t256>>>(Wg, (__half*)pwg, HID, DV);

    // projections (fp16 tensor cores, fp32 accum)
    gemm_f16<<<dim3(DK / 128, BL / 128), t256, GEMMF16_SMEM_BYTES>>>(
        (const __half*)phh, (const __half*)pwq, (float*)pq, BL, DK, HID);
    gemm_f16<<<dim3(DK / 128, BL / 128), t256, GEMMF16_SMEM_BYTES>>>(
        (const __half*)phh, (const __half*)pwk, (float*)pk, BL, DK, HID);
    gemm_f16<<<dim3(DV / 128, BL / 128), t256, GEMMF16_SMEM_BYTES>>>(
        (const __half*)phh, (const __half*)pwv, (float*)pv, BL, DV, HID);
    gemm_f16<<<dim3(DV / 128, BL / 128), t256, GEMMF16_SMEM_BYTES>>>(
        (const __half*)phh, (const __half*)pwg, (float*)pg, BL, DV, HID);
    // low-rank gate path (fp32, original h)
    gemm16_kernel<<<(BL * 16) / 256, t256>>>(h, Wgk1);
    gk_kernel<<<(BL * DK) / 256, t256>>>(Wgk2, bgk2);
    // gate prep (fp16 qg/ki)
    gateprep_kernel<<<dim3(DK / 256, BATCH * NCHUNK), t256>>>();
    // GLA
    gla_state_kernel<<<dim3(HDV / 64, BH), t256, STATE_SMEM_FLOATS * 4>>>();
    gla_out_kernel<<<dim3(NCHUNK, BH), t256, OUT_SMEM_HALVES * 2>>>();
    // rms norm + swish gate (fp16 out)
    normgate_kernel<<<BL * NH, t256>>>(gnw);
    // output projection
    ttrans_kernel<<<dim3(HID / 32, DV / 32), t256>>>(Wo, (__half*)pwo, DV, HID);
    gemm_f16<<<dim3(HID / 128, BL / 128), t256, GEMMF16_SMEM_BYTES>>>(
        (const __half*)pogh, (const __half*)pwo, out, BL, HID, DV);
}

// round 12
// speedup vs baseline: 7.7371x; 1.0200x over previous
#include <cuda_runtime.h>
#include <cuda_fp16.h>
#include <math.h>
#include <stdint.h>

#define BATCH 4
#define SEQL 2048
#define HID 1024
#define NH 4
#define DK 1024
#define DV 2048
#define HDK 256
#define HDV 512
#define CHUNK 64
#define NCHUNK (SEQL / CHUNK)
#define BL (BATCH * SEQL) /* 8192 */
#define BH (BATCH * NH)   /* 16 */
#define NQKV 4096         /* q(1024) | k(1024) | v(2048) */

// ---------------- scratch (static device allocations; no runtime alloc) ----
__device__ float g_gt[BL * DV];
__device__ float g_gk[BL * DK];
__device__ float g_t16[BL * 16];
__device__ float g_o[BL * DV];
// fp16 operands
__device__ __half g_hh[BL * HID];
__device__ __half g_ogh[BL * DV];
__device__ __half g_qkvh[(long)BL * NQKV];   // merged q|k|v, fp16
__device__ __half g_wqkvh[NQKV * HID];       // merged transposed weights
__device__ __half g_wgh[HID * DV];
__device__ __half g_woh[DV * HID];
// gate-prep outputs (fp16) + eb (fp32)
__device__ __half g_qgh[BL * DK];
__device__ __half g_kih[BL * DK];
__device__ float g_eb[BATCH * NCHUNK * DK];
// materialized chunk-start states: [bh][n][v(512)][d(256)] fp32
__device__ float g_S[(long)BH * NCHUNK * HDV * HDK];

// ================= helpers =================================================
__device__ __forceinline__ void mma_tf32(float* c, const unsigned* a, const unsigned* b) {
    asm volatile(
        "mma.sync.aligned.m16n8k8.row.col.f32.tf32.tf32.f32 "
        "{%0,%1,%2,%3}, {%4,%5,%6,%7}, {%8,%9}, {%0,%1,%2,%3};"
        : "+f"(c[0]), "+f"(c[1]), "+f"(c[2]), "+f"(c[3])
        : "r"(a[0]), "r"(a[1]), "r"(a[2]), "r"(a[3]), "r"(b[0]), "r"(b[1]));
}

__device__ __forceinline__ void mma_f16(float* c, const unsigned* a, const unsigned* b) {
    asm volatile(
        "mma.sync.aligned.m16n8k16.row.col.f32.f16.f16.f32 "
        "{%0,%1,%2,%3}, {%4,%5,%6,%7}, {%8,%9}, {%0,%1,%2,%3};"
        : "+f"(c[0]), "+f"(c[1]), "+f"(c[2]), "+f"(c[3])
        : "r"(a[0]), "r"(a[1]), "r"(a[2]), "r"(a[3]), "r"(b[0]), "r"(b[1]));
}

__device__ __forceinline__ void ldsm_x4(unsigned* r, unsigned addr) {
    asm volatile("ldmatrix.sync.aligned.m8n8.x4.shared.b16 {%0,%1,%2,%3}, [%4];"
                 : "=r"(r[0]), "=r"(r[1]), "=r"(r[2]), "=r"(r[3]) : "r"(addr));
}
__device__ __forceinline__ void ldsm_x2(unsigned* r, unsigned addr) {
    asm volatile("ldmatrix.sync.aligned.m8n8.x2.shared.b16 {%0,%1}, [%2];"
                 : "=r"(r[0]), "=r"(r[1]) : "r"(addr));
}

// ---------------- fp16 conversion pass --------------------------------------
__global__ __launch_bounds__(256) void htrunc_kernel(
    const float* __restrict__ src, __half* __restrict__ dst, int n4)
{
    int i = blockIdx.x * 256 + threadIdx.x;
    if (i < n4) {
        float4 v = ((const float4*)src)[i];
        ((__half2*)dst)[i * 2] = __floats2half2_rn(v.x, v.y);
        ((__half2*)dst)[i * 2 + 1] = __floats2half2_rn(v.z, v.w);
    }
}

// ---------------- weight transpose + fp16: W[K][N] -> WT[N][K] --------------
__global__ __launch_bounds__(256) void ttrans_kernel(
    const float* __restrict__ W, __half* __restrict__ WT, int Kd, int Nd)
{
    __shared__ float t[32][33];
    const int bx = blockIdx.x * 32;
    const int by = blockIdx.y * 32;
    const int x = threadIdx.x & 31, y = threadIdx.x >> 5;
#pragma unroll
    for (int j = 0; j < 32; j += 8)
        t[y + j][x] = W[(long)(by + y + j) * Nd + bx + x];
    __syncthreads();
#pragma unroll
    for (int j = 0; j < 32; j += 8)
        WT[(long)(bx + y + j) * Kd + by + x] = __float2half_rn(t[x][y + j]);
}

// ================= FP16 tensor-core GEMM ===================================
// Block 128x128x64, 256 threads (8 warps 2Mx4N), warp 64x32, 3-stage cp.async.
#define KC 64
#define ASTRH 72
#define TILEH (128 * ASTRH)
#define STAGEH (2 * TILEH)
#define GEMMF16_SMEM_BYTES (3 * STAGEH * 2)

template <typename OutT>
__global__ __launch_bounds__(256, 2) void gemm_f16(
    const __half* __restrict__ A, const __half* __restrict__ BT,
    OutT* __restrict__ C, int M, int N, int K)
{
    extern __shared__ __half smh[];
    const int tid = threadIdx.x;
    const int warp = tid >> 5, lane = tid & 31;
    const long bm = (long)blockIdx.y * 128, bn = (long)blockIdx.x * 128;
    const int wm = (warp & 1) * 64, wn = (warp >> 1) * 32;

    float acc[4][4][4];
#pragma unroll
    for (int mt = 0; mt < 4; mt++)
#pragma unroll
        for (int nt = 0; nt < 4; nt++)
#pragma unroll
            for (int u = 0; u < 4; u++) acc[mt][nt][u] = 0.f;

    auto load_tile = [&](int s, int kc) {
        const int k0 = kc * KC;
#pragma unroll
        for (int p = 0; p < 8; p++) {
            const int i = tid + p * 256;
            const int hsel = i >> 10;
            const int idx = i & 1023;
            const int row = idx >> 3, ch = idx & 7;
            const __half* src = hsel ? (BT + (bn + row) * (long)K + k0 + ch * 8)
                                     : (A + (bm + row) * (long)K + k0 + ch * 8);
            unsigned dst = (unsigned)__cvta_generic_to_shared(
                smh + s * STAGEH + hsel * TILEH + row * ASTRH + ch * 8);
            asm volatile("cp.async.cg.shared.global [%0], [%1], 16;\n"
                         :: "r"(dst), "l"(src));
        }
    };

    const int nk = K / KC;
    load_tile(0, 0);
    asm volatile("cp.async.commit_group;\n");
    load_tile(1, 1);
    asm volatile("cp.async.commit_group;\n");

    const int arow = (lane & 7) + ((lane >> 3) & 1) * 8;
    const int akoff = (lane >> 4) * 8;
    const int bnrow = lane & 7;
    const int bkoff = ((lane >> 3) & 1) * 8;

    for (int it = 0; it < nk; it++) {
        const int s = it % 3;
        if (it + 2 < nk) {
            load_tile((it + 2) % 3, it + 2);
            asm volatile("cp.async.commit_group;\n");
            asm volatile("cp.async.wait_group 2;\n");
        } else if (it + 1 < nk) {
            asm volatile("cp.async.wait_group 1;\n");
        } else {
            asm volatile("cp.async.wait_group 0;\n");
        }
        __syncthreads();

        const __half* sA = smh + s * STAGEH;
        const __half* sB = smh + s * STAGEH + TILEH;
#pragma unroll
        for (int kk = 0; kk < 4; kk++) {
            const int k0 = kk * 16;
            unsigned a[4][4], b[4][2];
#pragma unroll
            for (int mt = 0; mt < 4; mt++) {
                unsigned ad = (unsigned)__cvta_generic_to_shared(
                    sA + (wm + mt * 16 + arow) * ASTRH + k0 + akoff);
                ldsm_x4(a[mt], ad);
            }
#pragma unroll
            for (int nt = 0; nt < 4; nt++) {
                unsigned bd = (unsigned)__cvta_generic_to_shared(
                    sB + (wn + nt * 8 + bnrow) * ASTRH + k0 + bkoff);
                ldsm_x2(b[nt], bd);
            }
#pragma unroll
            for (int mt = 0; mt < 4; mt++)
#pragma unroll
                for (int nt = 0; nt < 4; nt++) mma_f16(acc[mt][nt], a[mt], b[nt]);
        }
        __syncthreads();
    }

    const int r = lane >> 2, cl = lane & 3;
    OutT* Cb = C + (bm + wm) * (long)N + bn + wn;
#pragma unroll
    for (int mt = 0; mt < 4; mt++) {
        const int row0 = mt * 16 + r;
#pragma unroll
        for (int nt = 0; nt < 4; nt++) {
            const int col = nt * 8 + 2 * cl;
            if constexpr (sizeof(OutT) == 4) {
                *(float2*)(Cb + (long)row0 * N + col) =
                    make_float2(acc[mt][nt][0], acc[mt][nt][1]);
                *(float2*)(Cb + (long)(row0 + 8) * N + col) =
                    make_float2(acc[mt][nt][2], acc[mt][nt][3]);
            } else {
                *(__half2*)(Cb + (long)row0 * N + col) =
                    __floats2half2_rn(acc[mt][nt][0], acc[mt][nt][1]);
                *(__half2*)(Cb + (long)(row0 + 8) * N + col) =
                    __floats2half2_rn(acc[mt][nt][2], acc[mt][nt][3]);
            }
        }
    }
}

// ---------------- low-rank gate: tmp = h @ Wgk1 -----------------------------
__global__ __launch_bounds__(256) void gemm16_kernel(
    const float* __restrict__ A, const float* __restrict__ W)
{
    int idx = blockIdx.x * 256 + threadIdx.x;
    int row = idx >> 4, col = idx & 15;
    const float* a = A + (long)row * HID;
    float acc = 0.f;
#pragma unroll 8
    for (int k = 0; k < HID; k++) acc += a[k] * W[k * 16 + col];
    g_t16[idx] = acc;
}

// ---------------- gk = log_sigmoid(tmp @ Wgk2 + b) / 16 --------------------
__global__ __launch_bounds__(256) void gk_kernel(
    const float* __restrict__ W2, const float* __restrict__ bias)
{
    int idx = blockIdx.x * 256 + threadIdx.x;
    int row = idx >> 10, c = idx & 1023;
    const float* t = g_t16 + row * 16;
    float acc = bias[c];
#pragma unroll
    for (int l = 0; l < 16; l++) acc += t[l] * W2[l * DK + c];
    float ax = fabsf(acc);
    float ls = fminf(acc, 0.f) - __logf(1.f + __expf(-ax));
    g_gk[idx] = ls * 0.0625f;
}

// ---------------- gate prep: qg/ki (fp16) + eb ------------------------------
__global__ __launch_bounds__(256) void gateprep_kernel()
{
    const int col = blockIdx.x * 256 + threadIdx.x;
    const int bn = blockIdx.y;
    const int b = bn / NCHUNK, n = bn % NCHUNK;
    const long rowbase = (long)(b * SEQL + n * CHUNK);
    const float* gkp = g_gk + rowbase * DK + col;
    const __half* qp = g_qkvh + rowbase * NQKV + col;
    const __half* kp = qp + DK;
    __half* qgp = g_qgh + rowbase * DK + col;
    __half* kip = g_kih + rowbase * DK + col;
    const float scale = 0.0625f;

    float bsum = 0.f, ep = 1.f;
#pragma unroll 4
    for (int t = 0; t < CHUNK; t++) {
        bsum += gkp[(long)t * DK];
        ep = __expf(bsum);
        float en = __expf(-bsum);
        qgp[(long)t * DK] = __float2half_rn(__half2float(qp[(long)t * NQKV]) * ep * scale);
        kip[(long)t * DK] = __float2half_rn(__half2float(kp[(long)t * NQKV]) * en);
    }
    g_eb[(long)bn * DK + col] = ep;
}

// ================= GLA split: sequential state kernel (tf32) ================
#define QSTR 257
#define VSTR 65
#define STSTR 260
#define STATE_SMEM_FLOATS (64 * QSTR + 64 * STSTR + 64 * VSTR + 256)

__global__ __launch_bounds__(256) void gla_state_kernel()
{
    extern __shared__ float sm[];
    float* ki  = sm;
    float* ST  = ki + 64 * QSTR;
    float* vtT = ST + 64 * STSTR;
    float* eb  = vtT + 64 * VSTR;

    const int tid = threadIdx.x;
    const int warp = tid >> 5, lane = tid & 31;
    const int r = lane >> 2, cl = lane & 3, cl2 = 2 * (lane & 3);
    const int vs = blockIdx.x;
    const int bh = blockIdx.y;
    const int b = bh >> 2, hh = bh & 3;

    for (int i = tid; i < 64 * STSTR; i += 256) ST[i] = 0.f;
    __syncthreads();

    for (int n = 0; n < NCHUNK; n++) {
        {
            const long sbase = ((long)(bh * NCHUNK + n) * HDV + vs * 64) * HDK;
#pragma unroll
            for (int idx = tid; idx < 64 * 64; idx += 256) {
                int row = idx >> 6, c4 = idx & 63;
                const float* srow = ST + row * STSTR + c4 * 4;
                ((float4*)(g_S + sbase + (long)row * HDK))[c4] =
                    make_float4(srow[0], srow[1], srow[2], srow[3]);
            }
        }
        {
            eb[tid] = g_eb[((long)(b * NCHUNK + n)) * DK + hh * HDK + tid];
            const long rowbase = (long)(b * SEQL + n * CHUNK);
#pragma unroll
            for (int idx = tid; idx < 64 * 32; idx += 256) {
                int t = idx >> 5, c8 = idx & 31;
                const __half2* src = (const __half2*)(g_kih + (rowbase + t) * DK + hh * HDK + c8 * 8);
                float* kd = ki + t * QSTR + c8 * 8;
#pragma unroll
                for (int j = 0; j < 4; j++) {
                    float2 f = __half22float2(src[j]);
                    kd[j * 2] = f.x;
                    kd[j * 2 + 1] = f.y;
                }
            }
            const __half* vsrc = g_qkvh + rowbase * NQKV + 2 * DK + hh * HDV + vs * 64;
#pragma unroll
            for (int i = tid; i < 64 * 64; i += 256) {
                int t = i >> 6, vo = i & 63;
                vtT[vo * VSTR + t] = __half2float(vsrc[(long)t * NQKV + vo]);
            }
        }
        __syncthreads();

        {
#pragma unroll
            for (int mt = 0; mt < 2; mt++) {
                const int m0 = warp * 32 + mt * 16;
                float cD[8][4];
#pragma unroll
                for (int ns = 0; ns < 8; ns++)
#pragma unroll
                    for (int u = 0; u < 4; u++) cD[ns][u] = 0.f;
#pragma unroll
                for (int k0 = 0; k0 < CHUNK; k0 += 8) {
                    unsigned a[4];
                    const float* ap = ki + (k0 + cl) * QSTR + m0 + r;
                    a[0] = __float_as_uint(ap[0]);
                    a[1] = __float_as_uint(ap[8]);
                    a[2] = __float_as_uint(ap[4 * QSTR]);
                    a[3] = __float_as_uint(ap[4 * QSTR + 8]);
#pragma unroll
                    for (int ns = 0; ns < 8; ns++) {
                        unsigned bb[2];
                        const float* bp = vtT + (ns * 8 + r) * VSTR + k0 + cl;
                        bb[0] = __float_as_uint(bp[0]);
                        bb[1] = __float_as_uint(bp[4]);
                        mma_tf32(cD[ns], a, bb);
                    }
                }
                const float e0 = eb[m0 + r];
                const float e1 = eb[m0 + r + 8];
#pragma unroll
                for (int ns = 0; ns < 8; ns++) {
                    const int col = ns * 8 + cl2;
                    float* s00 = ST + col * STSTR + m0 + r;
                    float* s01 = ST + (col + 1) * STSTR + m0 + r;
                    s00[0] = e0 * (s00[0] + cD[ns][0]);
                    s01[0] = e0 * (s01[0] + cD[ns][1]);
                    s00[8] = e1 * (s00[8] + cD[ns][2]);
                    s01[8] = e1 * (s01[8] + cD[ns][3]);
                }
            }
        }
        __syncthreads();
    }
}

// ================= GLA split: parallel output kernel (fp16) =================
#define OQ 264
#define OV 72
#define OUT_SMEM_HALVES (2 * 64 * OQ + 2 * 64 * OV)

__global__ __launch_bounds__(256, 2) void gla_out_kernel()
{
    extern __shared__ __half smo[];
    __half* qgh  = smo;
    __half* kist = qgh + 64 * OQ;
    __half* sch  = kist + 64 * OQ;
    __half* vtTh = sch + 64 * OV;

    const int tid = threadIdx.x;
    const int warp = tid >> 5, lane = tid & 31;
    const int r = lane >> 2, cl = lane & 3;
    const int n = blockIdx.x;
    const int bh = blockIdx.y;
    const int b = bh >> 2, hh = bh & 3;

    const int wm = (warp & 3) * 16;
    const int wn = (warp >> 2) * 32;

    const int arow = (lane & 7) + ((lane >> 3) & 1) * 8;
    const int akoff = (lane >> 4) * 8;
    const int bnrow = lane & 7;
    const int bkoff = ((lane >> 3) & 1) * 8;

    const long rowbase = (long)(b * SEQL + n * CHUNK);

    {
#pragma unroll
        for (int idx = tid; idx < 64 * 32; idx += 256) {
            int t = idx >> 5, c8 = idx & 31;
            *(uint4*)(qgh + t * OQ + c8 * 8) =
                *(const uint4*)(g_qgh + (rowbase + t) * DK + hh * HDK + c8 * 8);
            *(uint4*)(kist + t * OQ + c8 * 8) =
                *(const uint4*)(g_kih + (rowbase + t) * DK + hh * HDK + c8 * 8);
        }
    }
    __syncthreads();

    {
        float c[4][4];
#pragma unroll
        for (int nt = 0; nt < 4; nt++)
#pragma unroll
            for (int u = 0; u < 4; u++) c[nt][u] = 0.f;
#pragma unroll
        for (int k0 = 0; k0 < HDK; k0 += 16) {
            unsigned a[4];
            ldsm_x4(a, (unsigned)__cvta_generic_to_shared(
                qgh + (wm + arow) * OQ + k0 + akoff));
#pragma unroll
            for (int nt = 0; nt < 4; nt++) {
                unsigned bb[2];
                ldsm_x2(bb, (unsigned)__cvta_generic_to_shared(
                    kist + (wn + nt * 8 + bnrow) * OQ + k0 + bkoff));
                mma_f16(c[nt], a, bb);
            }
        }
        const int row0 = wm + r, row1 = wm + r + 8;
#pragma unroll
        for (int nt = 0; nt < 4; nt++) {
            const int col = wn + nt * 8 + 2 * cl;
            sch[row0 * OV + col]     = (col     <= row0) ? __float2half_rn(c[nt][0]) : __half(0.f);
            sch[row0 * OV + col + 1] = (col + 1 <= row0) ? __float2half_rn(c[nt][1]) : __half(0.f);
            sch[row1 * OV + col]     = (col     <= row1) ? __float2half_rn(c[nt][2]) : __half(0.f);
            sch[row1 * OV + col + 1] = (col + 1 <= row1) ? __float2half_rn(c[nt][3]) : __half(0.f);
        }
    }
    __syncthreads();

    for (int vs = 0; vs < HDV / 64; vs++) {
        {
            const long sbase = ((long)(bh * NCHUNK + n) * HDV + vs * 64) * HDK;
#pragma unroll
            for (int idx = tid; idx < 64 * 64; idx += 256) {
                int row = idx >> 6, c4 = idx & 63;
                float4 v4 = ((const float4*)(g_S + sbase + (long)row * HDK))[c4];
                __half* dst = kist + row * OQ + c4 * 4;
                *(__half2*)dst       = __floats2half2_rn(v4.x, v4.y);
                *(__half2*)(dst + 2) = __floats2half2_rn(v4.z, v4.w);
            }
            const __half* vsrc = g_qkvh + rowbase * NQKV + 2 * DK + hh * HDV + vs * 64;
#pragma unroll
            for (int i = tid; i < 64 * 64; i += 256) {
                int t = i >> 6, vo = i & 63;
                vtTh[vo * OV + t] = vsrc[(long)t * NQKV + vo];
            }
        }
        __syncthreads();

        {
            float o[4][4];
#pragma unroll
            for (int nt = 0; nt < 4; nt++)
#pragma unroll
                for (int u = 0; u < 4; u++) o[nt][u] = 0.f;
#pragma unroll
            for (int k0 = 0; k0 < CHUNK; k0 += 16) {
                unsigned a[4];
                ldsm_x4(a, (unsigned)__cvta_generic_to_shared(
                    sch + (wm + arow) * OV + k0 + akoff));
#pragma unroll
                for (int nt = 0; nt < 4; nt++) {
                    unsigned bb[2];
                    ldsm_x2(bb, (unsigned)__cvta_generic_to_shared(
                        vtTh + (wn + nt * 8 + bnrow) * OV + k0 + bkoff));
                    mma_f16(o[nt], a, bb);
                }
            }
#pragma unroll
            for (int k0 = 0; k0 < HDK; k0 += 16) {
                unsigned a[4];
                ldsm_x4(a, (unsigned)__cvta_generic_to_shared(
                    qgh + (wm + arow) * OQ + k0 + akoff));
#pragma unroll
                for (int nt = 0; nt < 4; nt++) {
                    unsigned bb[2];
                    ldsm_x2(bb, (unsigned)__cvta_generic_to_shared(
                        kist + (wn + nt * 8 + bnrow) * OQ + k0 + bkoff));
                    mma_f16(o[nt], a, bb);
                }
            }
            const long ocol = hh * HDV + vs * 64;
            float* op = g_o + (rowbase + wm + r) * (long)DV + ocol + wn;
            float* op8 = op + 8 * DV;
#pragma unroll
            for (int nt = 0; nt < 4; nt++) {
                const int col = nt * 8 + 2 * cl;
                *(float2*)(op + col)  = make_float2(o[nt][0], o[nt][1]);
                *(float2*)(op8 + col) = make_float2(o[nt][2], o[nt][3]);
            }
        }
        __syncthreads();
    }
}

// ---------------- RMS norm + swish gate (fp16 output) ----------------------
__global__ __launch_bounds__(256) void normgate_kernel(const float* __restrict__ gnw)
{
    const int row = blockIdx.x;
    const int tid = threadIdx.x;
    const long base = (long)(row >> 2) * DV + (row & 3) * HDV;
    const float* op = g_o + base;
    const float* gp = g_gt + base;
    __half* ogp = g_ogh + base;

    float vals[2];
    float ss = 0.f;
#pragma unroll
    for (int u = 0; u < 2; u++) {
        vals[u] = op[tid + 256 * u];
        ss += vals[u] * vals[u];
    }
    __shared__ float red[8];
#pragma unroll
    for (int o = 16; o > 0; o >>= 1) ss += __shfl_xor_sync(0xffffffffu, ss, o);
    if ((tid & 31) == 0) red[tid >> 5] = ss;
    __syncthreads();
    if (tid < 8) {
        float rr = red[tid];
#pragma unroll
        for (int o = 4; o > 0; o >>= 1) rr += __shfl_xor_sync(0xffu, rr, o);
        if (tid == 0) red[0] = rr;
    }
    __syncthreads();
    const float rinv = rsqrtf(red[0] * (1.f / 512.f) + 1e-5f);
#pragma unroll
    for (int u = 0; u < 2; u++) {
        int c = tid + 256 * u;
        float g = gp[c];
        float sig = 1.f / (1.f + __expf(-g));
        ogp[c] = __float2half_rn(vals[u] * rinv * gnw[c] * (g * sig));
    }
}

// ---------------- launch ----------------------------------------------------
extern "C" void kernel_launch(void* const* d_in, const int* in_sizes, int n_in,
                              void* d_out, int out_size)
{
    (void)in_sizes; (void)n_in; (void)out_size;
    const float* h    = (const float*)d_in[0];
    const float* Wq   = (const float*)d_in[1];
    const float* Wk   = (const float*)d_in[2];
    const float* Wv   = (const float*)d_in[3];
    const float* Wg   = (const float*)d_in[4];
    const float* Wgk1 = (const float*)d_in[5];
    const float* Wgk2 = (const float*)d_in[6];
    const float* bgk2 = (const float*)d_in[7];
    const float* gnw  = (const float*)d_in[8];
    const float* Wo   = (const float*)d_in[9];
    float* out = (float*)d_out;

    void *pg, *pogh, *phh, *pqkv, *pwqkv, *pwg, *pwo;
    cudaGetSymbolAddress(&pg, g_gt);
    cudaGetSymbolAddress(&pogh, g_ogh);
    cudaGetSymbolAddress(&phh, g_hh);
    cudaGetSymbolAddress(&pqkv, g_qkvh);
    cudaGetSymbolAddress(&pwqkv, g_wqkvh);
    cudaGetSymbolAddress(&pwg, g_wgh);
    cudaGetSymbolAddress(&pwo, g_woh);

    static_assert(STATE_SMEM_FLOATS * 4 <= 232448, "state smem too big");
    static_assert(OUT_SMEM_HALVES * 2 * 2 <= 232448, "out smem too big");
    static_assert(GEMMF16_SMEM_BYTES * 2 <= 232448, "gemm smem too big");
    cudaFuncSetAttribute(gla_state_kernel, cudaFuncAttributeMaxDynamicSharedMemorySize,
                         STATE_SMEM_FLOATS * 4);
    cudaFuncSetAttribute(gla_out_kernel, cudaFuncAttributeMaxDynamicSharedMemorySize,
                         OUT_SMEM_HALVES * 2);
    cudaFuncSetAttribute(gemm_f16<float>, cudaFuncAttributeMaxDynamicSharedMemorySize,
                         GEMMF16_SMEM_BYTES);
    cudaFuncSetAttribute(gemm_f16<__half>, cudaFuncAttributeMaxDynamicSharedMemorySize,
                         GEMMF16_SMEM_BYTES);

    __half* wqkv = (__half*)pwqkv;

    dim3 t256(256);
    // conversion passes
    htrunc_kernel<<<(BL * HID / 4 + 255) / 256, t256>>>(h, (__half*)phh, BL * HID / 4);
    ttrans_kernel<<<dim3(DK / 32, HID / 32), t256>>>(Wq, wqkv, HID, DK);
    ttrans_kernel<<<dim3(DK / 32, HID / 32), t256>>>(Wk, wqkv + (long)DK * HID, HID, DK);
    ttrans_kernel<<<dim3(DV / 32, HID / 32), t256>>>(Wv, wqkv + (long)2 * DK * HID, HID, DV);
    ttrans_kernel<<<dim3(DV / 32, HID / 32), t256>>>(Wg, (__half*)pwg, HID, DV);

    // merged q|k|v projection (fp16 out) + g projection (fp32 out)
    gemm_f16<__half><<<dim3(NQKV / 128, BL / 128), t256, GEMMF16_SMEM_BYTES>>>(
        (const __half*)phh, wqkv, (__half*)pqkv, BL, NQKV, HID);
    gemm_f16<float><<<dim3(DV / 128, BL / 128), t256, GEMMF16_SMEM_BYTES>>>(
        (const __half*)phh, (const __half*)pwg, (float*)pg, BL, DV, HID);
    // low-rank gate path (fp32, original h)
    gemm16_kernel<<<(BL * 16) / 256, t256>>>(h, Wgk1);
    gk_kernel<<<(BL * DK) / 256, t256>>>(Wgk2, bgk2);
    // gate prep (fp16 qg/ki)
    gateprep_kernel<<<dim3(DK / 256, BATCH * NCHUNK), t256>>>();
    // GLA
    gla_state_kernel<<<dim3(HDV / 64, BH), t256, STATE_SMEM_FLOATS * 4>>>();
    gla_out_kernel<<<dim3(NCHUNK, BH), t256, OUT_SMEM_HALVES * 2>>>();
    // rms norm + swish gate (fp16 out)
    normgate_kernel<<<BL * NH, t256>>>(gnw);
    // output projection
    ttrans_kernel<<<dim3(HID / 32, DV / 32), t256>>>(Wo, (__half*)pwo, DV, HID);
    gemm_f16<float><<<dim3(HID / 128, BL / 128), t256, GEMMF16_SMEM_BYTES>>>(
        (const __half*)pogh, (const __half*)pwo, out, BL, HID, DV);
}

// round 16
// speedup vs baseline: 7.8425x; 1.0136x over previous
#include <cuda_runtime.h>
#include <cuda_fp16.h>
#include <math.h>
#include <stdint.h>

#define BATCH 4
#define SEQL 2048
#define HID 1024
#define NH 4
#define DK 1024
#define DV 2048
#define HDK 256
#define HDV 512
#define CHUNK 64
#define NCHUNK (SEQL / CHUNK)
#define BL (BATCH * SEQL) /* 8192 */
#define BH (BATCH * NH)   /* 16 */
#define NQKV 4096         /* q(1024) | k(1024) | v(2048) */

// ---------------- scratch (static device allocations; no runtime alloc) ----
__device__ float g_gt[BL * DV];
__device__ float g_gk[BL * DK];
__device__ float g_t16[BL * 16];
__device__ float g_o[BL * DV];
// fp16 operands
__device__ __half g_hh[BL * HID];
__device__ __half g_ogh[BL * DV];
__device__ __half g_qkvh[(long)BL * NQKV];
__device__ __half g_wqkvh[NQKV * HID];
__device__ __half g_wgh[HID * DV];
__device__ __half g_woh[DV * HID];
// gate-prep outputs (fp16) + eb (fp32)
__device__ __half g_qgh[BL * DK];
__device__ __half g_kih[BL * DK];
__device__ float g_eb[BATCH * NCHUNK * DK];
// materialized chunk-start states: [bh][n][v(512)][d(256)] fp16
// (identical to downstream use: gla_out converts S to fp16 before MMA anyway)
__device__ __half g_Sh[(long)BH * NCHUNK * HDV * HDK];

// ================= helpers =================================================
__device__ __forceinline__ void mma_tf32(float* c, const unsigned* a, const unsigned* b) {
    asm volatile(
        "mma.sync.aligned.m16n8k8.row.col.f32.tf32.tf32.f32 "
        "{%0,%1,%2,%3}, {%4,%5,%6,%7}, {%8,%9}, {%0,%1,%2,%3};"
        : "+f"(c[0]), "+f"(c[1]), "+f"(c[2]), "+f"(c[3])
        : "r"(a[0]), "r"(a[1]), "r"(a[2]), "r"(a[3]), "r"(b[0]), "r"(b[1]));
}

__device__ __forceinline__ void mma_f16(float* c, const unsigned* a, const unsigned* b) {
    asm volatile(
        "mma.sync.aligned.m16n8k16.row.col.f32.f16.f16.f32 "
        "{%0,%1,%2,%3}, {%4,%5,%6,%7}, {%8,%9}, {%0,%1,%2,%3};"
        : "+f"(c[0]), "+f"(c[1]), "+f"(c[2]), "+f"(c[3])
        : "r"(a[0]), "r"(a[1]), "r"(a[2]), "r"(a[3]), "r"(b[0]), "r"(b[1]));
}

__device__ __forceinline__ void ldsm_x4(unsigned* r, unsigned addr) {
    asm volatile("ldmatrix.sync.aligned.m8n8.x4.shared.b16 {%0,%1,%2,%3}, [%4];"
                 : "=r"(r[0]), "=r"(r[1]), "=r"(r[2]), "=r"(r[3]) : "r"(addr));
}
__device__ __forceinline__ void ldsm_x2(unsigned* r, unsigned addr) {
    asm volatile("ldmatrix.sync.aligned.m8n8.x2.shared.b16 {%0,%1}, [%2];"
                 : "=r"(r[0]), "=r"(r[1]) : "r"(addr));
}

// ---------------- fp16 conversion pass --------------------------------------
__global__ __launch_bounds__(256) void htrunc_kernel(
    const float* __restrict__ src, __half* __restrict__ dst, int n4)
{
    int i = blockIdx.x * 256 + threadIdx.x;
    if (i < n4) {
        float4 v = ((const float4*)src)[i];
        ((__half2*)dst)[i * 2] = __floats2half2_rn(v.x, v.y);
        ((__half2*)dst)[i * 2 + 1] = __floats2half2_rn(v.z, v.w);
    }
}

// ---------------- weight transpose + fp16: W[K][N] -> WT[N][K] --------------
__global__ __launch_bounds__(256) void ttrans_kernel(
    const float* __restrict__ W, __half* __restrict__ WT, int Kd, int Nd)
{
    __shared__ float t[32][33];
    const int bx = blockIdx.x * 32;
    const int by = blockIdx.y * 32;
    const int x = threadIdx.x & 31, y = threadIdx.x >> 5;
#pragma unroll
    for (int j = 0; j < 32; j += 8)
        t[y + j][x] = W[(long)(by + y + j) * Nd + bx + x];
    __syncthreads();
#pragma unroll
    for (int j = 0; j < 32; j += 8)
        WT[(long)(bx + y + j) * Kd + by + x] = __float2half_rn(t[x][y + j]);
}

// ================= FP16 tensor-core GEMM ===================================
// C[M,N] = A[M,K] @ BT[N,K]^T. Templated M-tile (BM in {64,128}), N-tile 128,
// K-chunk 64, 256 threads (2Mx4N warps, warp tile (BM/2)x32), 3-stage cp.async.
#define KC 64
#define ASTRH 72

template <int BM, typename OutT>
__global__ __launch_bounds__(256, 2) void gemm_f16(
    const __half* __restrict__ A, const __half* __restrict__ BT,
    OutT* __restrict__ C, int M, int N, int K)
{
    constexpr int MT = BM / 32;                    // warp m-subtiles
    constexpr int TROWS = BM + 128;                // A rows + B rows per stage
    constexpr int STG = TROWS * ASTRH;             // halves per stage
    extern __shared__ __half smh[];
    const int tid = threadIdx.x;
    const int warp = tid >> 5, lane = tid & 31;
    const long bm = (long)blockIdx.y * BM, bn = (long)blockIdx.x * 128;
    const int wm = (warp & 1) * (BM / 2), wn = (warp >> 1) * 32;

    float acc[MT][4][4];
#pragma unroll
    for (int mt = 0; mt < MT; mt++)
#pragma unroll
        for (int nt = 0; nt < 4; nt++)
#pragma unroll
            for (int u = 0; u < 4; u++) acc[mt][nt][u] = 0.f;

    auto load_tile = [&](int s, int kc) {
        const int k0 = kc * KC;
#pragma unroll
        for (int p = 0; p < TROWS * 8 / 256; p++) {
            const int i = tid + p * 256;
            const int row = i >> 3, ch = i & 7;
            const __half* src = (row < BM)
                ? (A + (bm + row) * (long)K + k0 + ch * 8)
                : (BT + (bn + row - BM) * (long)K + k0 + ch * 8);
            unsigned dst = (unsigned)__cvta_generic_to_shared(
                smh + s * STG + row * ASTRH + ch * 8);
            asm volatile("cp.async.cg.shared.global [%0], [%1], 16;\n"
                         :: "r"(dst), "l"(src));
        }
    };

    const int nk = K / KC;
    load_tile(0, 0);
    asm volatile("cp.async.commit_group;\n");
    load_tile(1, 1);
    asm volatile("cp.async.commit_group;\n");

    const int arow = (lane & 7) + ((lane >> 3) & 1) * 8;
    const int akoff = (lane >> 4) * 8;
    const int bnrow = lane & 7;
    const int bkoff = ((lane >> 3) & 1) * 8;

    for (int it = 0; it < nk; it++) {
        const int s = it % 3;
        if (it + 2 < nk) {
            load_tile((it + 2) % 3, it + 2);
            asm volatile("cp.async.commit_group;\n");
            asm volatile("cp.async.wait_group 2;\n");
        } else if (it + 1 < nk) {
            asm volatile("cp.async.wait_group 1;\n");
        } else {
            asm volatile("cp.async.wait_group 0;\n");
        }
        __syncthreads();

        const __half* sA = smh + s * STG;
        const __half* sB = smh + s * STG + BM * ASTRH;
#pragma unroll
        for (int kk = 0; kk < 4; kk++) {
            const int k0 = kk * 16;
            unsigned a[MT][4], b[4][2];
#pragma unroll
            for (int mt = 0; mt < MT; mt++) {
                unsigned ad = (unsigned)__cvta_generic_to_shared(
                    sA + (wm + mt * 16 + arow) * ASTRH + k0 + akoff);
                ldsm_x4(a[mt], ad);
            }
#pragma unroll
            for (int nt = 0; nt < 4; nt++) {
                unsigned bd = (unsigned)__cvta_generic_to_shared(
                    sB + (wn + nt * 8 + bnrow) * ASTRH + k0 + bkoff);
                ldsm_x2(b[nt], bd);
            }
#pragma unroll
            for (int mt = 0; mt < MT; mt++)
#pragma unroll
                for (int nt = 0; nt < 4; nt++) mma_f16(acc[mt][nt], a[mt], b[nt]);
        }
        __syncthreads();
    }

    const int r = lane >> 2, cl = lane & 3;
    OutT* Cb = C + (bm + wm) * (long)N + bn + wn;
#pragma unroll
    for (int mt = 0; mt < MT; mt++) {
        const int row0 = mt * 16 + r;
#pragma unroll
        for (int nt = 0; nt < 4; nt++) {
            const int col = nt * 8 + 2 * cl;
            if constexpr (sizeof(OutT) == 4) {
                *(float2*)(Cb + (long)row0 * N + col) =
                    make_float2(acc[mt][nt][0], acc[mt][nt][1]);
                *(float2*)(Cb + (long)(row0 + 8) * N + col) =
                    make_float2(acc[mt][nt][2], acc[mt][nt][3]);
            } else {
                *(__half2*)(Cb + (long)row0 * N + col) =
                    __floats2half2_rn(acc[mt][nt][0], acc[mt][nt][1]);
                *(__half2*)(Cb + (long)(row0 + 8) * N + col) =
                    __floats2half2_rn(acc[mt][nt][2], acc[mt][nt][3]);
            }
        }
    }
}

#define GEMM_SMEM(BM) (3 * ((BM) + 128) * ASTRH * 2)

// ---------------- low-rank gate: tmp = h @ Wgk1 -----------------------------
__global__ __launch_bounds__(256) void gemm16_kernel(
    const float* __restrict__ A, const float* __restrict__ W)
{
    int idx = blockIdx.x * 256 + threadIdx.x;
    int row = idx >> 4, col = idx & 15;
    const float* a = A + (long)row * HID;
    float acc = 0.f;
#pragma unroll 8
    for (int k = 0; k < HID; k++) acc += a[k] * W[k * 16 + col];
    g_t16[idx] = acc;
}

// ---------------- gk = log_sigmoid(tmp @ Wgk2 + b) / 16 --------------------
__global__ __launch_bounds__(256) void gk_kernel(
    const float* __restrict__ W2, const float* __restrict__ bias)
{
    int idx = blockIdx.x * 256 + threadIdx.x;
    int row = idx >> 10, c = idx & 1023;
    const float* t = g_t16 + row * 16;
    float acc = bias[c];
#pragma unroll
    for (int l = 0; l < 16; l++) acc += t[l] * W2[l * DK + c];
    float ax = fabsf(acc);
    float ls = fminf(acc, 0.f) - __logf(1.f + __expf(-ax));
    g_gk[idx] = ls * 0.0625f;
}

// ---------------- gate prep: qg/ki (fp16) + eb ------------------------------
__global__ __launch_bounds__(256) void gateprep_kernel()
{
    const int col = blockIdx.x * 256 + threadIdx.x;
    const int bn = blockIdx.y;
    const int b = bn / NCHUNK, n = bn % NCHUNK;
    const long rowbase = (long)(b * SEQL + n * CHUNK);
    const float* gkp = g_gk + rowbase * DK + col;
    const __half* qp = g_qkvh + rowbase * NQKV + col;
    const __half* kp = qp + DK;
    __half* qgp = g_qgh + rowbase * DK + col;
    __half* kip = g_kih + rowbase * DK + col;
    const float scale = 0.0625f;

    float bsum = 0.f, ep = 1.f;
#pragma unroll 4
    for (int t = 0; t < CHUNK; t++) {
        bsum += gkp[(long)t * DK];
        ep = __expf(bsum);
        float en = __expf(-bsum);
        qgp[(long)t * DK] = __float2half_rn(__half2float(qp[(long)t * NQKV]) * ep * scale);
        kip[(long)t * DK] = __float2half_rn(__half2float(kp[(long)t * NQKV]) * en);
    }
    g_eb[(long)bn * DK + col] = ep;
}

// ================= GLA split: sequential state kernel (tf32) ================
#define QSTR 257
#define VSTR 65
#define STSTR 260
#define STATE_SMEM_FLOATS (64 * QSTR + 64 * STSTR + 64 * VSTR + 256)

__global__ __launch_bounds__(256) void gla_state_kernel()
{
    extern __shared__ float sm[];
    float* ki  = sm;
    float* ST  = ki + 64 * QSTR;
    float* vtT = ST + 64 * STSTR;
    float* eb  = vtT + 64 * VSTR;

    const int tid = threadIdx.x;
    const int warp = tid >> 5, lane = tid & 31;
    const int r = lane >> 2, cl = lane & 3, cl2 = 2 * (lane & 3);
    const int vs = blockIdx.x;
    const int bh = blockIdx.y;
    const int b = bh >> 2, hh = bh & 3;

    for (int i = tid; i < 64 * STSTR; i += 256) ST[i] = 0.f;
    __syncthreads();

    for (int n = 0; n < NCHUNK; n++) {
        // ---- store S_n snapshot as fp16 (value-identical to downstream use)
        {
            const long sbase = ((long)(bh * NCHUNK + n) * HDV + vs * 64) * HDK;
#pragma unroll
            for (int idx = tid; idx < 64 * 32; idx += 256) {
                int row = idx >> 5, c8 = idx & 31;
                const float* srow = ST + row * STSTR + c8 * 8;
                __half2 hh4[4];
#pragma unroll
                for (int j = 0; j < 4; j++)
                    hh4[j] = __floats2half2_rn(srow[j * 2], srow[j * 2 + 1]);
                *(uint4*)(g_Sh + sbase + (long)row * HDK + c8 * 8) = *(uint4*)hh4;
            }
        }
        {
            eb[tid] = g_eb[((long)(b * NCHUNK + n)) * DK + hh * HDK + tid];
            const long rowbase = (long)(b * SEQL + n * CHUNK);
#pragma unroll
            for (int idx = tid; idx < 64 * 32; idx += 256) {
                int t = idx >> 5, c8 = idx & 31;
                const __half2* src = (const __half2*)(g_kih + (rowbase + t) * DK + hh * HDK + c8 * 8);
                float* kd = ki + t * QSTR + c8 * 8;
#pragma unroll
                for (int j = 0; j < 4; j++) {
                    float2 f = __half22float2(src[j]);
                    kd[j * 2] = f.x;
                    kd[j * 2 + 1] = f.y;
                }
            }
            const __half* vsrc = g_qkvh + rowbase * NQKV + 2 * DK + hh * HDV + vs * 64;
#pragma unroll
            for (int i = tid; i < 64 * 64; i += 256) {
                int t = i >> 6, vo = i & 63;
                vtT[vo * VSTR + t] = __half2float(vsrc[(long)t * NQKV + vo]);
            }
        }
        __syncthreads();

        {
#pragma unroll
            for (int mt = 0; mt < 2; mt++) {
                const int m0 = warp * 32 + mt * 16;
                float cD[8][4];
#pragma unroll
                for (int ns = 0; ns < 8; ns++)
#pragma unroll
                    for (int u = 0; u < 4; u++) cD[ns][u] = 0.f;
#pragma unroll
                for (int k0 = 0; k0 < CHUNK; k0 += 8) {
                    unsigned a[4];
                    const float* ap = ki + (k0 + cl) * QSTR + m0 + r;
                    a[0] = __float_as_uint(ap[0]);
                    a[1] = __float_as_uint(ap[8]);
                    a[2] = __float_as_uint(ap[4 * QSTR]);
                    a[3] = __float_as_uint(ap[4 * QSTR + 8]);
#pragma unroll
                    for (int ns = 0; ns < 8; ns++) {
                        unsigned bb[2];
                        const float* bp = vtT + (ns * 8 + r) * VSTR + k0 + cl;
                        bb[0] = __float_as_uint(bp[0]);
                        bb[1] = __float_as_uint(bp[4]);
                        mma_tf32(cD[ns], a, bb);
                    }
                }
                const float e0 = eb[m0 + r];
                const float e1 = eb[m0 + r + 8];
#pragma unroll
                for (int ns = 0; ns < 8; ns++) {
                    const int col = ns * 8 + cl2;
                    float* s00 = ST + col * STSTR + m0 + r;
                    float* s01 = ST + (col + 1) * STSTR + m0 + r;
                    s00[0] = e0 * (s00[0] + cD[ns][0]);
                    s01[0] = e0 * (s01[0] + cD[ns][1]);
                    s00[8] = e1 * (s00[8] + cD[ns][2]);
                    s01[8] = e1 * (s01[8] + cD[ns][3]);
                }
            }
        }
        __syncthreads();
    }
}

// ================= GLA split: parallel output kernel (fp16) =================
#define OQ 264
#define OV 72
#define OUT_SMEM_HALVES (2 * 64 * OQ + 2 * 64 * OV)

__global__ __launch_bounds__(256, 2) void gla_out_kernel()
{
    extern __shared__ __half smo[];
    __half* qgh  = smo;
    __half* kist = qgh + 64 * OQ;
    __half* sch  = kist + 64 * OQ;
    __half* vtTh = sch + 64 * OV;

    const int tid = threadIdx.x;
    const int warp = tid >> 5, lane = tid & 31;
    const int r = lane >> 2, cl = lane & 3;
    const int n = blockIdx.x;
    const int bh = blockIdx.y;
    const int b = bh >> 2, hh = bh & 3;

    const int wm = (warp & 3) * 16;
    const int wn = (warp >> 2) * 32;

    const int arow = (lane & 7) + ((lane >> 3) & 1) * 8;
    const int akoff = (lane >> 4) * 8;
    const int bnrow = lane & 7;
    const int bkoff = ((lane >> 3) & 1) * 8;

    const long rowbase = (long)(b * SEQL + n * CHUNK);

    {
#pragma unroll
        for (int idx = tid; idx < 64 * 32; idx += 256) {
            int t = idx >> 5, c8 = idx & 31;
            *(uint4*)(qgh + t * OQ + c8 * 8) =
                *(const uint4*)(g_qgh + (rowbase + t) * DK + hh * HDK + c8 * 8);
            *(uint4*)(kist + t * OQ + c8 * 8) =
                *(const uint4*)(g_kih + (rowbase + t) * DK + hh * HDK + c8 * 8);
        }
    }
    __syncthreads();

    {
        float c[4][4];
#pragma unroll
        for (int nt = 0; nt < 4; nt++)
#pragma unroll
            for (int u = 0; u < 4; u++) c[nt][u] = 0.f;
#pragma unroll
        for (int k0 = 0; k0 < HDK; k0 += 16) {
            unsigned a[4];
            ldsm_x4(a, (unsigned)__cvta_generic_to_shared(
                qgh + (wm + arow) * OQ + k0 + akoff));
#pragma unroll
            for (int nt = 0; nt < 4; nt++) {
                unsigned bb[2];
                ldsm_x2(bb, (unsigned)__cvta_generic_to_shared(
                    kist + (wn + nt * 8 + bnrow) * OQ + k0 + bkoff));
                mma_f16(c[nt], a, bb);
            }
        }
        const int row0 = wm + r, row1 = wm + r + 8;
#pragma unroll
        for (int nt = 0; nt < 4; nt++) {
            const int col = wn + nt * 8 + 2 * cl;
            sch[row0 * OV + col]     = (col     <= row0) ? __float2half_rn(c[nt][0]) : __half(0.f);
            sch[row0 * OV + col + 1] = (col + 1 <= row0) ? __float2half_rn(c[nt][1]) : __half(0.f);
            sch[row1 * OV + col]     = (col     <= row1) ? __float2half_rn(c[nt][2]) : __half(0.f);
            sch[row1 * OV + col + 1] = (col + 1 <= row1) ? __float2half_rn(c[nt][3]) : __half(0.f);
        }
    }
    __syncthreads();

    for (int vs = 0; vs < HDV / 64; vs++) {
        {
            const long sbase = ((long)(bh * NCHUNK + n) * HDV + vs * 64) * HDK;
#pragma unroll
            for (int idx = tid; idx < 64 * 32; idx += 256) {
                int row = idx >> 5, c8 = idx & 31;
                *(uint4*)(kist + row * OQ + c8 * 8) =
                    *(const uint4*)(g_Sh + sbase + (long)row * HDK + c8 * 8);
            }
            const __half* vsrc = g_qkvh + rowbase * NQKV + 2 * DK + hh * HDV + vs * 64;
#pragma unroll
            for (int i = tid; i < 64 * 64; i += 256) {
                int t = i >> 6, vo = i & 63;
                vtTh[vo * OV + t] = vsrc[(long)t * NQKV + vo];
            }
        }
        __syncthreads();

        {
            float o[4][4];
#pragma unroll
            for (int nt = 0; nt < 4; nt++)
#pragma unroll
                for (int u = 0; u < 4; u++) o[nt][u] = 0.f;
#pragma unroll
            for (int k0 = 0; k0 < CHUNK; k0 += 16) {
                unsigned a[4];
                ldsm_x4(a, (unsigned)__cvta_generic_to_shared(
                    sch + (wm + arow) * OV + k0 + akoff));
#pragma unroll
                for (int nt = 0; nt < 4; nt++) {
                    unsigned bb[2];
                    ldsm_x2(bb, (unsigned)__cvta_generic_to_shared(
                        vtTh + (wn + nt * 8 + bnrow) * OV + k0 + bkoff));
                    mma_f16(o[nt], a, bb);
                }
            }
#pragma unroll
            for (int k0 = 0; k0 < HDK; k0 += 16) {
                unsigned a[4];
                ldsm_x4(a, (unsigned)__cvta_generic_to_shared(
                    qgh + (wm + arow) * OQ + k0 + akoff));
#pragma unroll
                for (int nt = 0; nt < 4; nt++) {
                    unsigned bb[2];
                    ldsm_x2(bb, (unsigned)__cvta_generic_to_shared(
                        kist + (wn + nt * 8 + bnrow) * OQ + k0 + bkoff));
                    mma_f16(o[nt], a, bb);
                }
            }
            const long ocol = hh * HDV + vs * 64;
            float* op = g_o + (rowbase + wm + r) * (long)DV + ocol + wn;
            float* op8 = op + 8 * DV;
#pragma unroll
            for (int nt = 0; nt < 4; nt++) {
                const int col = nt * 8 + 2 * cl;
                *(float2*)(op + col)  = make_float2(o[nt][0], o[nt][1]);
                *(float2*)(op8 + col) = make_float2(o[nt][2], o[nt][3]);
            }
        }
        __syncthreads();
    }
}

// ---------------- RMS norm + swish gate (fp16 output) ----------------------
__global__ __launch_bounds__(256) void normgate_kernel(const float* __restrict__ gnw)
{
    const int row = blockIdx.x;
    const int tid = threadIdx.x;
    const long base = (long)(row >> 2) * DV + (row & 3) * HDV;
    const float* op = g_o + base;
    const float* gp = g_gt + base;
    __half* ogp = g_ogh + base;

    float vals[2];
    float ss = 0.f;
#pragma unroll
    for (int u = 0; u < 2; u++) {
        vals[u] = op[tid + 256 * u];
        ss += vals[u] * vals[u];
    }
    __shared__ float red[8];
#pragma unroll
    for (int o = 16; o > 0; o >>= 1) ss += __shfl_xor_sync(0xffffffffu, ss, o);
    if ((tid & 31) == 0) red[tid >> 5] = ss;
    __syncthreads();
    if (tid < 8) {
        float rr = red[tid];
#pragma unroll
        for (int o = 4; o > 0; o >>= 1) rr += __shfl_xor_sync(0xffu, rr, o);
        if (tid == 0) red[0] = rr;
    }
    __syncthreads();
    const float rinv = rsqrtf(red[0] * (1.f / 512.f) + 1e-5f);
#pragma unroll
    for (int u = 0; u < 2; u++) {
        int c = tid + 256 * u;
        float g = gp[c];
        float sig = 1.f / (1.f + __expf(-g));
        ogp[c] = __float2half_rn(vals[u] * rinv * gnw[c] * (g * sig));
    }
}

// ---------------- launch ----------------------------------------------------
extern "C" void kernel_launch(void* const* d_in, const int* in_sizes, int n_in,
                              void* d_out, int out_size)
{
    (void)in_sizes; (void)n_in; (void)out_size;
    const float* h    = (const float*)d_in[0];
    const float* Wq   = (const float*)d_in[1];
    const float* Wk   = (const float*)d_in[2];
    const float* Wv   = (const float*)d_in[3];
    const float* Wg   = (const float*)d_in[4];
    const float* Wgk1 = (const float*)d_in[5];
    const float* Wgk2 = (const float*)d_in[6];
    const float* bgk2 = (const float*)d_in[7];
    const float* gnw  = (const float*)d_in[8];
    const float* Wo   = (const float*)d_in[9];
    float* out = (float*)d_out;

    void *pg, *pogh, *phh, *pqkv, *pwqkv, *pwg, *pwo;
    cudaGetSymbolAddress(&pg, g_gt);
    cudaGetSymbolAddress(&pogh, g_ogh);
    cudaGetSymbolAddress(&phh, g_hh);
    cudaGetSymbolAddress(&pqkv, g_qkvh);
    cudaGetSymbolAddress(&pwqkv, g_wqkvh);
    cudaGetSymbolAddress(&pwg, g_wgh);
    cudaGetSymbolAddress(&pwo, g_woh);

    static_assert(STATE_SMEM_FLOATS * 4 <= 232448, "state smem too big");
    static_assert(OUT_SMEM_HALVES * 2 * 2 <= 232448, "out smem too big");
    static_assert(GEMM_SMEM(128) * 2 <= 232448, "gemm128 smem too big");
    static_assert(GEMM_SMEM(64) * 2 <= 232448, "gemm64 smem too big");
    cudaFuncSetAttribute(gla_state_kernel, cudaFuncAttributeMaxDynamicSharedMemorySize,
                         STATE_SMEM_FLOATS * 4);
    cudaFuncSetAttribute(gla_out_kernel, cudaFuncAttributeMaxDynamicSharedMemorySize,
                         OUT_SMEM_HALVES * 2);
    cudaFuncSetAttribute(gemm_f16<128, float>, cudaFuncAttributeMaxDynamicSharedMemorySize,
                         GEMM_SMEM(128));
    cudaFuncSetAttribute(gemm_f16<128, __half>, cudaFuncAttributeMaxDynamicSharedMemorySize,
                         GEMM_SMEM(128));
    cudaFuncSetAttribute(gemm_f16<64, float>, cudaFuncAttributeMaxDynamicSharedMemorySize,
                         GEMM_SMEM(64));

    __half* wqkv = (__half*)pwqkv;

    dim3 t256(256);
    // conversion passes
    htrunc_kernel<<<(BL * HID / 4 + 255) / 256, t256>>>(h, (__half*)phh, BL * HID / 4);
    ttrans_kernel<<<dim3(DK / 32, HID / 32), t256>>>(Wq, wqkv, HID, DK);
    ttrans_kernel<<<dim3(DK / 32, HID / 32), t256>>>(Wk, wqkv + (long)DK * HID, HID, DK);
    ttrans_kernel<<<dim3(DV / 32, HID / 32), t256>>>(Wv, wqkv + (long)2 * DK * HID, HID, DV);
    ttrans_kernel<<<dim3(DV / 32, HID / 32), t256>>>(Wg, (__half*)pwg, HID, DV);

    // merged q|k|v projection (fp16 out) + g projection (fp32 out)
    gemm_f16<128, __half><<<dim3(NQKV / 128, BL / 128), t256, GEMM_SMEM(128)>>>(
        (const __half*)phh, wqkv, (__half*)pqkv, BL, NQKV, HID);
    gemm_f16<128, float><<<dim3(DV / 128, BL / 128), t256, GEMM_SMEM(128)>>>(
        (const __half*)phh, (const __half*)pwg, (float*)pg, BL, DV, HID);
    // low-rank gate path (fp32, original h)
    gemm16_kernel<<<(BL * 16) / 256, t256>>>(h, Wgk1);
    gk_kernel<<<(BL * DK) / 256, t256>>>(Wgk2, bgk2);
    // gate prep (fp16 qg/ki)
    gateprep_kernel<<<dim3(DK / 256, BATCH * NCHUNK), t256>>>();
    // GLA
    gla_state_kernel<<<dim3(HDV / 64, BH), t256, STATE_SMEM_FLOATS * 4>>>();
    gla_out_kernel<<<dim3(NCHUNK, BH), t256, OUT_SMEM_HALVES * 2>>>();
    // rms norm + swish gate (fp16 out)
    normgate_kernel<<<BL * NH, t256>>>(gnw);
    // output projection (BM=64 for better wave occupancy at N=1024)
    ttrans_kernel<<<dim3(HID / 32, DV / 32), t256>>>(Wo, (__half*)pwo, DV, HID);
    gemm_f16<64, float><<<dim3(HID / 128, BL / 64), t256, GEMM_SMEM(64)>>>(
        (const __half*)pogh, (const __half*)pwo, out, BL, HID, DV);
}

// round 17
// speedup vs baseline: 7.8457x; 1.0004x over previous
#include <cuda_runtime.h>
#include <cuda_fp16.h>
#include <math.h>
#include <stdint.h>

#define BATCH 4
#define SEQL 2048
#define HID 1024
#define NH 4
#define DK 1024
#define DV 2048
#define HDK 256
#define HDV 512
#define CHUNK 64
#define NCHUNK (SEQL / CHUNK)
#define BL (BATCH * SEQL) /* 8192 */
#define BH (BATCH * NH)   /* 16 */
#define NQKV 4096         /* q(1024) | k(1024) | v(2048) */

// ---------------- scratch (static device allocations; no runtime alloc) ----
__device__ float g_gt[BL * DV];
__device__ float g_gk[BL * DK];
__device__ float g_t16[BL * 16];
__device__ float g_o[BL * DV];
// fp16 operands
__device__ __half g_hh[BL * HID];
__device__ __half g_ogh[BL * DV];
__device__ __half g_qkvh[(long)BL * NQKV];
__device__ __half g_wqkvh[NQKV * HID];
__device__ __half g_wgh[HID * DV];
__device__ __half g_woh[DV * HID];
// gate-prep outputs (fp16) + eb (fp32)
__device__ __half g_qgh[BL * DK];
__device__ __half g_kih[BL * DK];
__device__ float g_eb[BATCH * NCHUNK * DK];
// materialized chunk-start states: [bh][n][v(512)][d(256)] fp16
// (identical to downstream use: gla_out converts S to fp16 before MMA anyway)
__device__ __half g_Sh[(long)BH * NCHUNK * HDV * HDK];

// ================= helpers =================================================
__device__ __forceinline__ void mma_tf32(float* c, const unsigned* a, const unsigned* b) {
    asm volatile(
        "mma.sync.aligned.m16n8k8.row.col.f32.tf32.tf32.f32 "
        "{%0,%1,%2,%3}, {%4,%5,%6,%7}, {%8,%9}, {%0,%1,%2,%3};"
        : "+f"(c[0]), "+f"(c[1]), "+f"(c[2]), "+f"(c[3])
        : "r"(a[0]), "r"(a[1]), "r"(a[2]), "r"(a[3]), "r"(b[0]), "r"(b[1]));
}

__device__ __forceinline__ void mma_f16(float* c, const unsigned* a, const unsigned* b) {
    asm volatile(
        "mma.sync.aligned.m16n8k16.row.col.f32.f16.f16.f32 "
        "{%0,%1,%2,%3}, {%4,%5,%6,%7}, {%8,%9}, {%0,%1,%2,%3};"
        : "+f"(c[0]), "+f"(c[1]), "+f"(c[2]), "+f"(c[3])
        : "r"(a[0]), "r"(a[1]), "r"(a[2]), "r"(a[3]), "r"(b[0]), "r"(b[1]));
}

__device__ __forceinline__ void ldsm_x4(unsigned* r, unsigned addr) {
    asm volatile("ldmatrix.sync.aligned.m8n8.x4.shared.b16 {%0,%1,%2,%3}, [%4];"
                 : "=r"(r[0]), "=r"(r[1]), "=r"(r[2]), "=r"(r[3]) : "r"(addr));
}
__device__ __forceinline__ void ldsm_x2(unsigned* r, unsigned addr) {
    asm volatile("ldmatrix.sync.aligned.m8n8.x2.shared.b16 {%0,%1}, [%2];"
                 : "=r"(r[0]), "=r"(r[1]) : "r"(addr));
}

// ---------------- fp16 conversion pass --------------------------------------
__global__ __launch_bounds__(256) void htrunc_kernel(
    const float* __restrict__ src, __half* __restrict__ dst, int n4)
{
    int i = blockIdx.x * 256 + threadIdx.x;
    if (i < n4) {
        float4 v = ((const float4*)src)[i];
        ((__half2*)dst)[i * 2] = __floats2half2_rn(v.x, v.y);
        ((__half2*)dst)[i * 2 + 1] = __floats2half2_rn(v.z, v.w);
    }
}

// ---------------- weight transpose + fp16: W[K][N] -> WT[N][K] --------------
__global__ __launch_bounds__(256) void ttrans_kernel(
    const float* __restrict__ W, __half* __restrict__ WT, int Kd, int Nd)
{
    __shared__ float t[32][33];
    const int bx = blockIdx.x * 32;
    const int by = blockIdx.y * 32;
    const int x = threadIdx.x & 31, y = threadIdx.x >> 5;
#pragma unroll
    for (int j = 0; j < 32; j += 8)
        t[y + j][x] = W[(long)(by + y + j) * Nd + bx + x];
    __syncthreads();
#pragma unroll
    for (int j = 0; j < 32; j += 8)
        WT[(long)(bx + y + j) * Kd + by + x] = __float2half_rn(t[x][y + j]);
}

// ================= FP16 tensor-core GEMM ===================================
// C[M,N] = A[M,K] @ BT[N,K]^T. Templated M-tile (BM in {64,128}), N-tile 128,
// K-chunk 64, 256 threads (2Mx4N warps, warp tile (BM/2)x32), 3-stage cp.async.
#define KC 64
#define ASTRH 72

template <int BM, typename OutT>
__global__ __launch_bounds__(256, 2) void gemm_f16(
    const __half* __restrict__ A, const __half* __restrict__ BT,
    OutT* __restrict__ C, int M, int N, int K)
{
    constexpr int MT = BM / 32;                    // warp m-subtiles
    constexpr int TROWS = BM + 128;                // A rows + B rows per stage
    constexpr int STG = TROWS * ASTRH;             // halves per stage
    extern __shared__ __half smh[];
    const int tid = threadIdx.x;
    const int warp = tid >> 5, lane = tid & 31;
    const long bm = (long)blockIdx.y * BM, bn = (long)blockIdx.x * 128;
    const int wm = (warp & 1) * (BM / 2), wn = (warp >> 1) * 32;

    float acc[MT][4][4];
#pragma unroll
    for (int mt = 0; mt < MT; mt++)
#pragma unroll
        for (int nt = 0; nt < 4; nt++)
#pragma unroll
            for (int u = 0; u < 4; u++) acc[mt][nt][u] = 0.f;

    auto load_tile = [&](int s, int kc) {
        const int k0 = kc * KC;
#pragma unroll
        for (int p = 0; p < TROWS * 8 / 256; p++) {
            const int i = tid + p * 256;
            const int row = i >> 3, ch = i & 7;
            const __half* src = (row < BM)
                ? (A + (bm + row) * (long)K + k0 + ch * 8)
                : (BT + (bn + row - BM) * (long)K + k0 + ch * 8);
            unsigned dst = (unsigned)__cvta_generic_to_shared(
                smh + s * STG + row * ASTRH + ch * 8);
            asm volatile("cp.async.cg.shared.global [%0], [%1], 16;\n"
                         :: "r"(dst), "l"(src));
        }
    };

    const int nk = K / KC;
    load_tile(0, 0);
    asm volatile("cp.async.commit_group;\n");
    load_tile(1, 1);
    asm volatile("cp.async.commit_group;\n");

    const int arow = (lane & 7) + ((lane >> 3) & 1) * 8;
    const int akoff = (lane >> 4) * 8;
    const int bnrow = lane & 7;
    const int bkoff = ((lane >> 3) & 1) * 8;

    for (int it = 0; it < nk; it++) {
        const int s = it % 3;
        if (it + 2 < nk) {
            load_tile((it + 2) % 3, it + 2);
            asm volatile("cp.async.commit_group;\n");
            asm volatile("cp.async.wait_group 2;\n");
        } else if (it + 1 < nk) {
            asm volatile("cp.async.wait_group 1;\n");
        } else {
            asm volatile("cp.async.wait_group 0;\n");
        }
        __syncthreads();

        const __half* sA = smh + s * STG;
        const __half* sB = smh + s * STG + BM * ASTRH;
#pragma unroll
        for (int kk = 0; kk < 4; kk++) {
            const int k0 = kk * 16;
            unsigned a[MT][4], b[4][2];
#pragma unroll
            for (int mt = 0; mt < MT; mt++) {
                unsigned ad = (unsigned)__cvta_generic_to_shared(
                    sA + (wm + mt * 16 + arow) * ASTRH + k0 + akoff);
                ldsm_x4(a[mt], ad);
            }
#pragma unroll
            for (int nt = 0; nt < 4; nt++) {
                unsigned bd = (unsigned)__cvta_generic_to_shared(
                    sB + (wn + nt * 8 + bnrow) * ASTRH + k0 + bkoff);
                ldsm_x2(b[nt], bd);
            }
#pragma unroll
            for (int mt = 0; mt < MT; mt++)
#pragma unroll
                for (int nt = 0; nt < 4; nt++) mma_f16(acc[mt][nt], a[mt], b[nt]);
        }
        __syncthreads();
    }

    const int r = lane >> 2, cl = lane & 3;
    OutT* Cb = C + (bm + wm) * (long)N + bn + wn;
#pragma unroll
    for (int mt = 0; mt < MT; mt++) {
        const int row0 = mt * 16 + r;
#pragma unroll
        for (int nt = 0; nt < 4; nt++) {
            const int col = nt * 8 + 2 * cl;
            if constexpr (sizeof(OutT) == 4) {
                *(float2*)(Cb + (long)row0 * N + col) =
                    make_float2(acc[mt][nt][0], acc[mt][nt][1]);
                *(float2*)(Cb + (long)(row0 + 8) * N + col) =
                    make_float2(acc[mt][nt][2], acc[mt][nt][3]);
            } else {
                *(__half2*)(Cb + (long)row0 * N + col) =
                    __floats2half2_rn(acc[mt][nt][0], acc[mt][nt][1]);
                *(__half2*)(Cb + (long)(row0 + 8) * N + col) =
                    __floats2half2_rn(acc[mt][nt][2], acc[mt][nt][3]);
            }
        }
    }
}

#define GEMM_SMEM(BM) (3 * ((BM) + 128) * ASTRH * 2)

// ---------------- low-rank gate: tmp = h @ Wgk1 -----------------------------
__global__ __launch_bounds__(256) void gemm16_kernel(
    const float* __restrict__ A, const float* __restrict__ W)
{
    int idx = blockIdx.x * 256 + threadIdx.x;
    int row = idx >> 4, col = idx & 15;
    const float* a = A + (long)row * HID;
    float acc = 0.f;
#pragma unroll 8
    for (int k = 0; k < HID; k++) acc += a[k] * W[k * 16 + col];
    g_t16[idx] = acc;
}

// ---------------- gk = log_sigmoid(tmp @ Wgk2 + b) / 16 --------------------
__global__ __launch_bounds__(256) void gk_kernel(
    const float* __restrict__ W2, const float* __restrict__ bias)
{
    int idx = blockIdx.x * 256 + threadIdx.x;
    int row = idx >> 10, c = idx & 1023;
    const float* t = g_t16 + row * 16;
    float acc = bias[c];
#pragma unroll
    for (int l = 0; l < 16; l++) acc += t[l] * W2[l * DK + c];
    float ax = fabsf(acc);
    float ls = fminf(acc, 0.f) - __logf(1.f + __expf(-ax));
    g_gk[idx] = ls * 0.0625f;
}

// ---------------- gate prep: qg/ki (fp16) + eb ------------------------------
__global__ __launch_bounds__(256) void gateprep_kernel()
{
    const int col = blockIdx.x * 256 + threadIdx.x;
    const int bn = blockIdx.y;
    const int b = bn / NCHUNK, n = bn % NCHUNK;
    const long rowbase = (long)(b * SEQL + n * CHUNK);
    const float* gkp = g_gk + rowbase * DK + col;
    const __half* qp = g_qkvh + rowbase * NQKV + col;
    const __half* kp = qp + DK;
    __half* qgp = g_qgh + rowbase * DK + col;
    __half* kip = g_kih + rowbase * DK + col;
    const float scale = 0.0625f;

    float bsum = 0.f, ep = 1.f;
#pragma unroll 4
    for (int t = 0; t < CHUNK; t++) {
        bsum += gkp[(long)t * DK];
        ep = __expf(bsum);
        float en = __expf(-bsum);
        qgp[(long)t * DK] = __float2half_rn(__half2float(qp[(long)t * NQKV]) * ep * scale);
        kip[(long)t * DK] = __float2half_rn(__half2float(kp[(long)t * NQKV]) * en);
    }
    g_eb[(long)bn * DK + col] = ep;
}

// ================= GLA split: sequential state kernel (tf32) ================
#define QSTR 257
#define VSTR 65
#define STSTR 260
#define STATE_SMEM_FLOATS (64 * QSTR + 64 * STSTR + 64 * VSTR + 256)

__global__ __launch_bounds__(256) void gla_state_kernel()
{
    extern __shared__ float sm[];
    float* ki  = sm;
    float* ST  = ki + 64 * QSTR;
    float* vtT = ST + 64 * STSTR;
    float* eb  = vtT + 64 * VSTR;

    const int tid = threadIdx.x;
    const int warp = tid >> 5, lane = tid & 31;
    const int r = lane >> 2, cl = lane & 3, cl2 = 2 * (lane & 3);
    const int vs = blockIdx.x;
    const int bh = blockIdx.y;
    const int b = bh >> 2, hh = bh & 3;

    for (int i = tid; i < 64 * STSTR; i += 256) ST[i] = 0.f;
    __syncthreads();

    for (int n = 0; n < NCHUNK; n++) {
        // ---- store S_n snapshot as fp16 (value-identical to downstream use)
        {
            const long sbase = ((long)(bh * NCHUNK + n) * HDV + vs * 64) * HDK;
#pragma unroll
            for (int idx = tid; idx < 64 * 32; idx += 256) {
                int row = idx >> 5, c8 = idx & 31;
                const float* srow = ST + row * STSTR + c8 * 8;
                __half2 hh4[4];
#pragma unroll
                for (int j = 0; j < 4; j++)
                    hh4[j] = __floats2half2_rn(srow[j * 2], srow[j * 2 + 1]);
                *(uint4*)(g_Sh + sbase + (long)row * HDK + c8 * 8) = *(uint4*)hh4;
            }
        }
        {
            eb[tid] = g_eb[((long)(b * NCHUNK + n)) * DK + hh * HDK + tid];
            const long rowbase = (long)(b * SEQL + n * CHUNK);
#pragma unroll
            for (int idx = tid; idx < 64 * 32; idx += 256) {
                int t = idx >> 5, c8 = idx & 31;
                const __half2* src = (const __half2*)(g_kih + (rowbase + t) * DK + hh * HDK + c8 * 8);
                float* kd = ki + t * QSTR + c8 * 8;
#pragma unroll
                for (int j = 0; j < 4; j++) {
                    float2 f = __half22float2(src[j]);
                    kd[j * 2] = f.x;
                    kd[j * 2 + 1] = f.y;
                }
            }
            const __half* vsrc = g_qkvh + rowbase * NQKV + 2 * DK + hh * HDV + vs * 64;
#pragma unroll
            for (int i = tid; i < 64 * 64; i += 256) {
                int t = i >> 6, vo = i & 63;
                vtT[vo * VSTR + t] = __half2float(vsrc[(long)t * NQKV + vo]);
            }
        }
        __syncthreads();

        {
#pragma unroll
            for (int mt = 0; mt < 2; mt++) {
                const int m0 = warp * 32 + mt * 16;
                float cD[8][4];
#pragma unroll
                for (int ns = 0; ns < 8; ns++)
#pragma unroll
                    for (int u = 0; u < 4; u++) cD[ns][u] = 0.f;
#pragma unroll
                for (int k0 = 0; k0 < CHUNK; k0 += 8) {
                    unsigned a[4];
                    const float* ap = ki + (k0 + cl) * QSTR + m0 + r;
                    a[0] = __float_as_uint(ap[0]);
                    a[1] = __float_as_uint(ap[8]);
                    a[2] = __float_as_uint(ap[4 * QSTR]);
                    a[3] = __float_as_uint(ap[4 * QSTR + 8]);
#pragma unroll
                    for (int ns = 0; ns < 8; ns++) {
                        unsigned bb[2];
                        const float* bp = vtT + (ns * 8 + r) * VSTR + k0 + cl;
                        bb[0] = __float_as_uint(bp[0]);
                        bb[1] = __float_as_uint(bp[4]);
                        mma_tf32(cD[ns], a, bb);
                    }
                }
                const float e0 = eb[m0 + r];
                const float e1 = eb[m0 + r + 8];
#pragma unroll
                for (int ns = 0; ns < 8; ns++) {
                    const int col = ns * 8 + cl2;
                    float* s00 = ST + col * STSTR + m0 + r;
                    float* s01 = ST + (col + 1) * STSTR + m0 + r;
                    s00[0] = e0 * (s00[0] + cD[ns][0]);
                    s01[0] = e0 * (s01[0] + cD[ns][1]);
                    s00[8] = e1 * (s00[8] + cD[ns][2]);
                    s01[8] = e1 * (s01[8] + cD[ns][3]);
                }
            }
        }
        __syncthreads();
    }
}

// ================= GLA split: parallel output kernel (fp16) =================
#define OQ 264
#define OV 72
#define OUT_SMEM_HALVES (2 * 64 * OQ + 2 * 64 * OV)

__global__ __launch_bounds__(256, 2) void gla_out_kernel()
{
    extern __shared__ __half smo[];
    __half* qgh  = smo;
    __half* kist = qgh + 64 * OQ;
    __half* sch  = kist + 64 * OQ;
    __half* vtTh = sch + 64 * OV;

    const int tid = threadIdx.x;
    const int warp = tid >> 5, lane = tid & 31;
    const int r = lane >> 2, cl = lane & 3;
    const int n = blockIdx.x;
    const int bh = blockIdx.y;
    const int b = bh >> 2, hh = bh & 3;

    const int wm = (warp & 3) * 16;
    const int wn = (warp >> 2) * 32;

    const int arow = (lane & 7) + ((lane >> 3) & 1) * 8;
    const int akoff = (lane >> 4) * 8;
    const int bnrow = lane & 7;
    const int bkoff = ((lane >> 3) & 1) * 8;

    const long rowbase = (long)(b * SEQL + n * CHUNK);

    {
#pragma unroll
        for (int idx = tid; idx < 64 * 32; idx += 256) {
            int t = idx >> 5, c8 = idx & 31;
            *(uint4*)(qgh + t * OQ + c8 * 8) =
                *(const uint4*)(g_qgh + (rowbase + t) * DK + hh * HDK + c8 * 8);
            *(uint4*)(kist + t * OQ + c8 * 8) =
                *(const uint4*)(g_kih + (rowbase + t) * DK + hh * HDK + c8 * 8);
        }
    }
    __syncthreads();

    {
        float c[4][4];
#pragma unroll
        for (int nt = 0; nt < 4; nt++)
#pragma unroll
            for (int u = 0; u < 4; u++) c[nt][u] = 0.f;
#pragma unroll
        for (int k0 = 0; k0 < HDK; k0 += 16) {
            unsigned a[4];
            ldsm_x4(a, (unsigned)__cvta_generic_to_shared(
                qgh + (wm + arow) * OQ + k0 + akoff));
#pragma unroll
            for (int nt = 0; nt < 4; nt++) {
                unsigned bb[2];
                ldsm_x2(bb, (unsigned)__cvta_generic_to_shared(
                    kist + (wn + nt * 8 + bnrow) * OQ + k0 + bkoff));
                mma_f16(c[nt], a, bb);
            }
        }
        const int row0 = wm + r, row1 = wm + r + 8;
#pragma unroll
        for (int nt = 0; nt < 4; nt++) {
            const int col = wn + nt * 8 + 2 * cl;
            sch[row0 * OV + col]     = (col     <= row0) ? __float2half_rn(c[nt][0]) : __half(0.f);
            sch[row0 * OV + col + 1] = (col + 1 <= row0) ? __float2half_rn(c[nt][1]) : __half(0.f);
            sch[row1 * OV + col]     = (col     <= row1) ? __float2half_rn(c[nt][2]) : __half(0.f);
            sch[row1 * OV + col + 1] = (col + 1 <= row1) ? __float2half_rn(c[nt][3]) : __half(0.f);
        }
    }
    __syncthreads();

    for (int vs = 0; vs < HDV / 64; vs++) {
        {
            const long sbase = ((long)(bh * NCHUNK + n) * HDV + vs * 64) * HDK;
#pragma unroll
            for (int idx = tid; idx < 64 * 32; idx += 256) {
                int row = idx >> 5, c8 = idx & 31;
                *(uint4*)(kist + row * OQ + c8 * 8) =
                    *(const uint4*)(g_Sh + sbase + (long)row * HDK + c8 * 8);
            }
            const __half* vsrc = g_qkvh + rowbase * NQKV + 2 * DK + hh * HDV + vs * 64;
#pragma unroll
            for (int i = tid; i < 64 * 64; i += 256) {
                int t = i >> 6, vo = i & 63;
                vtTh[vo * OV + t] = vsrc[(long)t * NQKV + vo];
            }
        }
        __syncthreads();

        {
            float o[4][4];
#pragma unroll
            for (int nt = 0; nt < 4; nt++)
#pragma unroll
                for (int u = 0; u < 4; u++) o[nt][u] = 0.f;
#pragma unroll
            for (int k0 = 0; k0 < CHUNK; k0 += 16) {
                unsigned a[4];
                ldsm_x4(a, (unsigned)__cvta_generic_to_shared(
                    sch + (wm + arow) * OV + k0 + akoff));
#pragma unroll
                for (int nt = 0; nt < 4; nt++) {
                    unsigned bb[2];
                    ldsm_x2(bb, (unsigned)__cvta_generic_to_shared(
                        vtTh + (wn + nt * 8 + bnrow) * OV + k0 + bkoff));
                    mma_f16(o[nt], a, bb);
                }
            }
#pragma unroll
            for (int k0 = 0; k0 < HDK; k0 += 16) {
                unsigned a[4];
                ldsm_x4(a, (unsigned)__cvta_generic_to_shared(
                    qgh + (wm + arow) * OQ + k0 + akoff));
#pragma unroll
                for (int nt = 0; nt < 4; nt++) {
                    unsigned bb[2];
                    ldsm_x2(bb, (unsigned)__cvta_generic_to_shared(
                        kist + (wn + nt * 8 + bnrow) * OQ + k0 + bkoff));
                    mma_f16(o[nt], a, bb);
                }
            }
            const long ocol = hh * HDV + vs * 64;
            float* op = g_o + (rowbase + wm + r) * (long)DV + ocol + wn;
            float* op8 = op + 8 * DV;
#pragma unroll
            for (int nt = 0; nt < 4; nt++) {
                const int col = nt * 8 + 2 * cl;
                *(float2*)(op + col)  = make_float2(o[nt][0], o[nt][1]);
                *(float2*)(op8 + col) = make_float2(o[nt][2], o[nt][3]);
            }
        }
        __syncthreads();
    }
}

// ---------------- RMS norm + swish gate (fp16 output) ----------------------
__global__ __launch_bounds__(256) void normgate_kernel(const float* __restrict__ gnw)
{
    const int row = blockIdx.x;
    const int tid = threadIdx.x;
    const long base = (long)(row >> 2) * DV + (row & 3) * HDV;
    const float* op = g_o + base;
    const float* gp = g_gt + base;
    __half* ogp = g_ogh + base;

    float vals[2];
    float ss = 0.f;
#pragma unroll
    for (int u = 0; u < 2; u++) {
        vals[u] = op[tid + 256 * u];
        ss += vals[u] * vals[u];
    }
    __shared__ float red[8];
#pragma unroll
    for (int o = 16; o > 0; o >>= 1) ss += __shfl_xor_sync(0xffffffffu, ss, o);
    if ((tid & 31) == 0) red[tid >> 5] = ss;
    __syncthreads();
    if (tid < 8) {
        float rr = red[tid];
#pragma unroll
        for (int o = 4; o > 0; o >>= 1) rr += __shfl_xor_sync(0xffu, rr, o);
        if (tid == 0) red[0] = rr;
    }
    __syncthreads();
    const float rinv = rsqrtf(red[0] * (1.f / 512.f) + 1e-5f);
#pragma unroll
    for (int u = 0; u < 2; u++) {
        int c = tid + 256 * u;
        float g = gp[c];
        float sig = 1.f / (1.f + __expf(-g));
        ogp[c] = __float2half_rn(vals[u] * rinv * gnw[c] * (g * sig));
    }
}

// ---------------- launch ----------------------------------------------------
extern "C" void kernel_launch(void* const* d_in, const int* in_sizes, int n_in,
                              void* d_out, int out_size)
{
    (void)in_sizes; (void)n_in; (void)out_size;
    const float* h    = (const float*)d_in[0];
    const float* Wq   = (const float*)d_in[1];
    const float* Wk   = (const float*)d_in[2];
    const float* Wv   = (const float*)d_in[3];
    const float* Wg   = (const float*)d_in[4];
    const float* Wgk1 = (const float*)d_in[5];
    const float* Wgk2 = (const float*)d_in[6];
    const float* bgk2 = (const float*)d_in[7];
    const float* gnw  = (const float*)d_in[8];
    const float* Wo   = (const float*)d_in[9];
    float* out = (float*)d_out;

    void *pg, *pogh, *phh, *pqkv, *pwqkv, *pwg, *pwo;
    cudaGetSymbolAddress(&pg, g_gt);
    cudaGetSymbolAddress(&pogh, g_ogh);
    cudaGetSymbolAddress(&phh, g_hh);
    cudaGetSymbolAddress(&pqkv, g_qkvh);
    cudaGetSymbolAddress(&pwqkv, g_wqkvh);
    cudaGetSymbolAddress(&pwg, g_wgh);
    cudaGetSymbolAddress(&pwo, g_woh);

    static_assert(STATE_SMEM_FLOATS * 4 <= 232448, "state smem too big");
    static_assert(OUT_SMEM_HALVES * 2 * 2 <= 232448, "out smem too big");
    static_assert(GEMM_SMEM(128) * 2 <= 232448, "gemm128 smem too big");
    static_assert(GEMM_SMEM(64) * 2 <= 232448, "gemm64 smem too big");
    cudaFuncSetAttribute(gla_state_kernel, cudaFuncAttributeMaxDynamicSharedMemorySize,
                         STATE_SMEM_FLOATS * 4);
    cudaFuncSetAttribute(gla_out_kernel, cudaFuncAttributeMaxDynamicSharedMemorySize,
                         OUT_SMEM_HALVES * 2);
    cudaFuncSetAttribute(gemm_f16<128, float>, cudaFuncAttributeMaxDynamicSharedMemorySize,
                         GEMM_SMEM(128));
    cudaFuncSetAttribute(gemm_f16<128, __half>, cudaFuncAttributeMaxDynamicSharedMemorySize,
                         GEMM_SMEM(128));
    cudaFuncSetAttribute(gemm_f16<64, float>, cudaFuncAttributeMaxDynamicSharedMemorySize,
                         GEMM_SMEM(64));

    __half* wqkv = (__half*)pwqkv;

    dim3 t256(256);
    // conversion passes
    htrunc_kernel<<<(BL * HID / 4 + 255) / 256, t256>>>(h, (__half*)phh, BL * HID / 4);
    ttrans_kernel<<<dim3(DK / 32, HID / 32), t256>>>(Wq, wqkv, HID, DK);
    ttrans_kernel<<<dim3(DK / 32, HID / 32), t256>>>(Wk, wqkv + (long)DK * HID, HID, DK);
    ttrans_kernel<<<dim3(DV / 32, HID / 32), t256>>>(Wv, wqkv + (long)2 * DK * HID, HID, DV);
    ttrans_kernel<<<dim3(DV / 32, HID / 32), t256>>>(Wg, (__half*)pwg, HID, DV);

    // merged q|k|v projection (fp16 out) + g projection (fp32 out)
    gemm_f16<128, __half><<<dim3(NQKV / 128, BL / 128), t256, GEMM_SMEM(128)>>>(
        (const __half*)phh, wqkv, (__half*)pqkv, BL, NQKV, HID);
    gemm_f16<128, float><<<dim3(DV / 128, BL / 128), t256, GEMM_SMEM(128)>>>(
        (const __half*)phh, (const __half*)pwg, (float*)pg, BL, DV, HID);
    // low-rank gate path (fp32, original h)
    gemm16_kernel<<<(BL * 16) / 256, t256>>>(h, Wgk1);
    gk_kernel<<<(BL * DK) / 256, t256>>>(Wgk2, bgk2);
    // gate prep (fp16 qg/ki)
    gateprep_kernel<<<dim3(DK / 256, BATCH * NCHUNK), t256>>>();
    // GLA
    gla_state_kernel<<<dim3(HDV / 64, BH), t256, STATE_SMEM_FLOATS * 4>>>();
    gla_out_kernel<<<dim3(NCHUNK, BH), t256, OUT_SMEM_HALVES * 2>>>();
    // rms norm + swish gate (fp16 out)
    normgate_kernel<<<BL * NH, t256>>>(gnw);
    // output projection (BM=64 for better wave occupancy at N=1024)
    ttrans_kernel<<<dim3(HID / 32, DV / 32), t256>>>(Wo, (__half*)pwo, DV, HID);
    gemm_f16<64, float><<<dim3(HID / 128, BL / 64), t256, GEMM_SMEM(64)>>>(
        (const __half*)pogh, (const __half*)pwo, out, BL, HID, DV);
}